// round 10
// baseline (speedup 1.0000x reference)
#include <cuda_runtime.h>
#include <math.h>
#include <stdint.h>

// ---------------------------------------------------------------------------
// Problem constants
// ---------------------------------------------------------------------------
#define NTOK   81
#define DM     512
#define NH     8
#define EH     64
#define DFF    1024
#define NL     3
#define RT     (2048 * 81)           // 165888 tokens
#define RTILES (RT / 128)            // 1296

// ---------------------------------------------------------------------------
// Scratch (device globals: no cudaMalloc allowed)
// ---------------------------------------------------------------------------
__device__ float g_h  [RT * DM];
__device__ float g_q  [RT * DM];
__device__ float g_k  [RT * DM];
__device__ float g_v  [RT * DM];
__device__ float g_att[RT * DM];
__device__ float g_y  [RT * DM];
__device__ float g_t  [RT * DFF];
__device__ float g_psum[RTILES * 512];
__device__ float g_psq [RTILES * 512];
__device__ float g_bnscale[2 * 512];
__device__ float g_bnshift[2 * 512];

// ---------------------------------------------------------------------------
// PTX helpers
// ---------------------------------------------------------------------------
__device__ __forceinline__ uint32_t smem_u32(const void* p) {
    uint32_t a;
    asm("{ .reg .u64 t; cvta.to.shared.u64 t, %1; cvt.u32.u64 %0, t; }"
        : "=r"(a) : "l"(p));
    return a;
}

__device__ __forceinline__ void cp16(uint32_t dst, const void* src) {
    asm volatile("cp.async.cg.shared.global [%0], [%1], 16;"
                 :: "r"(dst), "l"(src) : "memory");
}
#define CP_COMMIT() asm volatile("cp.async.commit_group;" ::: "memory")

__device__ __forceinline__ void mma_tf32(float* c, const uint32_t* a, const uint32_t* b) {
    asm volatile(
        "mma.sync.aligned.m16n8k8.row.col.f32.tf32.tf32.f32 "
        "{%0,%1,%2,%3}, {%4,%5,%6,%7}, {%8,%9}, {%0,%1,%2,%3};"
        : "+f"(c[0]), "+f"(c[1]), "+f"(c[2]), "+f"(c[3])
        : "r"(a[0]), "r"(a[1]), "r"(a[2]), "r"(a[3]), "r"(b[0]), "r"(b[1]));
}

__device__ __forceinline__ void ldsm_x4(uint32_t* r, uint32_t addr) {
    asm volatile("ldmatrix.sync.aligned.m8n8.x4.shared.b16 {%0,%1,%2,%3}, [%4];"
        : "=r"(r[0]), "=r"(r[1]), "=r"(r[2]), "=r"(r[3]) : "r"(addr));
}

// ---------------------------------------------------------------------------
// TF32 GEMM (R8 config, best measured): CTA 128x128, BK=32, 8 warps (2x4),
// warp tile 64x32, 2 CTAs/SM, 3-stage cp.async.cg.
// EPI: 0=bias, 1=bias+gelu, 2=bias+residual
// AFF: 0=none, 1=affine on A in-fragment (per-K), 2=affine on residual (per-col)
// STATS: 1 -> per-CTA column sum/sumsq partials
// ---------------------------------------------------------------------------
#define APAD 36
#define A_HALF 18432                     // 128*36*4
#define STAGE_B 36864
#define GEMM_SMEM (3 * STAGE_B)          // 110592 B

template <int EPI, int AFF, int STATS>
__global__ __launch_bounds__(256, 2)
void mma_gemm(const float* __restrict__ A, const float* __restrict__ W,
              const float* __restrict__ bias, const float* __restrict__ res,
              const float* __restrict__ scl, const float* __restrict__ shf,
              float* __restrict__ C, int K)
{
    extern __shared__ float smf[];
    uint32_t sA = smem_u32(smf);
    uint32_t sB = sA + A_HALF;

    int tid  = threadIdx.x;
    int wid  = tid >> 5, lane = tid & 31;
    int wm   = (wid >> 2) * 64;
    int wn   = (wid & 3) * 32;
    int row0 = blockIdx.y * 128, col0 = blockIdx.x * 128;
    int Dout = gridDim.x * 128;
    int qg   = lane >> 2, qt = lane & 3;
    int lg   = lane >> 3, lr = lane & 7;

    uint32_t baseA[4], baseB[2];
    #pragma unroll
    for (int mt = 0; mt < 4; mt++)
        baseA[mt] = sA + (((wm + mt * 16 + (lg & 1) * 8 + lr) * APAD) + (lg >> 1) * 4) * 4;
    #pragma unroll
    for (int p = 0; p < 2; p++)
        baseB[p]  = sB + (((wn + (2 * p + (lg >> 1)) * 8 + lr) * APAD) + (lg & 1) * 4) * 4;

    int rr = tid >> 3, cc4 = tid & 7;
    const float* gA = A + (size_t)(row0 + rr) * K + cc4 * 4;
    const float* gW = W + (size_t)(col0 + rr) * K + cc4 * 4;
    uint32_t dsl = (uint32_t)(rr * APAD + cc4 * 4) * 4;

    auto issue = [&](int st, int kb2) {
        uint32_t o = st * STAGE_B + dsl;
        const float* pa = gA + kb2 * 32;
        const float* pw = gW + kb2 * 32;
        #pragma unroll
        for (int i = 0; i < 4; i++) {
            cp16(sA + o + i * (32 * APAD * 4), pa + (size_t)i * 32 * K);
            cp16(sB + o + i * (32 * APAD * 4), pw + (size_t)i * 32 * K);
        }
        CP_COMMIT();
    };

    int NKB = K / 32;
    issue(0, 0);
    issue(1, 1);

    float acc[4][4][4];
    #pragma unroll
    for (int mt = 0; mt < 4; mt++)
        #pragma unroll
        for (int nt = 0; nt < 4; nt++)
            #pragma unroll
            for (int j = 0; j < 4; j++) acc[mt][nt][j] = 0.f;

    int st = 0, nst = 2;
    for (int kb = 0; kb < NKB; kb++) {
        if (kb + 1 < NKB)
            asm volatile("cp.async.wait_group 1;" ::: "memory");
        else
            asm volatile("cp.async.wait_group 0;" ::: "memory");
        __syncthreads();
        if (kb + 2 < NKB) {
            issue(nst, kb + 2);
            if (++nst == 3) nst = 0;
        }

        uint32_t stOff = st * STAGE_B;
        #pragma unroll
        for (int ks = 0; ks < 4; ks++) {
            uint32_t kB = stOff + ks * 32;
            uint32_t af[4][4], bf[4][2];
            #pragma unroll
            for (int mt = 0; mt < 4; mt++)
                ldsm_x4(af[mt], baseA[mt] + kB);
            #pragma unroll
            for (int p = 0; p < 2; p++) {
                uint32_t t[4];
                ldsm_x4(t, baseB[p] + kB);
                bf[2 * p][0] = t[0]; bf[2 * p][1] = t[1];
                bf[2 * p + 1][0] = t[2]; bf[2 * p + 1][1] = t[3];
            }
            if (AFF == 1) {
                int kg = kb * 32 + ks * 8 + qt;
                float s_lo = scl[kg], h_lo = shf[kg];
                float s_hi = scl[kg + 4], h_hi = shf[kg + 4];
                #pragma unroll
                for (int mt = 0; mt < 4; mt++) {
                    af[mt][0] = __float_as_uint(s_lo * __uint_as_float(af[mt][0]) + h_lo);
                    af[mt][1] = __float_as_uint(s_lo * __uint_as_float(af[mt][1]) + h_lo);
                    af[mt][2] = __float_as_uint(s_hi * __uint_as_float(af[mt][2]) + h_hi);
                    af[mt][3] = __float_as_uint(s_hi * __uint_as_float(af[mt][3]) + h_hi);
                }
            }
            #pragma unroll
            for (int mt = 0; mt < 4; mt++)
                #pragma unroll
                for (int nt = 0; nt < 4; nt++)
                    mma_tf32(acc[mt][nt], af[mt], bf[nt]);
        }
        if (++st == 3) st = 0;
    }

    float cs[8], cq[8];
    if (STATS) {
        #pragma unroll
        for (int j = 0; j < 8; j++) { cs[j] = 0.f; cq[j] = 0.f; }
    }

    #pragma unroll
    for (int mt = 0; mt < 4; mt++) {
        #pragma unroll
        for (int nt = 0; nt < 4; nt++) {
            int c  = col0 + wn + nt * 8 + 2 * qt;
            int r0 = row0 + wm + mt * 16 + qg;
            float b0 = bias[c], b1 = bias[c + 1];
            float s0 = 1.f, s1 = 1.f, h0 = 0.f, h1 = 0.f;
            if (AFF == 2) {
                s0 = scl[c]; s1 = scl[c + 1];
                h0 = shf[c]; h1 = shf[c + 1];
            }
            #pragma unroll
            for (int half = 0; half < 2; half++) {
                int r = r0 + half * 8;
                float vx = acc[mt][nt][half * 2 + 0] + b0;
                float vy = acc[mt][nt][half * 2 + 1] + b1;
                if (EPI == 1) {
                    vx = 0.5f * vx * (1.0f + erff(vx * 0.70710678118654752f));
                    vy = 0.5f * vy * (1.0f + erff(vy * 0.70710678118654752f));
                }
                size_t off = (size_t)r * Dout + c;
                if (EPI == 2) {
                    float2 rv = *(const float2*)(res + off);
                    if (AFF == 2) { vx += s0 * rv.x + h0; vy += s1 * rv.y + h1; }
                    else          { vx += rv.x;           vy += rv.y; }
                }
                if (STATS) {
                    cs[nt * 2 + 0] += vx; cq[nt * 2 + 0] += vx * vx;
                    cs[nt * 2 + 1] += vy; cq[nt * 2 + 1] += vy * vy;
                }
                *(float2*)(C + off) = make_float2(vx, vy);
            }
        }
    }

    if (STATS) {
        #pragma unroll
        for (int j = 0; j < 8; j++) {
            #pragma unroll
            for (int m = 4; m <= 16; m <<= 1) {
                cs[j] += __shfl_xor_sync(0xffffffffu, cs[j], m);
                cq[j] += __shfl_xor_sync(0xffffffffu, cq[j], m);
            }
        }
        __syncthreads();
        float* ssum = smf;
        float* ssq  = smf + 256;
        int wrow = wid >> 2;
        if (lane < 4) {
            #pragma unroll
            for (int nt = 0; nt < 4; nt++) {
                #pragma unroll
                for (int p = 0; p < 2; p++) {
                    int cl = wn + nt * 8 + 2 * qt + p;
                    ssum[wrow * 128 + cl] = cs[nt * 2 + p];
                    ssq [wrow * 128 + cl] = cq[nt * 2 + p];
                }
            }
        }
        __syncthreads();
        if (tid < 128) {
            int slot = blockIdx.y * 512 + col0 + tid;
            g_psum[slot] = ssum[tid] + ssum[128 + tid];
            g_psq [slot] = ssq [tid] + ssq [128 + tid];
        }
    }
}

// ---------------------------------------------------------------------------
// Token embedding: circular Conv1d(P->D,k=3) + sinusoidal PE
// ---------------------------------------------------------------------------
#define EMB_SMEM_FLOATS (512 * 49 + 336)
__global__ void embed_kernel(const float* __restrict__ x_enc,
                             const float* __restrict__ tok_w,
                             float* __restrict__ h)
{
    extern __shared__ float sm[];
    float* w_sm = sm;
    float* x_sm = sm + 512 * 49;
    int bm = blockIdx.x;
    int b = bm >> 6, m = bm & 63;
    int tid = threadIdx.x;

    for (int i = tid; i < 512 * 48; i += 256) {
        int d = i / 48, u = i - d * 48;
        w_sm[d * 49 + u] = tok_w[i];
    }
    for (int l = tid; l < 336; l += 256)
        x_sm[l] = x_enc[(b * 336 + l) * 64 + m];
    __syncthreads();

    const float CLOG = -9.210340371976184f / 256.0f;
    int d0 = tid, d1 = tid + 256;
    float fr0 = expf((float)(d0 >> 1) * CLOG);
    float fr1 = expf((float)(d1 >> 1) * CLOG);

    for (int n = 0; n < NTOK; n++) {
        float a0 = 0.f, a1 = 0.f;
        #pragma unroll
        for (int t = 0; t < 3; t++) {
            int pp = n - 1 + t;
            pp = (pp < 0) ? (NTOK - 1) : (pp >= NTOK ? 0 : pp);
            const float* xp = x_sm + pp * 4;
            #pragma unroll
            for (int p = 0; p < 16; p++) {
                float xv = xp[p];
                a0 += xv * w_sm[d0 * 49 + p * 3 + t];
                a1 += xv * w_sm[d1 * 49 + p * 3 + t];
            }
        }
        float ang0 = (float)n * fr0, ang1 = (float)n * fr1;
        float pe0 = (d0 & 1) ? cosf(ang0) : sinf(ang0);
        float pe1 = (d1 & 1) ? cosf(ang1) : sinf(ang1);
        size_t base = ((size_t)bm * NTOK + n) * DM;
        h[base + d0] = a0 + pe0;
        h[base + d1] = a1 + pe1;
    }
}

// ---------------------------------------------------------------------------
// Tensor-core attention per (bm, head).
// Scores: M=96(pad) x N=128(pad) x K=64 tf32 mma; softmax; AV: M=96 x N=64 x
// K=128 with V transposed in smem. Pads are zeroed -> exact zeros, no NaNs.
// ---------------------------------------------------------------------------
#define QP 68                 // pitch for Q/K smem (floats)
#define SP 132                // pitch for S and Vt smem (floats)
#define OFF_K  (96 * QP)                    // 6528
#define OFF_VT (OFF_K + 128 * QP)           // 15232
#define OFF_S  (OFF_VT + 64 * SP)           // 23680
#define AT_SMEM ((OFF_S + 96 * SP) * 4)     // 145408 B

__global__ __launch_bounds__(256)
void attn_mma_kernel(const float* __restrict__ q,
                     const float* __restrict__ k,
                     const float* __restrict__ v,
                     float* __restrict__ o)
{
    extern __shared__ float sm[];
    float* Qs = sm;
    float* Ks = sm + OFF_K;
    float* Vt = sm + OFF_VT;
    float* Ss = sm + OFF_S;

    int bmh = blockIdx.x;
    int bm = bmh >> 3, hh = bmh & 7;
    int tid = threadIdx.x;
    int wid = tid >> 5, lane = tid & 31;
    int qg = lane >> 2, qt = lane & 3;
    int lg = lane >> 3, lr = lane & 7;
    size_t base = (size_t)bm * NTOK * DM + hh * EH;

    // zero pads: Q rows 81..95, K rows 81..127, Vt cols 81..127
    for (int i = tid; i < 15 * QP; i += 256) Qs[81 * QP + i] = 0.f;
    for (int i = tid; i < 47 * QP; i += 256) Ks[81 * QP + i] = 0.f;
    for (int i = tid; i < 64 * 47; i += 256) {
        int e = i / 47, c = 81 + (i % 47);
        Vt[e * SP + c] = 0.f;
    }

    // loads
    const float4* gq = (const float4*)(q + base);
    const float4* gk = (const float4*)(k + base);
    for (int i = tid; i < NTOK * 16; i += 256) {
        int n = i >> 4, e4 = i & 15;
        *(float4*)&Qs[n * QP + e4 * 4] = gq[n * 128 + e4];
        *(float4*)&Ks[n * QP + e4 * 4] = gk[n * 128 + e4];
    }
    for (int i = tid; i < NTOK * 64; i += 256) {
        int s = i >> 6, e = i & 63;
        Vt[e * SP + s] = v[base + (size_t)s * DM + e];
    }
    __syncthreads();

    uint32_t qsu = smem_u32(Qs), ksu = smem_u32(Ks);
    uint32_t vtu = smem_u32(Vt), ssu = smem_u32(Ss);

    // ---- scores: warp grid 2(m) x 4(n); warp tile 48 x 32 ----
    {
        int wm = (wid >> 2) * 48;
        int wn = (wid & 3) * 32;
        uint32_t baseA[3], baseB[2];
        #pragma unroll
        for (int mt = 0; mt < 3; mt++)
            baseA[mt] = qsu + (((wm + mt * 16 + (lg & 1) * 8 + lr) * QP) + (lg >> 1) * 4) * 4;
        #pragma unroll
        for (int p = 0; p < 2; p++)
            baseB[p]  = ksu + (((wn + (2 * p + (lg >> 1)) * 8 + lr) * QP) + (lg & 1) * 4) * 4;

        float acc[3][4][4];
        #pragma unroll
        for (int mt = 0; mt < 3; mt++)
            #pragma unroll
            for (int nt = 0; nt < 4; nt++)
                #pragma unroll
                for (int j = 0; j < 4; j++) acc[mt][nt][j] = 0.f;

        #pragma unroll
        for (int ks = 0; ks < 8; ks++) {
            uint32_t kB = ks * 32;
            uint32_t af[3][4], bf[4][2];
            #pragma unroll
            for (int mt = 0; mt < 3; mt++)
                ldsm_x4(af[mt], baseA[mt] + kB);
            #pragma unroll
            for (int p = 0; p < 2; p++) {
                uint32_t t[4];
                ldsm_x4(t, baseB[p] + kB);
                bf[2 * p][0] = t[0]; bf[2 * p][1] = t[1];
                bf[2 * p + 1][0] = t[2]; bf[2 * p + 1][1] = t[3];
            }
            #pragma unroll
            for (int mt = 0; mt < 3; mt++)
                #pragma unroll
                for (int nt = 0; nt < 4; nt++)
                    mma_tf32(acc[mt][nt], af[mt], bf[nt]);
        }

        #pragma unroll
        for (int mt = 0; mt < 3; mt++) {
            #pragma unroll
            for (int nt = 0; nt < 4; nt++) {
                int c  = wn + nt * 8 + 2 * qt;
                int r0 = wm + mt * 16 + qg;
                #pragma unroll
                for (int half = 0; half < 2; half++) {
                    int r = r0 + half * 8;
                    *(float2*)&Ss[r * SP + c] = make_float2(
                        acc[mt][nt][half * 2 + 0] * 0.125f,
                        acc[mt][nt][half * 2 + 1] * 0.125f);
                }
            }
        }
    }
    __syncthreads();

    // ---- softmax: one warp per row (rows 0..80); zero pad cols ----
    for (int l = wid; l < NTOK; l += 8) {
        float* row = Ss + l * SP;
        float mx = -1e30f;
        for (int s2 = lane; s2 < NTOK; s2 += 32) mx = fmaxf(mx, row[s2]);
        #pragma unroll
        for (int m = 16; m; m >>= 1) mx = fmaxf(mx, __shfl_xor_sync(0xffffffffu, mx, m));
        float sum = 0.f;
        for (int s2 = lane; s2 < NTOK; s2 += 32) {
            float t = __expf(row[s2] - mx);
            row[s2] = t; sum += t;
        }
        #pragma unroll
        for (int m = 16; m; m >>= 1) sum += __shfl_xor_sync(0xffffffffu, sum, m);
        float inv = 1.0f / sum;
        for (int s2 = lane; s2 < NTOK; s2 += 32) row[s2] *= inv;
        for (int s2 = NTOK + lane; s2 < 128; s2 += 32) row[s2] = 0.f;
    }
    __syncthreads();

    // ---- AV: warp grid 2(m) x 4(n); warp tile 48 x 16; K=128 ----
    {
        int wm = (wid >> 2) * 48;
        int wn = (wid & 3) * 16;
        uint32_t baseA[3], baseB;
        #pragma unroll
        for (int mt = 0; mt < 3; mt++)
            baseA[mt] = ssu + (((wm + mt * 16 + (lg & 1) * 8 + lr) * SP) + (lg >> 1) * 4) * 4;
        baseB = vtu + (((wn + (lg >> 1) * 8 + lr) * SP) + (lg & 1) * 4) * 4;

        float acc[3][2][4];
        #pragma unroll
        for (int mt = 0; mt < 3; mt++)
            #pragma unroll
            for (int nt = 0; nt < 2; nt++)
                #pragma unroll
                for (int j = 0; j < 4; j++) acc[mt][nt][j] = 0.f;

        #pragma unroll
        for (int ks = 0; ks < 16; ks++) {
            uint32_t kB = ks * 32;
            uint32_t af[3][4], bf[2][2];
            #pragma unroll
            for (int mt = 0; mt < 3; mt++)
                ldsm_x4(af[mt], baseA[mt] + kB);
            {
                uint32_t t[4];
                ldsm_x4(t, baseB + kB);
                bf[0][0] = t[0]; bf[0][1] = t[1];
                bf[1][0] = t[2]; bf[1][1] = t[3];
            }
            #pragma unroll
            for (int mt = 0; mt < 3; mt++)
                #pragma unroll
                for (int nt = 0; nt < 2; nt++)
                    mma_tf32(acc[mt][nt], af[mt], bf[nt]);
        }

        #pragma unroll
        for (int mt = 0; mt < 3; mt++) {
            #pragma unroll
            for (int nt = 0; nt < 2; nt++) {
                int c  = wn + nt * 8 + 2 * qt;
                int r0 = wm + mt * 16 + qg;
                #pragma unroll
                for (int half = 0; half < 2; half++) {
                    int r = r0 + half * 8;
                    if (r < NTOK)
                        *(float2*)&o[base + (size_t)r * DM + c] = make_float2(
                            acc[mt][nt][half * 2 + 0],
                            acc[mt][nt][half * 2 + 1]);
                }
            }
        }
    }
}

// ---------------------------------------------------------------------------
// BN finalize: one block per channel, sum RTILES partials -> scale/shift
// ---------------------------------------------------------------------------
__global__ void bn_reduce2_kernel(const float* __restrict__ gamma,
                                  const float* __restrict__ beta,
                                  float* __restrict__ scl,
                                  float* __restrict__ shf)
{
    int c = blockIdx.x;
    int tid = threadIdx.x, wid = tid >> 5, lane = tid & 31;
    float s = 0.f, q = 0.f;
    for (int j = tid; j < RTILES; j += 256) {
        s += g_psum[j * 512 + c];
        q += g_psq [j * 512 + c];
    }
    #pragma unroll
    for (int m = 16; m; m >>= 1) {
        s += __shfl_xor_sync(0xffffffffu, s, m);
        q += __shfl_xor_sync(0xffffffffu, q, m);
    }
    __shared__ float rs[8], rq[8];
    if (lane == 0) { rs[wid] = s; rq[wid] = q; }
    __syncthreads();
    if (tid == 0) {
        float S = 0.f, Q = 0.f;
        #pragma unroll
        for (int w = 0; w < 8; w++) { S += rs[w]; Q += rq[w]; }
        const float invn = 1.0f / (float)RT;
        float mu  = S * invn;
        float var = Q * invn - mu * mu;
        float rinv = rsqrtf(var + 1e-5f);
        float sc = rinv * gamma[c];
        scl[c] = sc;
        shf[c] = beta[c] - mu * sc;
    }
}

__global__ void bn_norm_kernel(const float* __restrict__ y,
                               const float* __restrict__ scl,
                               const float* __restrict__ shf,
                               float* __restrict__ out)
{
    const int total = RT * DM / 4;
    for (int i = blockIdx.x * blockDim.x + threadIdx.x; i < total;
         i += gridDim.x * blockDim.x) {
        float4 vv = ((const float4*)y)[i];
        int c = (i & 127) * 4;
        float4 oo;
        oo.x = vv.x * scl[c + 0] + shf[c + 0];
        oo.y = vv.y * scl[c + 1] + shf[c + 1];
        oo.z = vv.z * scl[c + 2] + shf[c + 2];
        oo.w = vv.w * scl[c + 3] + shf[c + 3];
        ((float4*)out)[i] = oo;
    }
}

// ---------------------------------------------------------------------------
// Orchestration
// ---------------------------------------------------------------------------
extern "C" void kernel_launch(void* const* d_in, const int* in_sizes, int n_in,
                              void* d_out, int out_size)
{
    const float* x_enc = (const float*)d_in[0];
    const float* tok_w = (const float*)d_in[1];
    const float* wq  = (const float*)d_in[2];
    const float* bq  = (const float*)d_in[3];
    const float* wk  = (const float*)d_in[4];
    const float* bk  = (const float*)d_in[5];
    const float* wv  = (const float*)d_in[6];
    const float* bv  = (const float*)d_in[7];
    const float* wo  = (const float*)d_in[8];
    const float* bo  = (const float*)d_in[9];
    const float* c1w = (const float*)d_in[10];
    const float* c1b = (const float*)d_in[11];
    const float* c2w = (const float*)d_in[12];
    const float* c2b = (const float*)d_in[13];
    const float* g1  = (const float*)d_in[14];
    const float* be1 = (const float*)d_in[15];
    const float* g2  = (const float*)d_in[16];
    const float* be2 = (const float*)d_in[17];
    float* out = (float*)d_out;

    float *p_h, *p_q, *p_k, *p_v, *p_att, *p_y, *p_t, *p_scl, *p_shf;
    cudaGetSymbolAddress((void**)&p_h,   g_h);
    cudaGetSymbolAddress((void**)&p_q,   g_q);
    cudaGetSymbolAddress((void**)&p_k,   g_k);
    cudaGetSymbolAddress((void**)&p_v,   g_v);
    cudaGetSymbolAddress((void**)&p_att, g_att);
    cudaGetSymbolAddress((void**)&p_y,   g_y);
    cudaGetSymbolAddress((void**)&p_t,   g_t);
    cudaGetSymbolAddress((void**)&p_scl, g_bnscale);
    cudaGetSymbolAddress((void**)&p_shf, g_bnshift);
    float* scl0 = p_scl;       float* shf0 = p_shf;
    float* scl1 = p_scl + 512; float* shf1 = p_shf + 512;

    const int EMB_SMEM = EMB_SMEM_FLOATS * 4;
    cudaFuncSetAttribute(embed_kernel,
        cudaFuncAttributeMaxDynamicSharedMemorySize, EMB_SMEM);
    cudaFuncSetAttribute(attn_mma_kernel,
        cudaFuncAttributeMaxDynamicSharedMemorySize, AT_SMEM);
    cudaFuncSetAttribute(mma_gemm<0, 0, 0>,
        cudaFuncAttributeMaxDynamicSharedMemorySize, GEMM_SMEM);
    cudaFuncSetAttribute(mma_gemm<0, 1, 0>,
        cudaFuncAttributeMaxDynamicSharedMemorySize, GEMM_SMEM);
    cudaFuncSetAttribute(mma_gemm<2, 0, 1>,
        cudaFuncAttributeMaxDynamicSharedMemorySize, GEMM_SMEM);
    cudaFuncSetAttribute(mma_gemm<2, 2, 1>,
        cudaFuncAttributeMaxDynamicSharedMemorySize, GEMM_SMEM);
    cudaFuncSetAttribute(mma_gemm<1, 1, 0>,
        cudaFuncAttributeMaxDynamicSharedMemorySize, GEMM_SMEM);

    embed_kernel<<<2048, 256, EMB_SMEM>>>(x_enc, tok_w, p_h);

    for (int l = 0; l < NL; l++) {
        const int WOFF = l * DM * DM;
        const int FOFF = l * DFF * DM;

        if (l == 0) {
            mma_gemm<0, 0, 0><<<dim3(4, RTILES), 256, GEMM_SMEM>>>(p_h, wq + WOFF,
                bq + l * DM, nullptr, nullptr, nullptr, p_q, DM);
            mma_gemm<0, 0, 0><<<dim3(4, RTILES), 256, GEMM_SMEM>>>(p_h, wk + WOFF,
                bk + l * DM, nullptr, nullptr, nullptr, p_k, DM);
            mma_gemm<0, 0, 0><<<dim3(4, RTILES), 256, GEMM_SMEM>>>(p_h, wv + WOFF,
                bv + l * DM, nullptr, nullptr, nullptr, p_v, DM);
        } else {
            mma_gemm<0, 1, 0><<<dim3(4, RTILES), 256, GEMM_SMEM>>>(p_h, wq + WOFF,
                bq + l * DM, nullptr, scl1, shf1, p_q, DM);
            mma_gemm<0, 1, 0><<<dim3(4, RTILES), 256, GEMM_SMEM>>>(p_h, wk + WOFF,
                bk + l * DM, nullptr, scl1, shf1, p_k, DM);
            mma_gemm<0, 1, 0><<<dim3(4, RTILES), 256, GEMM_SMEM>>>(p_h, wv + WOFF,
                bv + l * DM, nullptr, scl1, shf1, p_v, DM);
        }

        attn_mma_kernel<<<2048 * NH, 256, AT_SMEM>>>(p_q, p_k, p_v, p_att);

        if (l == 0)
            mma_gemm<2, 0, 1><<<dim3(4, RTILES), 256, GEMM_SMEM>>>(p_att, wo + WOFF,
                bo + l * DM, p_h, nullptr, nullptr, p_y, DM);
        else
            mma_gemm<2, 2, 1><<<dim3(4, RTILES), 256, GEMM_SMEM>>>(p_att, wo + WOFF,
                bo + l * DM, p_h, scl1, shf1, p_y, DM);

        bn_reduce2_kernel<<<512, 256>>>(g1 + l * DM, be1 + l * DM, scl0, shf0);

        mma_gemm<1, 1, 0><<<dim3(8, RTILES), 256, GEMM_SMEM>>>(p_y, c1w + FOFF,
            c1b + l * DFF, nullptr, scl0, shf0, p_t, DM);
        mma_gemm<2, 2, 1><<<dim3(4, RTILES), 256, GEMM_SMEM>>>(p_t, c2w + FOFF,
            c2b + l * DM, p_y, scl0, shf0, p_h, DFF);

        bn_reduce2_kernel<<<512, 256>>>(g2 + l * DM, be2 + l * DM, scl1, shf1);
    }

    bn_norm_kernel<<<4096, 256>>>(p_h, scl1, shf1, out);
}

// round 11
// speedup vs baseline: 1.4595x; 1.4595x over previous
#include <cuda_runtime.h>
#include <cuda_fp16.h>
#include <math.h>
#include <stdint.h>

// ---------------------------------------------------------------------------
// Problem constants
// ---------------------------------------------------------------------------
#define NTOK   81
#define DM     512
#define NH     8
#define EH     64
#define DFF    1024
#define NL     3
#define RT     (2048 * 81)           // 165888 tokens
#define RTILES (RT / 128)            // 1296

// ---------------------------------------------------------------------------
// Scratch (device globals: no cudaMalloc allowed)
// ---------------------------------------------------------------------------
__device__ float g_h  [RT * DM];     // embed out / raw y2 (fp32)
__device__ float g_q  [RT * DM];
__device__ float g_k  [RT * DM];
__device__ float g_v  [RT * DM];
__device__ float g_y  [RT * DM];     // raw y1 (fp32)
__device__ __half g_h_h  [RT * DM];  // half copy of h / y2
__device__ __half g_att_h[RT * DM];  // attention out (half only)
__device__ __half g_y_h  [RT * DM];  // half copy of y1
__device__ __half g_t_h  [RT * DFF]; // FFN mid (half only)
__device__ __half g_wq_h[NL * DM * DM];
__device__ __half g_wk_h[NL * DM * DM];
__device__ __half g_wv_h[NL * DM * DM];
__device__ __half g_wo_h[NL * DM * DM];
__device__ __half g_c1_h[NL * DFF * DM];
__device__ __half g_c2_h[NL * DM * DFF];
__device__ float g_psum[RTILES * 512];
__device__ float g_psq [RTILES * 512];
__device__ float  g_bnscale[2 * 512];
__device__ float  g_bnshift[2 * 512];
__device__ __half g_bnscaleh[2 * 512];
__device__ __half g_bnshifth[2 * 512];

// ---------------------------------------------------------------------------
// PTX helpers
// ---------------------------------------------------------------------------
__device__ __forceinline__ uint32_t smem_u32(const void* p) {
    uint32_t a;
    asm("{ .reg .u64 t; cvta.to.shared.u64 t, %1; cvt.u32.u64 %0, t; }"
        : "=r"(a) : "l"(p));
    return a;
}

__device__ __forceinline__ void cp16(uint32_t dst, const void* src) {
    asm volatile("cp.async.cg.shared.global [%0], [%1], 16;"
                 :: "r"(dst), "l"(src) : "memory");
}
#define CP_COMMIT() asm volatile("cp.async.commit_group;" ::: "memory")

__device__ __forceinline__ void mma_f16(float* c, const uint32_t* a, const uint32_t* b) {
    asm volatile(
        "mma.sync.aligned.m16n8k16.row.col.f32.f16.f16.f32 "
        "{%0,%1,%2,%3}, {%4,%5,%6,%7}, {%8,%9}, {%0,%1,%2,%3};"
        : "+f"(c[0]), "+f"(c[1]), "+f"(c[2]), "+f"(c[3])
        : "r"(a[0]), "r"(a[1]), "r"(a[2]), "r"(a[3]), "r"(b[0]), "r"(b[1]));
}

__device__ __forceinline__ void ldsm_x4(uint32_t* r, uint32_t addr) {
    asm volatile("ldmatrix.sync.aligned.m8n8.x4.shared.b16 {%0,%1,%2,%3}, [%4];"
        : "=r"(r[0]), "=r"(r[1]), "=r"(r[2]), "=r"(r[3]) : "r"(addr));
}

// ---------------------------------------------------------------------------
// FP16 GEMM: C[r,o] = sum_k A[r,k]*W[o,k] (+bias), fp32 accumulate.
// CTA 128x128, BK=64, 8 warps (2x4), warp tile 64x32, 2 CTAs/SM,
// 3-stage cp.async.cg. m16n8k16 HMMA.
// EPI: 0=bias, 1=bias+gelu, 2=bias+residual
// AFF: 0=none, 1=half2 affine on A fragments (per-K), 2=fp32 affine on residual
// STATS: per-CTA column sum/sumsq partials;  WF: write fp32 C;  WH: write half C
// ---------------------------------------------------------------------------
#define PHB 144                          // bytes per smem row (72 halves)
#define A_HALF_B (128 * PHB)             // 18432
#define STAGE_B (2 * A_HALF_B)           // 36864
#define GEMM_SMEM (3 * STAGE_B)          // 110592 B

template <int EPI, int AFF, int STATS, int WF, int WH>
__global__ __launch_bounds__(256, 2)
void mma_gemm(const __half* __restrict__ A, const __half* __restrict__ W,
              const float* __restrict__ bias, const float* __restrict__ res,
              const float* __restrict__ scl, const float* __restrict__ shf,
              const __half* __restrict__ sclh, const __half* __restrict__ shfh,
              float* __restrict__ C, __half* __restrict__ Ch, int K)
{
    extern __shared__ float smf[];
    uint32_t sA = smem_u32(smf);
    uint32_t sB = sA + A_HALF_B;

    int tid  = threadIdx.x;
    int wid  = tid >> 5, lane = tid & 31;
    int wm   = (wid >> 2) * 64;
    int wn   = (wid & 3) * 32;
    int row0 = blockIdx.y * 128, col0 = blockIdx.x * 128;
    int Dout = gridDim.x * 128;
    int qg   = lane >> 2, qt = lane & 3;
    int lg   = lane >> 3, lr = lane & 7;

    uint32_t baseA[4], baseB[2];
    #pragma unroll
    for (int mt = 0; mt < 4; mt++)
        baseA[mt] = sA + (wm + mt * 16 + (lg & 1) * 8 + lr) * PHB + (lg >> 1) * 16;
    #pragma unroll
    for (int p = 0; p < 2; p++)
        baseB[p]  = sB + (wn + (2 * p + (lg & 1)) * 8 + lr) * PHB + (lg >> 1) * 16;

    auto issue = [&](int st, int kb2) {
        uint32_t o = st * STAGE_B;
        #pragma unroll
        for (int i = 0; i < 4; i++) {
            int slot = tid + 256 * i;
            int row = slot >> 3, c16 = slot & 7;
            uint32_t d = o + row * PHB + c16 * 16;
            cp16(sA + d, A + (size_t)(row0 + row) * K + kb2 * 64 + c16 * 8);
            cp16(sB + d, W + (size_t)(col0 + row) * K + kb2 * 64 + c16 * 8);
        }
        CP_COMMIT();
    };

    int NKB = K / 64;
    issue(0, 0);
    if (NKB > 1) issue(1, 1);

    float acc[4][4][4];
    #pragma unroll
    for (int mt = 0; mt < 4; mt++)
        #pragma unroll
        for (int nt = 0; nt < 4; nt++)
            #pragma unroll
            for (int j = 0; j < 4; j++) acc[mt][nt][j] = 0.f;

    int st = 0, nst = 2;
    for (int kb = 0; kb < NKB; kb++) {
        if (kb + 1 < NKB)
            asm volatile("cp.async.wait_group 1;" ::: "memory");
        else
            asm volatile("cp.async.wait_group 0;" ::: "memory");
        __syncthreads();
        if (kb + 2 < NKB) {
            issue(nst, kb + 2);
            if (++nst == 3) nst = 0;
        }

        uint32_t stOff = st * STAGE_B;
        #pragma unroll
        for (int ks = 0; ks < 4; ks++) {
            uint32_t kB = stOff + ks * 32;        // 16 halves per ks-step
            uint32_t af[4][4], bf[4][2];
            #pragma unroll
            for (int mt = 0; mt < 4; mt++)
                ldsm_x4(af[mt], baseA[mt] + kB);
            #pragma unroll
            for (int p = 0; p < 2; p++) {
                uint32_t t[4];
                ldsm_x4(t, baseB[p] + kB);
                bf[2 * p][0]     = t[0]; bf[2 * p][1]     = t[2];
                bf[2 * p + 1][0] = t[1]; bf[2 * p + 1][1] = t[3];
            }
            if (AFF == 1) {
                int kg = kb * 64 + ks * 16 + 2 * qt;
                __half2 s_lo = *(const __half2*)&sclh[kg];
                __half2 h_lo = *(const __half2*)&shfh[kg];
                __half2 s_hi = *(const __half2*)&sclh[kg + 8];
                __half2 h_hi = *(const __half2*)&shfh[kg + 8];
                #pragma unroll
                for (int mt = 0; mt < 4; mt++) {
                    __half2 v0 = *(__half2*)&af[mt][0];
                    __half2 v1 = *(__half2*)&af[mt][1];
                    __half2 v2 = *(__half2*)&af[mt][2];
                    __half2 v3 = *(__half2*)&af[mt][3];
                    v0 = __hfma2(v0, s_lo, h_lo);
                    v1 = __hfma2(v1, s_lo, h_lo);
                    v2 = __hfma2(v2, s_hi, h_hi);
                    v3 = __hfma2(v3, s_hi, h_hi);
                    af[mt][0] = *(uint32_t*)&v0;
                    af[mt][1] = *(uint32_t*)&v1;
                    af[mt][2] = *(uint32_t*)&v2;
                    af[mt][3] = *(uint32_t*)&v3;
                }
            }
            #pragma unroll
            for (int mt = 0; mt < 4; mt++)
                #pragma unroll
                for (int nt = 0; nt < 4; nt++)
                    mma_f16(acc[mt][nt], af[mt], bf[nt]);
        }
        if (++st == 3) st = 0;
    }

    // epilogue
    float cs[8], cq[8];
    if (STATS) {
        #pragma unroll
        for (int j = 0; j < 8; j++) { cs[j] = 0.f; cq[j] = 0.f; }
    }

    #pragma unroll
    for (int mt = 0; mt < 4; mt++) {
        #pragma unroll
        for (int nt = 0; nt < 4; nt++) {
            int c  = col0 + wn + nt * 8 + 2 * qt;
            int r0 = row0 + wm + mt * 16 + qg;
            float b0 = bias[c], b1 = bias[c + 1];
            float s0 = 1.f, s1 = 1.f, h0 = 0.f, h1 = 0.f;
            if (AFF == 2) {
                s0 = scl[c]; s1 = scl[c + 1];
                h0 = shf[c]; h1 = shf[c + 1];
            }
            #pragma unroll
            for (int half = 0; half < 2; half++) {
                int r = r0 + half * 8;
                float vx = acc[mt][nt][half * 2 + 0] + b0;
                float vy = acc[mt][nt][half * 2 + 1] + b1;
                if (EPI == 1) {
                    vx = 0.5f * vx * (1.0f + erff(vx * 0.70710678118654752f));
                    vy = 0.5f * vy * (1.0f + erff(vy * 0.70710678118654752f));
                }
                size_t off = (size_t)r * Dout + c;
                if (EPI == 2) {
                    float2 rv = *(const float2*)(res + off);
                    if (AFF == 2) { vx += s0 * rv.x + h0; vy += s1 * rv.y + h1; }
                    else          { vx += rv.x;           vy += rv.y; }
                }
                if (STATS) {
                    cs[nt * 2 + 0] += vx; cq[nt * 2 + 0] += vx * vx;
                    cs[nt * 2 + 1] += vy; cq[nt * 2 + 1] += vy * vy;
                }
                if (WF)
                    *(float2*)(C + off) = make_float2(vx, vy);
                if (WH) {
                    __half2 hv = __floats2half2_rn(vx, vy);
                    *(__half2*)(Ch + off) = hv;
                }
            }
        }
    }

    if (STATS) {
        #pragma unroll
        for (int j = 0; j < 8; j++) {
            #pragma unroll
            for (int m = 4; m <= 16; m <<= 1) {
                cs[j] += __shfl_xor_sync(0xffffffffu, cs[j], m);
                cq[j] += __shfl_xor_sync(0xffffffffu, cq[j], m);
            }
        }
        __syncthreads();
        float* ssum = smf;
        float* ssq  = smf + 256;
        int wrow = wid >> 2;
        if (lane < 4) {
            #pragma unroll
            for (int nt = 0; nt < 4; nt++) {
                #pragma unroll
                for (int p = 0; p < 2; p++) {
                    int cl = wn + nt * 8 + 2 * qt + p;
                    ssum[wrow * 128 + cl] = cs[nt * 2 + p];
                    ssq [wrow * 128 + cl] = cq[nt * 2 + p];
                }
            }
        }
        __syncthreads();
        if (tid < 128) {
            int slot = blockIdx.y * 512 + col0 + tid;
            g_psum[slot] = ssum[tid] + ssum[128 + tid];
            g_psq [slot] = ssq [tid] + ssq [128 + tid];
        }
    }
}

// ---------------------------------------------------------------------------
// fp32 -> fp16 conversion (weights)
// ---------------------------------------------------------------------------
__global__ void f2h_kernel(const float* __restrict__ src, __half* __restrict__ dst,
                           int n)
{
    for (int i = blockIdx.x * blockDim.x + threadIdx.x; i < n / 2;
         i += gridDim.x * blockDim.x) {
        float2 v = ((const float2*)src)[i];
        ((__half2*)dst)[i] = __floats2half2_rn(v.x, v.y);
    }
}

// ---------------------------------------------------------------------------
// Token embedding: circular Conv1d(P->D,k=3) + sinusoidal PE (fp32 + half out)
// ---------------------------------------------------------------------------
#define EMB_SMEM_FLOATS (512 * 49 + 336)
__global__ void embed_kernel(const float* __restrict__ x_enc,
                             const float* __restrict__ tok_w,
                             float* __restrict__ h, __half* __restrict__ hh)
{
    extern __shared__ float sm[];
    float* w_sm = sm;
    float* x_sm = sm + 512 * 49;
    int bm = blockIdx.x;
    int b = bm >> 6, m = bm & 63;
    int tid = threadIdx.x;

    for (int i = tid; i < 512 * 48; i += 256) {
        int d = i / 48, u = i - d * 48;
        w_sm[d * 49 + u] = tok_w[i];
    }
    for (int l = tid; l < 336; l += 256)
        x_sm[l] = x_enc[(b * 336 + l) * 64 + m];
    __syncthreads();

    const float CLOG = -9.210340371976184f / 256.0f;
    int d0 = tid, d1 = tid + 256;
    float fr0 = expf((float)(d0 >> 1) * CLOG);
    float fr1 = expf((float)(d1 >> 1) * CLOG);

    for (int n = 0; n < NTOK; n++) {
        float a0 = 0.f, a1 = 0.f;
        #pragma unroll
        for (int t = 0; t < 3; t++) {
            int pp = n - 1 + t;
            pp = (pp < 0) ? (NTOK - 1) : (pp >= NTOK ? 0 : pp);
            const float* xp = x_sm + pp * 4;
            #pragma unroll
            for (int p = 0; p < 16; p++) {
                float xv = xp[p];
                a0 += xv * w_sm[d0 * 49 + p * 3 + t];
                a1 += xv * w_sm[d1 * 49 + p * 3 + t];
            }
        }
        float ang0 = (float)n * fr0, ang1 = (float)n * fr1;
        float pe0 = (d0 & 1) ? cosf(ang0) : sinf(ang0);
        float pe1 = (d1 & 1) ? cosf(ang1) : sinf(ang1);
        size_t base = ((size_t)bm * NTOK + n) * DM;
        float v0 = a0 + pe0, v1 = a1 + pe1;
        h[base + d0] = v0;
        h[base + d1] = v1;
        hh[base + d0] = __float2half(v0);
        hh[base + d1] = __float2half(v1);
    }
}

// ---------------------------------------------------------------------------
// Fused attention per (bm, head) — R8 design (fp32, many CTAs/SM); half output
// ---------------------------------------------------------------------------
#define QPAD 17
#define SPAD 84
#define ATTN_SMEM_FLOATS (3 * 81 * 68 + 81 * SPAD)
__global__ void attn_kernel(const float* __restrict__ q,
                            const float* __restrict__ k,
                            const float* __restrict__ v,
                            __half* __restrict__ o)
{
    extern __shared__ float sm[];
    float4* qs4 = (float4*)sm;
    float4* ks4 = qs4 + 81 * QPAD;
    float4* vs4 = ks4 + 81 * QPAD;
    float*  ss  = sm + 3 * 81 * 68;
    int bmh = blockIdx.x;
    int bm = bmh >> 3, hh = bmh & 7;
    int tid = threadIdx.x;
    int wid = tid >> 5, lane = tid & 31;
    size_t base = (size_t)bm * NTOK * DM + hh * EH;

    const float4* gq = (const float4*)(q + base);
    const float4* gk = (const float4*)(k + base);
    const float4* gv = (const float4*)(v + base);
    for (int i = tid; i < NTOK * 16; i += 256) {
        int n = i >> 4, e4 = i & 15;
        int gi = n * 128 + e4;
        qs4[n * QPAD + e4] = gq[gi];
        ks4[n * QPAD + e4] = gk[gi];
        vs4[n * QPAD + e4] = gv[gi];
    }
    __syncthreads();

    for (int i = tid; i < 729; i += 256) {
        int l0 = (i / 27) * 3, s0 = (i % 27) * 3;
        float acc[3][3] = {};
        #pragma unroll 4
        for (int e4 = 0; e4 < 16; e4++) {
            float4 qv[3], kv[3];
            #pragma unroll
            for (int j = 0; j < 3; j++) {
                qv[j] = qs4[(l0 + j) * QPAD + e4];
                kv[j] = ks4[(s0 + j) * QPAD + e4];
            }
            #pragma unroll
            for (int a = 0; a < 3; a++)
                #pragma unroll
                for (int b2 = 0; b2 < 3; b2++)
                    acc[a][b2] += qv[a].x * kv[b2].x + qv[a].y * kv[b2].y
                                + qv[a].z * kv[b2].z + qv[a].w * kv[b2].w;
        }
        #pragma unroll
        for (int a = 0; a < 3; a++)
            #pragma unroll
            for (int b2 = 0; b2 < 3; b2++)
                ss[(l0 + a) * SPAD + s0 + b2] = acc[a][b2] * 0.125f;
    }
    __syncthreads();

    for (int l = wid; l < NTOK; l += 8) {
        float* row = ss + l * SPAD;
        float mx = -1e30f;
        for (int s2 = lane; s2 < NTOK; s2 += 32) mx = fmaxf(mx, row[s2]);
        #pragma unroll
        for (int m = 16; m; m >>= 1) mx = fmaxf(mx, __shfl_xor_sync(0xffffffffu, mx, m));
        float sum = 0.f;
        for (int s2 = lane; s2 < NTOK; s2 += 32) {
            float t = __expf(row[s2] - mx);
            row[s2] = t; sum += t;
        }
        #pragma unroll
        for (int m = 16; m; m >>= 1) sum += __shfl_xor_sync(0xffffffffu, sum, m);
        float inv = 1.0f / sum;
        for (int s2 = lane; s2 < NTOK; s2 += 32) row[s2] *= inv;
    }
    __syncthreads();

    for (int i = tid; i < 432; i += 256) {
        int l0 = (i / 16) * 3, e4 = i % 16;
        float4 acc[3] = {};
        for (int s2 = 0; s2 < NTOK; s2++) {
            float4 vv = vs4[s2 * QPAD + e4];
            #pragma unroll
            for (int j = 0; j < 3; j++) {
                float a = ss[(l0 + j) * SPAD + s2];
                acc[j].x += a * vv.x; acc[j].y += a * vv.y;
                acc[j].z += a * vv.z; acc[j].w += a * vv.w;
            }
        }
        #pragma unroll
        for (int j = 0; j < 3; j++) {
            size_t ob = base + (size_t)(l0 + j) * DM + e4 * 4;
            *(__half2*)(o + ob)     = __floats2half2_rn(acc[j].x, acc[j].y);
            *(__half2*)(o + ob + 2) = __floats2half2_rn(acc[j].z, acc[j].w);
        }
    }
}

// ---------------------------------------------------------------------------
// BN finalize: one block per channel -> fp32 + half scale/shift
// ---------------------------------------------------------------------------
__global__ void bn_reduce2_kernel(const float* __restrict__ gamma,
                                  const float* __restrict__ beta,
                                  float* __restrict__ scl, float* __restrict__ shf,
                                  __half* __restrict__ sclh, __half* __restrict__ shfh)
{
    int c = blockIdx.x;
    int tid = threadIdx.x, wid = tid >> 5, lane = tid & 31;
    float s = 0.f, q = 0.f;
    for (int j = tid; j < RTILES; j += 256) {
        s += g_psum[j * 512 + c];
        q += g_psq [j * 512 + c];
    }
    #pragma unroll
    for (int m = 16; m; m >>= 1) {
        s += __shfl_xor_sync(0xffffffffu, s, m);
        q += __shfl_xor_sync(0xffffffffu, q, m);
    }
    __shared__ float rs[8], rq[8];
    if (lane == 0) { rs[wid] = s; rq[wid] = q; }
    __syncthreads();
    if (tid == 0) {
        float S = 0.f, Q = 0.f;
        #pragma unroll
        for (int w = 0; w < 8; w++) { S += rs[w]; Q += rq[w]; }
        const float invn = 1.0f / (float)RT;
        float mu  = S * invn;
        float var = Q * invn - mu * mu;
        float rinv = rsqrtf(var + 1e-5f);
        float sc = rinv * gamma[c];
        float sh = beta[c] - mu * sc;
        scl[c] = sc;  shf[c] = sh;
        sclh[c] = __float2half(sc);
        shfh[c] = __float2half(sh);
    }
}

__global__ void bn_norm_kernel(const float* __restrict__ y,
                               const float* __restrict__ scl,
                               const float* __restrict__ shf,
                               float* __restrict__ out)
{
    const int total = RT * DM / 4;
    for (int i = blockIdx.x * blockDim.x + threadIdx.x; i < total;
         i += gridDim.x * blockDim.x) {
        float4 vv = ((const float4*)y)[i];
        int c = (i & 127) * 4;
        float4 oo;
        oo.x = vv.x * scl[c + 0] + shf[c + 0];
        oo.y = vv.y * scl[c + 1] + shf[c + 1];
        oo.z = vv.z * scl[c + 2] + shf[c + 2];
        oo.w = vv.w * scl[c + 3] + shf[c + 3];
        ((float4*)out)[i] = oo;
    }
}

// ---------------------------------------------------------------------------
// Orchestration
// ---------------------------------------------------------------------------
extern "C" void kernel_launch(void* const* d_in, const int* in_sizes, int n_in,
                              void* d_out, int out_size)
{
    const float* x_enc = (const float*)d_in[0];
    const float* tok_w = (const float*)d_in[1];
    const float* wq  = (const float*)d_in[2];
    const float* bq  = (const float*)d_in[3];
    const float* wk  = (const float*)d_in[4];
    const float* bk  = (const float*)d_in[5];
    const float* wv  = (const float*)d_in[6];
    const float* bv  = (const float*)d_in[7];
    const float* wo  = (const float*)d_in[8];
    const float* bo  = (const float*)d_in[9];
    const float* c1w = (const float*)d_in[10];
    const float* c1b = (const float*)d_in[11];
    const float* c2w = (const float*)d_in[12];
    const float* c2b = (const float*)d_in[13];
    const float* g1  = (const float*)d_in[14];
    const float* be1 = (const float*)d_in[15];
    const float* g2  = (const float*)d_in[16];
    const float* be2 = (const float*)d_in[17];
    float* out = (float*)d_out;

    float *p_h, *p_q, *p_k, *p_v, *p_y, *p_scl, *p_shf;
    __half *p_hh, *p_atth, *p_yh, *p_th, *p_sclh, *p_shfh;
    __half *p_wqh, *p_wkh, *p_wvh, *p_woh, *p_c1h, *p_c2h;
    cudaGetSymbolAddress((void**)&p_h,   g_h);
    cudaGetSymbolAddress((void**)&p_q,   g_q);
    cudaGetSymbolAddress((void**)&p_k,   g_k);
    cudaGetSymbolAddress((void**)&p_v,   g_v);
    cudaGetSymbolAddress((void**)&p_y,   g_y);
    cudaGetSymbolAddress((void**)&p_hh,   g_h_h);
    cudaGetSymbolAddress((void**)&p_atth, g_att_h);
    cudaGetSymbolAddress((void**)&p_yh,   g_y_h);
    cudaGetSymbolAddress((void**)&p_th,   g_t_h);
    cudaGetSymbolAddress((void**)&p_wqh, g_wq_h);
    cudaGetSymbolAddress((void**)&p_wkh, g_wk_h);
    cudaGetSymbolAddress((void**)&p_wvh, g_wv_h);
    cudaGetSymbolAddress((void**)&p_woh, g_wo_h);
    cudaGetSymbolAddress((void**)&p_c1h, g_c1_h);
    cudaGetSymbolAddress((void**)&p_c2h, g_c2_h);
    cudaGetSymbolAddress((void**)&p_scl, g_bnscale);
    cudaGetSymbolAddress((void**)&p_shf, g_bnshift);
    cudaGetSymbolAddress((void**)&p_sclh, g_bnscaleh);
    cudaGetSymbolAddress((void**)&p_shfh, g_bnshifth);
    float*  scl0  = p_scl;        float*  shf0  = p_shf;
    float*  scl1  = p_scl + 512;  float*  shf1  = p_shf + 512;
    __half* scl0h = p_sclh;       __half* shf0h = p_shfh;
    __half* scl1h = p_sclh + 512; __half* shf1h = p_shfh + 512;

    const int EMB_SMEM  = EMB_SMEM_FLOATS  * 4;
    const int ATTN_SMEM = ATTN_SMEM_FLOATS * 4;
    cudaFuncSetAttribute(embed_kernel,
        cudaFuncAttributeMaxDynamicSharedMemorySize, EMB_SMEM);
    cudaFuncSetAttribute(attn_kernel,
        cudaFuncAttributeMaxDynamicSharedMemorySize, ATTN_SMEM);
    cudaFuncSetAttribute(mma_gemm<0, 0, 0, 1, 0>,
        cudaFuncAttributeMaxDynamicSharedMemorySize, GEMM_SMEM);
    cudaFuncSetAttribute(mma_gemm<0, 1, 0, 1, 0>,
        cudaFuncAttributeMaxDynamicSharedMemorySize, GEMM_SMEM);
    cudaFuncSetAttribute(mma_gemm<2, 0, 1, 1, 1>,
        cudaFuncAttributeMaxDynamicSharedMemorySize, GEMM_SMEM);
    cudaFuncSetAttribute(mma_gemm<2, 2, 1, 1, 1>,
        cudaFuncAttributeMaxDynamicSharedMemorySize, GEMM_SMEM);
    cudaFuncSetAttribute(mma_gemm<1, 1, 0, 0, 1>,
        cudaFuncAttributeMaxDynamicSharedMemorySize, GEMM_SMEM);

    // convert weights to half (once per launch; harness graph replays it, cheap)
    f2h_kernel<<<512, 256>>>(wq,  p_wqh, NL * DM * DM);
    f2h_kernel<<<512, 256>>>(wk,  p_wkh, NL * DM * DM);
    f2h_kernel<<<512, 256>>>(wv,  p_wvh, NL * DM * DM);
    f2h_kernel<<<512, 256>>>(wo,  p_woh, NL * DM * DM);
    f2h_kernel<<<512, 256>>>(c1w, p_c1h, NL * DFF * DM);
    f2h_kernel<<<512, 256>>>(c2w, p_c2h, NL * DM * DFF);

    embed_kernel<<<2048, 256, EMB_SMEM>>>(x_enc, tok_w, p_h, p_hh);

    for (int l = 0; l < NL; l++) {
        const int WOFF = l * DM * DM;
        const int FOFF = l * DFF * DM;

        if (l == 0) {
            mma_gemm<0, 0, 0, 1, 0><<<dim3(4, RTILES), 256, GEMM_SMEM>>>(
                p_hh, p_wqh + WOFF, bq + l * DM, nullptr, nullptr, nullptr,
                nullptr, nullptr, p_q, nullptr, DM);
            mma_gemm<0, 0, 0, 1, 0><<<dim3(4, RTILES), 256, GEMM_SMEM>>>(
                p_hh, p_wkh + WOFF, bk + l * DM, nullptr, nullptr, nullptr,
                nullptr, nullptr, p_k, nullptr, DM);
            mma_gemm<0, 0, 0, 1, 0><<<dim3(4, RTILES), 256, GEMM_SMEM>>>(
                p_hh, p_wvh + WOFF, bv + l * DM, nullptr, nullptr, nullptr,
                nullptr, nullptr, p_v, nullptr, DM);
        } else {
            mma_gemm<0, 1, 0, 1, 0><<<dim3(4, RTILES), 256, GEMM_SMEM>>>(
                p_hh, p_wqh + WOFF, bq + l * DM, nullptr, nullptr, nullptr,
                scl1h, shf1h, p_q, nullptr, DM);
            mma_gemm<0, 1, 0, 1, 0><<<dim3(4, RTILES), 256, GEMM_SMEM>>>(
                p_hh, p_wkh + WOFF, bk + l * DM, nullptr, nullptr, nullptr,
                scl1h, shf1h, p_k, nullptr, DM);
            mma_gemm<0, 1, 0, 1, 0><<<dim3(4, RTILES), 256, GEMM_SMEM>>>(
                p_hh, p_wvh + WOFF, bv + l * DM, nullptr, nullptr, nullptr,
                scl1h, shf1h, p_v, nullptr, DM);
        }

        attn_kernel<<<2048 * NH, 256, ATTN_SMEM>>>(p_q, p_k, p_v, p_atth);

        if (l == 0)
            mma_gemm<2, 0, 1, 1, 1><<<dim3(4, RTILES), 256, GEMM_SMEM>>>(
                p_atth, p_woh + WOFF, bo + l * DM, p_h, nullptr, nullptr,
                nullptr, nullptr, p_y, p_yh, DM);
        else
            mma_gemm<2, 2, 1, 1, 1><<<dim3(4, RTILES), 256, GEMM_SMEM>>>(
                p_atth, p_woh + WOFF, bo + l * DM, p_h, scl1, shf1,
                nullptr, nullptr, p_y, p_yh, DM);

        bn_reduce2_kernel<<<512, 256>>>(g1 + l * DM, be1 + l * DM,
                                        scl0, shf0, scl0h, shf0h);

        mma_gemm<1, 1, 0, 0, 1><<<dim3(8, RTILES), 256, GEMM_SMEM>>>(
            p_yh, p_c1h + FOFF, c1b + l * DFF, nullptr, nullptr, nullptr,
            scl0h, shf0h, nullptr, p_th, DM);
        mma_gemm<2, 2, 1, 1, 1><<<dim3(4, RTILES), 256, GEMM_SMEM>>>(
            p_th, p_c2h + FOFF, c2b + l * DM, p_y, scl0, shf0,
            nullptr, nullptr, p_h, p_hh, DFF);

        bn_reduce2_kernel<<<512, 256>>>(g2 + l * DM, be2 + l * DM,
                                        scl1, shf1, scl1h, shf1h);
    }

    bn_norm_kernel<<<4096, 256>>>(p_h, scl1, shf1, out);
}

// round 12
// speedup vs baseline: 1.7590x; 1.2052x over previous
#include <cuda_runtime.h>
#include <cuda_fp16.h>
#include <math.h>
#include <stdint.h>

// ---------------------------------------------------------------------------
// Problem constants
// ---------------------------------------------------------------------------
#define NTOK   81
#define DM     512
#define NH     8
#define EH     64
#define DFF    1024
#define NL     3
#define RT     (2048 * 81)           // 165888 tokens
#define RTILES (RT / 128)            // 1296

// ---------------------------------------------------------------------------
// Scratch (device globals: no cudaMalloc allowed)
// ---------------------------------------------------------------------------
__device__ float  g_h [RT * DM];     // embed out / raw y2 (fp32)
__device__ float  g_y [RT * DM];     // raw y1 (fp32)
__device__ __half g_h_h  [RT * DM];
__device__ __half g_q_h  [RT * DM];
__device__ __half g_k_h  [RT * DM];
__device__ __half g_v_h  [RT * DM];
__device__ __half g_att_h[RT * DM];
__device__ __half g_y_h  [RT * DM];
__device__ __half g_t_h  [RT * DFF];
__device__ __half g_wq_h[NL * DM * DM];
__device__ __half g_wk_h[NL * DM * DM];
__device__ __half g_wv_h[NL * DM * DM];
__device__ __half g_wo_h[NL * DM * DM];
__device__ __half g_c1_h[NL * DFF * DM];
__device__ __half g_c2_h[NL * DM * DFF];
__device__ float  g_psum[RTILES * 512];
__device__ float  g_psq [RTILES * 512];
__device__ float  g_bnscale[2 * 512];
__device__ float  g_bnshift[2 * 512];
__device__ __half g_bnscaleh[2 * 512];
__device__ __half g_bnshifth[2 * 512];

// ---------------------------------------------------------------------------
// PTX helpers
// ---------------------------------------------------------------------------
__device__ __forceinline__ uint32_t smem_u32(const void* p) {
    uint32_t a;
    asm("{ .reg .u64 t; cvta.to.shared.u64 t, %1; cvt.u32.u64 %0, t; }"
        : "=r"(a) : "l"(p));
    return a;
}

__device__ __forceinline__ void cp16(uint32_t dst, const void* src) {
    asm volatile("cp.async.cg.shared.global [%0], [%1], 16;"
                 :: "r"(dst), "l"(src) : "memory");
}
#define CP_COMMIT() asm volatile("cp.async.commit_group;" ::: "memory")

__device__ __forceinline__ void mma_f16(float* c, const uint32_t* a, const uint32_t* b) {
    asm volatile(
        "mma.sync.aligned.m16n8k16.row.col.f32.f16.f16.f32 "
        "{%0,%1,%2,%3}, {%4,%5,%6,%7}, {%8,%9}, {%0,%1,%2,%3};"
        : "+f"(c[0]), "+f"(c[1]), "+f"(c[2]), "+f"(c[3])
        : "r"(a[0]), "r"(a[1]), "r"(a[2]), "r"(a[3]), "r"(b[0]), "r"(b[1]));
}

__device__ __forceinline__ void ldsm_x4(uint32_t* r, uint32_t addr) {
    asm volatile("ldmatrix.sync.aligned.m8n8.x4.shared.b16 {%0,%1,%2,%3}, [%4];"
        : "=r"(r[0]), "=r"(r[1]), "=r"(r[2]), "=r"(r[3]) : "r"(addr));
}

// ---------------------------------------------------------------------------
// FP16 GEMM (R11 config, best measured): CTA 128x128, BK=64, 8 warps (2x4),
// warp tile 64x32, 2 CTAs/SM, 3-stage cp.async.cg, m16n8k16 HMMA.
// EPI: 0=bias, 1=bias+gelu, 2=bias+residual
// AFF: 0=none, 1=half2 affine on A fragments, 2=fp32 affine on residual
// STATS / WF (fp32 out) / WH (half out)
// ---------------------------------------------------------------------------
#define PHB 144                          // bytes per smem row (72 halves)
#define A_HALF_B (128 * PHB)
#define STAGE_B (2 * A_HALF_B)
#define GEMM_SMEM (3 * STAGE_B)          // 110592 B

template <int EPI, int AFF, int STATS, int WF, int WH>
__global__ __launch_bounds__(256, 2)
void mma_gemm(const __half* __restrict__ A, const __half* __restrict__ W,
              const float* __restrict__ bias, const float* __restrict__ res,
              const float* __restrict__ scl, const float* __restrict__ shf,
              const __half* __restrict__ sclh, const __half* __restrict__ shfh,
              float* __restrict__ C, __half* __restrict__ Ch, int K)
{
    extern __shared__ float smf[];
    uint32_t sA = smem_u32(smf);
    uint32_t sB = sA + A_HALF_B;

    int tid  = threadIdx.x;
    int wid  = tid >> 5, lane = tid & 31;
    int wm   = (wid >> 2) * 64;
    int wn   = (wid & 3) * 32;
    int row0 = blockIdx.y * 128, col0 = blockIdx.x * 128;
    int Dout = gridDim.x * 128;
    int qg   = lane >> 2, qt = lane & 3;
    int lg   = lane >> 3, lr = lane & 7;

    uint32_t baseA[4], baseB[2];
    #pragma unroll
    for (int mt = 0; mt < 4; mt++)
        baseA[mt] = sA + (wm + mt * 16 + (lg & 1) * 8 + lr) * PHB + (lg >> 1) * 16;
    #pragma unroll
    for (int p = 0; p < 2; p++)
        baseB[p]  = sB + (wn + (2 * p + (lg & 1)) * 8 + lr) * PHB + (lg >> 1) * 16;

    auto issue = [&](int st, int kb2) {
        uint32_t o = st * STAGE_B;
        #pragma unroll
        for (int i = 0; i < 4; i++) {
            int slot = tid + 256 * i;
            int row = slot >> 3, c16 = slot & 7;
            uint32_t d = o + row * PHB + c16 * 16;
            cp16(sA + d, A + (size_t)(row0 + row) * K + kb2 * 64 + c16 * 8);
            cp16(sB + d, W + (size_t)(col0 + row) * K + kb2 * 64 + c16 * 8);
        }
        CP_COMMIT();
    };

    int NKB = K / 64;
    issue(0, 0);
    if (NKB > 1) issue(1, 1);

    float acc[4][4][4];
    #pragma unroll
    for (int mt = 0; mt < 4; mt++)
        #pragma unroll
        for (int nt = 0; nt < 4; nt++)
            #pragma unroll
            for (int j = 0; j < 4; j++) acc[mt][nt][j] = 0.f;

    int st = 0, nst = 2;
    for (int kb = 0; kb < NKB; kb++) {
        if (kb + 1 < NKB)
            asm volatile("cp.async.wait_group 1;" ::: "memory");
        else
            asm volatile("cp.async.wait_group 0;" ::: "memory");
        __syncthreads();
        if (kb + 2 < NKB) {
            issue(nst, kb + 2);
            if (++nst == 3) nst = 0;
        }

        uint32_t stOff = st * STAGE_B;
        #pragma unroll
        for (int ks = 0; ks < 4; ks++) {
            uint32_t kB = stOff + ks * 32;
            uint32_t af[4][4], bf[4][2];
            #pragma unroll
            for (int mt = 0; mt < 4; mt++)
                ldsm_x4(af[mt], baseA[mt] + kB);
            #pragma unroll
            for (int p = 0; p < 2; p++) {
                uint32_t t[4];
                ldsm_x4(t, baseB[p] + kB);
                bf[2 * p][0]     = t[0]; bf[2 * p][1]     = t[2];
                bf[2 * p + 1][0] = t[1]; bf[2 * p + 1][1] = t[3];
            }
            if (AFF == 1) {
                int kg = kb * 64 + ks * 16 + 2 * qt;
                __half2 s_lo = *(const __half2*)&sclh[kg];
                __half2 h_lo = *(const __half2*)&shfh[kg];
                __half2 s_hi = *(const __half2*)&sclh[kg + 8];
                __half2 h_hi = *(const __half2*)&shfh[kg + 8];
                #pragma unroll
                for (int mt = 0; mt < 4; mt++) {
                    __half2 v0 = *(__half2*)&af[mt][0];
                    __half2 v1 = *(__half2*)&af[mt][1];
                    __half2 v2 = *(__half2*)&af[mt][2];
                    __half2 v3 = *(__half2*)&af[mt][3];
                    v0 = __hfma2(v0, s_lo, h_lo);
                    v1 = __hfma2(v1, s_lo, h_lo);
                    v2 = __hfma2(v2, s_hi, h_hi);
                    v3 = __hfma2(v3, s_hi, h_hi);
                    af[mt][0] = *(uint32_t*)&v0;
                    af[mt][1] = *(uint32_t*)&v1;
                    af[mt][2] = *(uint32_t*)&v2;
                    af[mt][3] = *(uint32_t*)&v3;
                }
            }
            #pragma unroll
            for (int mt = 0; mt < 4; mt++)
                #pragma unroll
                for (int nt = 0; nt < 4; nt++)
                    mma_f16(acc[mt][nt], af[mt], bf[nt]);
        }
        if (++st == 3) st = 0;
    }

    float cs[8], cq[8];
    if (STATS) {
        #pragma unroll
        for (int j = 0; j < 8; j++) { cs[j] = 0.f; cq[j] = 0.f; }
    }

    #pragma unroll
    for (int mt = 0; mt < 4; mt++) {
        #pragma unroll
        for (int nt = 0; nt < 4; nt++) {
            int c  = col0 + wn + nt * 8 + 2 * qt;
            int r0 = row0 + wm + mt * 16 + qg;
            float b0 = bias[c], b1 = bias[c + 1];
            float s0 = 1.f, s1 = 1.f, h0 = 0.f, h1 = 0.f;
            if (AFF == 2) {
                s0 = scl[c]; s1 = scl[c + 1];
                h0 = shf[c]; h1 = shf[c + 1];
            }
            #pragma unroll
            for (int half = 0; half < 2; half++) {
                int r = r0 + half * 8;
                float vx = acc[mt][nt][half * 2 + 0] + b0;
                float vy = acc[mt][nt][half * 2 + 1] + b1;
                if (EPI == 1) {
                    vx = 0.5f * vx * (1.0f + erff(vx * 0.70710678118654752f));
                    vy = 0.5f * vy * (1.0f + erff(vy * 0.70710678118654752f));
                }
                size_t off = (size_t)r * Dout + c;
                if (EPI == 2) {
                    float2 rv = *(const float2*)(res + off);
                    if (AFF == 2) { vx += s0 * rv.x + h0; vy += s1 * rv.y + h1; }
                    else          { vx += rv.x;           vy += rv.y; }
                }
                if (STATS) {
                    cs[nt * 2 + 0] += vx; cq[nt * 2 + 0] += vx * vx;
                    cs[nt * 2 + 1] += vy; cq[nt * 2 + 1] += vy * vy;
                }
                if (WF)
                    *(float2*)(C + off) = make_float2(vx, vy);
                if (WH)
                    *(__half2*)(Ch + off) = __floats2half2_rn(vx, vy);
            }
        }
    }

    if (STATS) {
        #pragma unroll
        for (int j = 0; j < 8; j++) {
            #pragma unroll
            for (int m = 4; m <= 16; m <<= 1) {
                cs[j] += __shfl_xor_sync(0xffffffffu, cs[j], m);
                cq[j] += __shfl_xor_sync(0xffffffffu, cq[j], m);
            }
        }
        __syncthreads();
        float* ssum = smf;
        float* ssq  = smf + 256;
        int wrow = wid >> 2;
        if (lane < 4) {
            #pragma unroll
            for (int nt = 0; nt < 4; nt++) {
                #pragma unroll
                for (int p = 0; p < 2; p++) {
                    int cl = wn + nt * 8 + 2 * qt + p;
                    ssum[wrow * 128 + cl] = cs[nt * 2 + p];
                    ssq [wrow * 128 + cl] = cq[nt * 2 + p];
                }
            }
        }
        __syncthreads();
        if (tid < 128) {
            int slot = blockIdx.y * 512 + col0 + tid;
            g_psum[slot] = ssum[tid] + ssum[128 + tid];
            g_psq [slot] = ssq [tid] + ssq [128 + tid];
        }
    }
}

// ---------------------------------------------------------------------------
// fp32 -> fp16 conversion (weights)
// ---------------------------------------------------------------------------
__global__ void f2h_kernel(const float* __restrict__ src, __half* __restrict__ dst,
                           int n)
{
    for (int i = blockIdx.x * blockDim.x + threadIdx.x; i < n / 2;
         i += gridDim.x * blockDim.x) {
        float2 v = ((const float2*)src)[i];
        ((__half2*)dst)[i] = __floats2half2_rn(v.x, v.y);
    }
}

// ---------------------------------------------------------------------------
// Token embedding (fp32 + half out)
// ---------------------------------------------------------------------------
#define EMB_SMEM_FLOATS (512 * 49 + 336)
__global__ void embed_kernel(const float* __restrict__ x_enc,
                             const float* __restrict__ tok_w,
                             float* __restrict__ h, __half* __restrict__ hh)
{
    extern __shared__ float sm[];
    float* w_sm = sm;
    float* x_sm = sm + 512 * 49;
    int bm = blockIdx.x;
    int b = bm >> 6, m = bm & 63;
    int tid = threadIdx.x;

    for (int i = tid; i < 512 * 48; i += 256) {
        int d = i / 48, u = i - d * 48;
        w_sm[d * 49 + u] = tok_w[i];
    }
    for (int l = tid; l < 336; l += 256)
        x_sm[l] = x_enc[(b * 336 + l) * 64 + m];
    __syncthreads();

    const float CLOG = -9.210340371976184f / 256.0f;
    int d0 = tid, d1 = tid + 256;
    float fr0 = expf((float)(d0 >> 1) * CLOG);
    float fr1 = expf((float)(d1 >> 1) * CLOG);

    for (int n = 0; n < NTOK; n++) {
        float a0 = 0.f, a1 = 0.f;
        #pragma unroll
        for (int t = 0; t < 3; t++) {
            int pp = n - 1 + t;
            pp = (pp < 0) ? (NTOK - 1) : (pp >= NTOK ? 0 : pp);
            const float* xp = x_sm + pp * 4;
            #pragma unroll
            for (int p = 0; p < 16; p++) {
                float xv = xp[p];
                a0 += xv * w_sm[d0 * 49 + p * 3 + t];
                a1 += xv * w_sm[d1 * 49 + p * 3 + t];
            }
        }
        float ang0 = (float)n * fr0, ang1 = (float)n * fr1;
        float pe0 = (d0 & 1) ? cosf(ang0) : sinf(ang0);
        float pe1 = (d1 & 1) ? cosf(ang1) : sinf(ang1);
        size_t base = ((size_t)bm * NTOK + n) * DM;
        float v0 = a0 + pe0, v1 = a1 + pe1;
        h[base + d0] = v0;
        h[base + d1] = v1;
        hh[base + d0] = __float2half(v0);
        hh[base + d1] = __float2half(v1);
    }
}

// ---------------------------------------------------------------------------
// FP16 mma attention per (bm, head), register softmax, 2 CTAs/SM.
// Scores 96x128xK64; AV 96x64xK128. Pads zeroed / predicated.
// ---------------------------------------------------------------------------
#define QKP 72                 // Q/K pitch (halves); 144 B
#define SVP 136                // Sh/Vt pitch (halves); 272 B
#define OFF_KH   (96 * QKP)                 // 6912 halves
#define OFF_VT_H (OFF_KH + 128 * QKP)       // 16128
#define OFF_SH_H (OFF_VT_H + 64 * SVP)      // 24832
#define RED_OFF_B ((OFF_SH_H + 96 * SVP) * 2)  // 75776 bytes
#define AT_SMEM (RED_OFF_B + 96 * 4 * 4)       // 77312 bytes

__global__ __launch_bounds__(256, 2)
void attn_fa_kernel(const __half* __restrict__ q, const __half* __restrict__ k,
                    const __half* __restrict__ v, __half* __restrict__ o)
{
    extern __shared__ __half smh[];
    __half* Qh = smh;
    __half* Kh = smh + OFF_KH;
    __half* Vt = smh + OFF_VT_H;
    __half* Sh = smh + OFF_SH_H;
    float*  red = (float*)((char*)smh + RED_OFF_B);   // [96][4]

    int bmh = blockIdx.x;
    int bm = bmh >> 3, hh = bmh & 7;
    int tid = threadIdx.x;
    int wid = tid >> 5, lane = tid & 31;
    int qg = lane >> 2, qt = lane & 3;
    int lg = lane >> 3, lr = lane & 7;
    size_t base = (size_t)bm * NTOK * DM + hh * EH;

    // zero pads
    const __half HZ = __float2half(0.f);
    for (int i = tid; i < 15 * QKP; i += 256) Qh[81 * QKP + i] = HZ;
    for (int i = tid; i < 47 * QKP; i += 256) Kh[81 * QKP + i] = HZ;
    for (int i = tid; i < 64 * 47; i += 256) {
        int e = i / 47, c = 81 + (i % 47);
        Vt[e * SVP + c] = HZ;
    }

    // loads
    for (int i = tid; i < NTOK * 8; i += 256) {
        int n = i >> 3, e8 = i & 7;
        *(uint4*)&Qh[n * QKP + e8 * 8] = *(const uint4*)(q + base + (size_t)n * DM + e8 * 8);
        *(uint4*)&Kh[n * QKP + e8 * 8] = *(const uint4*)(k + base + (size_t)n * DM + e8 * 8);
    }
    for (int i = tid; i < NTOK * 64; i += 256) {
        int s = i >> 6, e = i & 63;
        Vt[e * SVP + s] = v[base + (size_t)s * DM + e];
    }
    __syncthreads();

    uint32_t qsu = smem_u32(Qh), ksu = smem_u32(Kh);
    uint32_t vtu = smem_u32(Vt), shu = smem_u32(Sh);
    int wm = (wid >> 2) * 48;
    int wnS = (wid & 3) * 32;        // score warp cols
    int widn = wid & 3;

    // ---- scores ----
    float sacc[3][4][4];
    #pragma unroll
    for (int mt = 0; mt < 3; mt++)
        #pragma unroll
        for (int nt = 0; nt < 4; nt++)
            #pragma unroll
            for (int j = 0; j < 4; j++) sacc[mt][nt][j] = 0.f;
    {
        uint32_t baseA[3], baseB[2];
        #pragma unroll
        for (int mt = 0; mt < 3; mt++)
            baseA[mt] = qsu + (wm + mt * 16 + (lg & 1) * 8 + lr) * (QKP * 2) + (lg >> 1) * 16;
        #pragma unroll
        for (int p = 0; p < 2; p++)
            baseB[p]  = ksu + (wnS + (2 * p + (lg & 1)) * 8 + lr) * (QKP * 2) + (lg >> 1) * 16;

        #pragma unroll
        for (int ks = 0; ks < 4; ks++) {
            uint32_t kB = ks * 32;
            uint32_t af[3][4], bf[4][2];
            #pragma unroll
            for (int mt = 0; mt < 3; mt++)
                ldsm_x4(af[mt], baseA[mt] + kB);
            #pragma unroll
            for (int p = 0; p < 2; p++) {
                uint32_t t[4];
                ldsm_x4(t, baseB[p] + kB);
                bf[2 * p][0]     = t[0]; bf[2 * p][1]     = t[2];
                bf[2 * p + 1][0] = t[1]; bf[2 * p + 1][1] = t[3];
            }
            #pragma unroll
            for (int mt = 0; mt < 3; mt++)
                #pragma unroll
                for (int nt = 0; nt < 4; nt++)
                    mma_f16(sacc[mt][nt], af[mt], bf[nt]);
        }
    }

    // ---- register softmax ----
    const float SC = 0.125f;
    float rmax[3][2];
    #pragma unroll
    for (int mt = 0; mt < 3; mt++) { rmax[mt][0] = -1e30f; rmax[mt][1] = -1e30f; }
    #pragma unroll
    for (int mt = 0; mt < 3; mt++)
        #pragma unroll
        for (int nt = 0; nt < 4; nt++)
            #pragma unroll
            for (int j = 0; j < 4; j++) {
                int c = wnS + nt * 8 + 2 * qt + (j & 1);
                if (c <= 80) {
                    float vv = sacc[mt][nt][j] * SC;
                    int hl = j >> 1;
                    rmax[mt][hl] = fmaxf(rmax[mt][hl], vv);
                }
            }
    #pragma unroll
    for (int mt = 0; mt < 3; mt++)
        #pragma unroll
        for (int hl = 0; hl < 2; hl++) {
            rmax[mt][hl] = fmaxf(rmax[mt][hl], __shfl_xor_sync(0xffffffffu, rmax[mt][hl], 1));
            rmax[mt][hl] = fmaxf(rmax[mt][hl], __shfl_xor_sync(0xffffffffu, rmax[mt][hl], 2));
        }
    if (qt == 0) {
        #pragma unroll
        for (int mt = 0; mt < 3; mt++)
            #pragma unroll
            for (int hl = 0; hl < 2; hl++)
                red[(wm + mt * 16 + qg + hl * 8) * 4 + widn] = rmax[mt][hl];
    }
    __syncthreads();
    float fmx[3][2];
    #pragma unroll
    for (int mt = 0; mt < 3; mt++)
        #pragma unroll
        for (int hl = 0; hl < 2; hl++) {
            const float* rr = &red[(wm + mt * 16 + qg + hl * 8) * 4];
            fmx[mt][hl] = fmaxf(fmaxf(rr[0], rr[1]), fmaxf(rr[2], rr[3]));
        }
    __syncthreads();    // max reads done before reusing red for sums

    float rsum[3][2] = {};
    #pragma unroll
    for (int mt = 0; mt < 3; mt++)
        #pragma unroll
        for (int nt = 0; nt < 4; nt++)
            #pragma unroll
            for (int j = 0; j < 4; j++) {
                int c = wnS + nt * 8 + 2 * qt + (j & 1);
                int hl = j >> 1;
                float e = 0.f;
                if (c <= 80)
                    e = __expf(sacc[mt][nt][j] * SC - fmx[mt][hl]);
                sacc[mt][nt][j] = e;          // reuse as P
                rsum[mt][hl] += e;
            }
    #pragma unroll
    for (int mt = 0; mt < 3; mt++)
        #pragma unroll
        for (int hl = 0; hl < 2; hl++) {
            rsum[mt][hl] += __shfl_xor_sync(0xffffffffu, rsum[mt][hl], 1);
            rsum[mt][hl] += __shfl_xor_sync(0xffffffffu, rsum[mt][hl], 2);
        }
    if (qt == 0) {
        #pragma unroll
        for (int mt = 0; mt < 3; mt++)
            #pragma unroll
            for (int hl = 0; hl < 2; hl++)
                red[(wm + mt * 16 + qg + hl * 8) * 4 + widn] = rsum[mt][hl];
    }
    __syncthreads();
    float finv[3][2];
    #pragma unroll
    for (int mt = 0; mt < 3; mt++)
        #pragma unroll
        for (int hl = 0; hl < 2; hl++) {
            const float* rr = &red[(wm + mt * 16 + qg + hl * 8) * 4];
            finv[mt][hl] = 1.0f / (rr[0] + rr[1] + rr[2] + rr[3]);
        }

    // write normalized P (half) to Sh
    #pragma unroll
    for (int mt = 0; mt < 3; mt++)
        #pragma unroll
        for (int nt = 0; nt < 4; nt++)
            #pragma unroll
            for (int hl = 0; hl < 2; hl++) {
                int r = wm + mt * 16 + qg + hl * 8;
                int c = wnS + nt * 8 + 2 * qt;
                *(__half2*)&Sh[r * SVP + c] = __floats2half2_rn(
                    sacc[mt][nt][hl * 2 + 0] * finv[mt][hl],
                    sacc[mt][nt][hl * 2 + 1] * finv[mt][hl]);
            }
    __syncthreads();

    // ---- AV: warp tile 48 x 16, K=128 ----
    {
        int wnV = (wid & 3) * 16;
        uint32_t baseA[3], baseB;
        #pragma unroll
        for (int mt = 0; mt < 3; mt++)
            baseA[mt] = shu + (wm + mt * 16 + (lg & 1) * 8 + lr) * (SVP * 2) + (lg >> 1) * 16;
        baseB = vtu + (wnV + (lg & 1) * 8 + lr) * (SVP * 2) + (lg >> 1) * 16;

        float oacc[3][2][4];
        #pragma unroll
        for (int mt = 0; mt < 3; mt++)
            #pragma unroll
            for (int nt = 0; nt < 2; nt++)
                #pragma unroll
                for (int j = 0; j < 4; j++) oacc[mt][nt][j] = 0.f;

        #pragma unroll
        for (int ks = 0; ks < 8; ks++) {
            uint32_t kB = ks * 32;
            uint32_t af[3][4], bf[2][2];
            #pragma unroll
            for (int mt = 0; mt < 3; mt++)
                ldsm_x4(af[mt], baseA[mt] + kB);
            {
                uint32_t t[4];
                ldsm_x4(t, baseB + kB);
                bf[0][0] = t[0]; bf[0][1] = t[2];
                bf[1][0] = t[1]; bf[1][1] = t[3];
            }
            #pragma unroll
            for (int mt = 0; mt < 3; mt++)
                #pragma unroll
                for (int nt = 0; nt < 2; nt++)
                    mma_f16(oacc[mt][nt], af[mt], bf[nt]);
        }

        #pragma unroll
        for (int mt = 0; mt < 3; mt++)
            #pragma unroll
            for (int nt = 0; nt < 2; nt++) {
                int c  = wnV + nt * 8 + 2 * qt;
                int r0 = wm + mt * 16 + qg;
                #pragma unroll
                for (int hl = 0; hl < 2; hl++) {
                    int r = r0 + hl * 8;
                    if (r < NTOK)
                        *(__half2*)(o + base + (size_t)r * DM + c) = __floats2half2_rn(
                            oacc[mt][nt][hl * 2 + 0], oacc[mt][nt][hl * 2 + 1]);
                }
            }
    }
}

// ---------------------------------------------------------------------------
// BN finalize
// ---------------------------------------------------------------------------
__global__ void bn_reduce2_kernel(const float* __restrict__ gamma,
                                  const float* __restrict__ beta,
                                  float* __restrict__ scl, float* __restrict__ shf,
                                  __half* __restrict__ sclh, __half* __restrict__ shfh)
{
    int c = blockIdx.x;
    int tid = threadIdx.x, wid = tid >> 5, lane = tid & 31;
    float s = 0.f, q = 0.f;
    for (int j = tid; j < RTILES; j += 256) {
        s += g_psum[j * 512 + c];
        q += g_psq [j * 512 + c];
    }
    #pragma unroll
    for (int m = 16; m; m >>= 1) {
        s += __shfl_xor_sync(0xffffffffu, s, m);
        q += __shfl_xor_sync(0xffffffffu, q, m);
    }
    __shared__ float rs[8], rq[8];
    if (lane == 0) { rs[wid] = s; rq[wid] = q; }
    __syncthreads();
    if (tid == 0) {
        float S = 0.f, Q = 0.f;
        #pragma unroll
        for (int w = 0; w < 8; w++) { S += rs[w]; Q += rq[w]; }
        const float invn = 1.0f / (float)RT;
        float mu  = S * invn;
        float var = Q * invn - mu * mu;
        float rinv = rsqrtf(var + 1e-5f);
        float sc = rinv * gamma[c];
        float sh = beta[c] - mu * sc;
        scl[c] = sc;  shf[c] = sh;
        sclh[c] = __float2half(sc);
        shfh[c] = __float2half(sh);
    }
}

__global__ void bn_norm_kernel(const float* __restrict__ y,
                               const float* __restrict__ scl,
                               const float* __restrict__ shf,
                               float* __restrict__ out)
{
    const int total = RT * DM / 4;
    for (int i = blockIdx.x * blockDim.x + threadIdx.x; i < total;
         i += gridDim.x * blockDim.x) {
        float4 vv = ((const float4*)y)[i];
        int c = (i & 127) * 4;
        float4 oo;
        oo.x = vv.x * scl[c + 0] + shf[c + 0];
        oo.y = vv.y * scl[c + 1] + shf[c + 1];
        oo.z = vv.z * scl[c + 2] + shf[c + 2];
        oo.w = vv.w * scl[c + 3] + shf[c + 3];
        ((float4*)out)[i] = oo;
    }
}

// ---------------------------------------------------------------------------
// Orchestration
// ---------------------------------------------------------------------------
extern "C" void kernel_launch(void* const* d_in, const int* in_sizes, int n_in,
                              void* d_out, int out_size)
{
    const float* x_enc = (const float*)d_in[0];
    const float* tok_w = (const float*)d_in[1];
    const float* wq  = (const float*)d_in[2];
    const float* bq  = (const float*)d_in[3];
    const float* wk  = (const float*)d_in[4];
    const float* bk  = (const float*)d_in[5];
    const float* wv  = (const float*)d_in[6];
    const float* bv  = (const float*)d_in[7];
    const float* wo  = (const float*)d_in[8];
    const float* bo  = (const float*)d_in[9];
    const float* c1w = (const float*)d_in[10];
    const float* c1b = (const float*)d_in[11];
    const float* c2w = (const float*)d_in[12];
    const float* c2b = (const float*)d_in[13];
    const float* g1  = (const float*)d_in[14];
    const float* be1 = (const float*)d_in[15];
    const float* g2  = (const float*)d_in[16];
    const float* be2 = (const float*)d_in[17];
    float* out = (float*)d_out;

    float *p_h, *p_y, *p_scl, *p_shf;
    __half *p_hh, *p_qh, *p_kh, *p_vh, *p_atth, *p_yh, *p_th, *p_sclh, *p_shfh;
    __half *p_wqh, *p_wkh, *p_wvh, *p_woh, *p_c1h, *p_c2h;
    cudaGetSymbolAddress((void**)&p_h,   g_h);
    cudaGetSymbolAddress((void**)&p_y,   g_y);
    cudaGetSymbolAddress((void**)&p_hh,   g_h_h);
    cudaGetSymbolAddress((void**)&p_qh,   g_q_h);
    cudaGetSymbolAddress((void**)&p_kh,   g_k_h);
    cudaGetSymbolAddress((void**)&p_vh,   g_v_h);
    cudaGetSymbolAddress((void**)&p_atth, g_att_h);
    cudaGetSymbolAddress((void**)&p_yh,   g_y_h);
    cudaGetSymbolAddress((void**)&p_th,   g_t_h);
    cudaGetSymbolAddress((void**)&p_wqh, g_wq_h);
    cudaGetSymbolAddress((void**)&p_wkh, g_wk_h);
    cudaGetSymbolAddress((void**)&p_wvh, g_wv_h);
    cudaGetSymbolAddress((void**)&p_woh, g_wo_h);
    cudaGetSymbolAddress((void**)&p_c1h, g_c1_h);
    cudaGetSymbolAddress((void**)&p_c2h, g_c2_h);
    cudaGetSymbolAddress((void**)&p_scl, g_bnscale);
    cudaGetSymbolAddress((void**)&p_shf, g_bnshift);
    cudaGetSymbolAddress((void**)&p_sclh, g_bnscaleh);
    cudaGetSymbolAddress((void**)&p_shfh, g_bnshifth);
    float*  scl0  = p_scl;        float*  shf0  = p_shf;
    float*  scl1  = p_scl + 512;  float*  shf1  = p_shf + 512;
    __half* scl0h = p_sclh;       __half* shf0h = p_shfh;
    __half* scl1h = p_sclh + 512; __half* shf1h = p_shfh + 512;

    const int EMB_SMEM = EMB_SMEM_FLOATS * 4;
    cudaFuncSetAttribute(embed_kernel,
        cudaFuncAttributeMaxDynamicSharedMemorySize, EMB_SMEM);
    cudaFuncSetAttribute(attn_fa_kernel,
        cudaFuncAttributeMaxDynamicSharedMemorySize, AT_SMEM);
    cudaFuncSetAttribute(mma_gemm<0, 0, 0, 0, 1>,
        cudaFuncAttributeMaxDynamicSharedMemorySize, GEMM_SMEM);
    cudaFuncSetAttribute(mma_gemm<0, 1, 0, 0, 1>,
        cudaFuncAttributeMaxDynamicSharedMemorySize, GEMM_SMEM);
    cudaFuncSetAttribute(mma_gemm<2, 0, 1, 1, 1>,
        cudaFuncAttributeMaxDynamicSharedMemorySize, GEMM_SMEM);
    cudaFuncSetAttribute(mma_gemm<2, 2, 1, 1, 1>,
        cudaFuncAttributeMaxDynamicSharedMemorySize, GEMM_SMEM);
    cudaFuncSetAttribute(mma_gemm<1, 1, 0, 0, 1>,
        cudaFuncAttributeMaxDynamicSharedMemorySize, GEMM_SMEM);

    f2h_kernel<<<512, 256>>>(wq,  p_wqh, NL * DM * DM);
    f2h_kernel<<<512, 256>>>(wk,  p_wkh, NL * DM * DM);
    f2h_kernel<<<512, 256>>>(wv,  p_wvh, NL * DM * DM);
    f2h_kernel<<<512, 256>>>(wo,  p_woh, NL * DM * DM);
    f2h_kernel<<<512, 256>>>(c1w, p_c1h, NL * DFF * DM);
    f2h_kernel<<<512, 256>>>(c2w, p_c2h, NL * DM * DFF);

    embed_kernel<<<2048, 256, EMB_SMEM>>>(x_enc, tok_w, p_h, p_hh);

    for (int l = 0; l < NL; l++) {
        const int WOFF = l * DM * DM;
        const int FOFF = l * DFF * DM;

        if (l == 0) {
            mma_gemm<0, 0, 0, 0, 1><<<dim3(4, RTILES), 256, GEMM_SMEM>>>(
                p_hh, p_wqh + WOFF, bq + l * DM, nullptr, nullptr, nullptr,
                nullptr, nullptr, nullptr, p_qh, DM);
            mma_gemm<0, 0, 0, 0, 1><<<dim3(4, RTILES), 256, GEMM_SMEM>>>(
                p_hh, p_wkh + WOFF, bk + l * DM, nullptr, nullptr, nullptr,
                nullptr, nullptr, nullptr, p_kh, DM);
            mma_gemm<0, 0, 0, 0, 1><<<dim3(4, RTILES), 256, GEMM_SMEM>>>(
                p_hh, p_wvh + WOFF, bv + l * DM, nullptr, nullptr, nullptr,
                nullptr, nullptr, nullptr, p_vh, DM);
        } else {
            mma_gemm<0, 1, 0, 0, 1><<<dim3(4, RTILES), 256, GEMM_SMEM>>>(
                p_hh, p_wqh + WOFF, bq + l * DM, nullptr, nullptr, nullptr,
                scl1h, shf1h, nullptr, p_qh, DM);
            mma_gemm<0, 1, 0, 0, 1><<<dim3(4, RTILES), 256, GEMM_SMEM>>>(
                p_hh, p_wkh + WOFF, bk + l * DM, nullptr, nullptr, nullptr,
                scl1h, shf1h, nullptr, p_kh, DM);
            mma_gemm<0, 1, 0, 0, 1><<<dim3(4, RTILES), 256, GEMM_SMEM>>>(
                p_hh, p_wvh + WOFF, bv + l * DM, nullptr, nullptr, nullptr,
                scl1h, shf1h, nullptr, p_vh, DM);
        }

        attn_fa_kernel<<<2048 * NH, 256, AT_SMEM>>>(p_qh, p_kh, p_vh, p_atth);

        if (l == 0)
            mma_gemm<2, 0, 1, 1, 1><<<dim3(4, RTILES), 256, GEMM_SMEM>>>(
                p_atth, p_woh + WOFF, bo + l * DM, p_h, nullptr, nullptr,
                nullptr, nullptr, p_y, p_yh, DM);
        else
            mma_gemm<2, 2, 1, 1, 1><<<dim3(4, RTILES), 256, GEMM_SMEM>>>(
                p_atth, p_woh + WOFF, bo + l * DM, p_h, scl1, shf1,
                nullptr, nullptr, p_y, p_yh, DM);

        bn_reduce2_kernel<<<512, 256>>>(g1 + l * DM, be1 + l * DM,
                                        scl0, shf0, scl0h, shf0h);

        mma_gemm<1, 1, 0, 0, 1><<<dim3(8, RTILES), 256, GEMM_SMEM>>>(
            p_yh, p_c1h + FOFF, c1b + l * DFF, nullptr, nullptr, nullptr,
            scl0h, shf0h, nullptr, p_th, DM);
        mma_gemm<2, 2, 1, 1, 1><<<dim3(4, RTILES), 256, GEMM_SMEM>>>(
            p_th, p_c2h + FOFF, c2b + l * DM, p_y, scl0, shf0,
            nullptr, nullptr, p_h, p_hh, DFF);

        bn_reduce2_kernel<<<512, 256>>>(g2 + l * DM, be2 + l * DM,
                                        scl1, shf1, scl1h, shf1h);
    }

    bn_norm_kernel<<<4096, 256>>>(p_h, scl1, shf1, out);
}

// round 14
// speedup vs baseline: 1.7865x; 1.0157x over previous
#include <cuda_runtime.h>
#include <cuda_fp16.h>
#include <math.h>
#include <stdint.h>

// ---------------------------------------------------------------------------
// Problem constants
// ---------------------------------------------------------------------------
#define NTOK   81
#define DM     512
#define NH     8
#define EH     64
#define DFF    1024
#define NL     3
#define RT     (2048 * 81)           // 165888 tokens
#define RTILES (RT / 128)            // 1296

// ---------------------------------------------------------------------------
// Scratch (device globals: no cudaMalloc allowed)
// fp32 residual stream (h, y) + half GEMM operand stream
// ---------------------------------------------------------------------------
__device__ float  g_h [RT * DM];     // embed out / raw y2 (fp32)
__device__ float  g_y [RT * DM];     // raw y1 (fp32)
__device__ __half g_h_h  [RT * DM];
__device__ __half g_q_h  [RT * DM];
__device__ __half g_k_h  [RT * DM];
__device__ __half g_v_h  [RT * DM];
__device__ __half g_att_h[RT * DM];
__device__ __half g_y_h  [RT * DM];
__device__ __half g_t_h  [RT * DFF];
__device__ __half g_wq_h[NL * DM * DM];
__device__ __half g_wk_h[NL * DM * DM];
__device__ __half g_wv_h[NL * DM * DM];
__device__ __half g_wo_h[NL * DM * DM];
__device__ __half g_c1_h[NL * DFF * DM];
__device__ __half g_c2_h[NL * DM * DFF];
__device__ float  g_psum[RTILES * 512];
__device__ float  g_psq [RTILES * 512];
__device__ float  g_bnscale[2 * 512];
__device__ float  g_bnshift[2 * 512];
__device__ __half g_bnscaleh[2 * 512];
__device__ __half g_bnshifth[2 * 512];

// ---------------------------------------------------------------------------
// PTX helpers
// ---------------------------------------------------------------------------
__device__ __forceinline__ uint32_t smem_u32(const void* p) {
    uint32_t a;
    asm("{ .reg .u64 t; cvta.to.shared.u64 t, %1; cvt.u32.u64 %0, t; }"
        : "=r"(a) : "l"(p));
    return a;
}

__device__ __forceinline__ void cp16(uint32_t dst, const void* src) {
    asm volatile("cp.async.cg.shared.global [%0], [%1], 16;"
                 :: "r"(dst), "l"(src) : "memory");
}
#define CP_COMMIT() asm volatile("cp.async.commit_group;" ::: "memory")

__device__ __forceinline__ void mma_f16(float* c, const uint32_t* a, const uint32_t* b) {
    asm volatile(
        "mma.sync.aligned.m16n8k16.row.col.f32.f16.f16.f32 "
        "{%0,%1,%2,%3}, {%4,%5,%6,%7}, {%8,%9}, {%0,%1,%2,%3};"
        : "+f"(c[0]), "+f"(c[1]), "+f"(c[2]), "+f"(c[3])
        : "r"(a[0]), "r"(a[1]), "r"(a[2]), "r"(a[3]), "r"(b[0]), "r"(b[1]));
}

__device__ __forceinline__ void ldsm_x4(uint32_t* r, uint32_t addr) {
    asm volatile("ldmatrix.sync.aligned.m8n8.x4.shared.b16 {%0,%1,%2,%3}, [%4];"
        : "=r"(r[0]), "=r"(r[1]), "=r"(r[2]), "=r"(r[3]) : "r"(addr));
}

// ---------------------------------------------------------------------------
// FP16 GEMM (R11/R12 config): CTA 128x128, BK=64, 8 warps (2x4), warp tile
// 64x32, 2 CTAs/SM, 3-stage cp.async.cg, m16n8k16 HMMA, fp32 accumulate.
// EPI: 0=bias, 1=bias+gelu, 2=bias+residual(fp32)
// AFF: 0=none, 1=half2 affine on A fragments, 2=fp32 affine on fp32 residual
// STATS / WF (fp32 out) / WH (half out)
// ---------------------------------------------------------------------------
#define PHB 144                          // bytes per smem row (72 halves)
#define A_HALF_B (128 * PHB)
#define STAGE_B (2 * A_HALF_B)
#define GEMM_SMEM (3 * STAGE_B)          // 110592 B

template <int EPI, int AFF, int STATS, int WF, int WH>
__global__ __launch_bounds__(256, 2)
void mma_gemm(const __half* __restrict__ A, const __half* __restrict__ W,
              const float* __restrict__ bias, const float* __restrict__ res,
              const float* __restrict__ scl, const float* __restrict__ shf,
              const __half* __restrict__ sclh, const __half* __restrict__ shfh,
              float* __restrict__ C, __half* __restrict__ Ch, int K)
{
    extern __shared__ float smf[];
    uint32_t sA = smem_u32(smf);
    uint32_t sB = sA + A_HALF_B;

    int tid  = threadIdx.x;
    int wid  = tid >> 5, lane = tid & 31;
    int wm   = (wid >> 2) * 64;
    int wn   = (wid & 3) * 32;
    int row0 = blockIdx.y * 128, col0 = blockIdx.x * 128;
    int Dout = gridDim.x * 128;
    int qg   = lane >> 2, qt = lane & 3;
    int lg   = lane >> 3, lr = lane & 7;

    uint32_t baseA[4], baseB[2];
    #pragma unroll
    for (int mt = 0; mt < 4; mt++)
        baseA[mt] = sA + (wm + mt * 16 + (lg & 1) * 8 + lr) * PHB + (lg >> 1) * 16;
    #pragma unroll
    for (int p = 0; p < 2; p++)
        baseB[p]  = sB + (wn + (2 * p + (lg & 1)) * 8 + lr) * PHB + (lg >> 1) * 16;

    auto issue = [&](int st, int kb2) {
        uint32_t o = st * STAGE_B;
        #pragma unroll
        for (int i = 0; i < 4; i++) {
            int slot = tid + 256 * i;
            int row = slot >> 3, c16 = slot & 7;
            uint32_t d = o + row * PHB + c16 * 16;
            cp16(sA + d, A + (size_t)(row0 + row) * K + kb2 * 64 + c16 * 8);
            cp16(sB + d, W + (size_t)(col0 + row) * K + kb2 * 64 + c16 * 8);
        }
        CP_COMMIT();
    };

    int NKB = K / 64;
    issue(0, 0);
    if (NKB > 1) issue(1, 1);

    float acc[4][4][4];
    #pragma unroll
    for (int mt = 0; mt < 4; mt++)
        #pragma unroll
        for (int nt = 0; nt < 4; nt++)
            #pragma unroll
            for (int j = 0; j < 4; j++) acc[mt][nt][j] = 0.f;

    int st = 0, nst = 2;
    for (int kb = 0; kb < NKB; kb++) {
        if (kb + 1 < NKB)
            asm volatile("cp.async.wait_group 1;" ::: "memory");
        else
            asm volatile("cp.async.wait_group 0;" ::: "memory");
        __syncthreads();
        if (kb + 2 < NKB) {
            issue(nst, kb + 2);
            if (++nst == 3) nst = 0;
        }

        uint32_t stOff = st * STAGE_B;
        #pragma unroll
        for (int ks = 0; ks < 4; ks++) {
            uint32_t kB = stOff + ks * 32;
            uint32_t af[4][4], bf[4][2];
            #pragma unroll
            for (int mt = 0; mt < 4; mt++)
                ldsm_x4(af[mt], baseA[mt] + kB);
            #pragma unroll
            for (int p = 0; p < 2; p++) {
                uint32_t t[4];
                ldsm_x4(t, baseB[p] + kB);
                bf[2 * p][0]     = t[0]; bf[2 * p][1]     = t[2];
                bf[2 * p + 1][0] = t[1]; bf[2 * p + 1][1] = t[3];
            }
            if (AFF == 1) {
                int kg = kb * 64 + ks * 16 + 2 * qt;
                __half2 s_lo = *(const __half2*)&sclh[kg];
                __half2 h_lo = *(const __half2*)&shfh[kg];
                __half2 s_hi = *(const __half2*)&sclh[kg + 8];
                __half2 h_hi = *(const __half2*)&shfh[kg + 8];
                #pragma unroll
                for (int mt = 0; mt < 4; mt++) {
                    __half2 v0 = *(__half2*)&af[mt][0];
                    __half2 v1 = *(__half2*)&af[mt][1];
                    __half2 v2 = *(__half2*)&af[mt][2];
                    __half2 v3 = *(__half2*)&af[mt][3];
                    v0 = __hfma2(v0, s_lo, h_lo);
                    v1 = __hfma2(v1, s_lo, h_lo);
                    v2 = __hfma2(v2, s_hi, h_hi);
                    v3 = __hfma2(v3, s_hi, h_hi);
                    af[mt][0] = *(uint32_t*)&v0;
                    af[mt][1] = *(uint32_t*)&v1;
                    af[mt][2] = *(uint32_t*)&v2;
                    af[mt][3] = *(uint32_t*)&v3;
                }
            }
            #pragma unroll
            for (int mt = 0; mt < 4; mt++)
                #pragma unroll
                for (int nt = 0; nt < 4; nt++)
                    mma_f16(acc[mt][nt], af[mt], bf[nt]);
        }
        if (++st == 3) st = 0;
    }

    float cs[8], cq[8];
    if (STATS) {
        #pragma unroll
        for (int j = 0; j < 8; j++) { cs[j] = 0.f; cq[j] = 0.f; }
    }

    #pragma unroll
    for (int mt = 0; mt < 4; mt++) {
        #pragma unroll
        for (int nt = 0; nt < 4; nt++) {
            int c  = col0 + wn + nt * 8 + 2 * qt;
            int r0 = row0 + wm + mt * 16 + qg;
            float b0 = bias[c], b1 = bias[c + 1];
            float s0 = 1.f, s1 = 1.f, h0 = 0.f, h1 = 0.f;
            if (AFF == 2) {
                s0 = scl[c]; s1 = scl[c + 1];
                h0 = shf[c]; h1 = shf[c + 1];
            }
            #pragma unroll
            for (int half = 0; half < 2; half++) {
                int r = r0 + half * 8;
                float vx = acc[mt][nt][half * 2 + 0] + b0;
                float vy = acc[mt][nt][half * 2 + 1] + b1;
                if (EPI == 1) {
                    vx = 0.5f * vx * (1.0f + erff(vx * 0.70710678118654752f));
                    vy = 0.5f * vy * (1.0f + erff(vy * 0.70710678118654752f));
                }
                size_t off = (size_t)r * Dout + c;
                if (EPI == 2) {
                    float2 rv = *(const float2*)(res + off);
                    if (AFF == 2) { vx += s0 * rv.x + h0; vy += s1 * rv.y + h1; }
                    else          { vx += rv.x;           vy += rv.y; }
                }
                if (STATS) {
                    cs[nt * 2 + 0] += vx; cq[nt * 2 + 0] += vx * vx;
                    cs[nt * 2 + 1] += vy; cq[nt * 2 + 1] += vy * vy;
                }
                if (WF)
                    *(float2*)(C + off) = make_float2(vx, vy);
                if (WH)
                    *(__half2*)(Ch + off) = __floats2half2_rn(vx, vy);
            }
        }
    }

    if (STATS) {
        #pragma unroll
        for (int j = 0; j < 8; j++) {
            #pragma unroll
            for (int m = 4; m <= 16; m <<= 1) {
                cs[j] += __shfl_xor_sync(0xffffffffu, cs[j], m);
                cq[j] += __shfl_xor_sync(0xffffffffu, cq[j], m);
            }
        }
        __syncthreads();
        float* ssum = smf;
        float* ssq  = smf + 256;
        int wrow = wid >> 2;
        if (lane < 4) {
            #pragma unroll
            for (int nt = 0; nt < 4; nt++) {
                #pragma unroll
                for (int p = 0; p < 2; p++) {
                    int cl = wn + nt * 8 + 2 * qt + p;
                    ssum[wrow * 128 + cl] = cs[nt * 2 + p];
                    ssq [wrow * 128 + cl] = cq[nt * 2 + p];
                }
            }
        }
        __syncthreads();
        if (tid < 128) {
            int slot = blockIdx.y * 512 + col0 + tid;
            g_psum[slot] = ssum[tid] + ssum[128 + tid];
            g_psq [slot] = ssq [tid] + ssq [128 + tid];
        }
    }
}

// ---------------------------------------------------------------------------
// fp32 -> fp16 conversion (weights)
// ---------------------------------------------------------------------------
__global__ void f2h_kernel(const float* __restrict__ src, __half* __restrict__ dst,
                           int n)
{
    for (int i = blockIdx.x * blockDim.x + threadIdx.x; i < n / 2;
         i += gridDim.x * blockDim.x) {
        float2 v = ((const float2*)src)[i];
        ((__half2*)dst)[i] = __floats2half2_rn(v.x, v.y);
    }
}

// ---------------------------------------------------------------------------
// Token embedding: circular Conv1d(P->D,k=3) + sinusoidal PE via fp32 rotation
// recurrence (drift ~81*eps, negligible). fp32 + half outputs.
// ---------------------------------------------------------------------------
#define EMB_SMEM_FLOATS (512 * 49 + 336)
__global__ void embed_kernel(const float* __restrict__ x_enc,
                             const float* __restrict__ tok_w,
                             float* __restrict__ h, __half* __restrict__ hh)
{
    extern __shared__ float sm[];
    float* w_sm = sm;
    float* x_sm = sm + 512 * 49;
    int bm = blockIdx.x;
    int b = bm >> 6, m = bm & 63;
    int tid = threadIdx.x;

    for (int i = tid; i < 512 * 48; i += 256) {
        int d = i / 48, u = i - d * 48;
        w_sm[d * 49 + u] = tok_w[i];
    }
    for (int l = tid; l < 336; l += 256)
        x_sm[l] = x_enc[(b * 336 + l) * 64 + m];
    __syncthreads();

    const float CLOG = -9.210340371976184f / 256.0f;
    int d0 = tid, d1 = tid + 256;
    float fr0 = expf((float)(d0 >> 1) * CLOG);
    float fr1 = expf((float)(d1 >> 1) * CLOG);
    float sf0 = sinf(fr0), cf0 = cosf(fr0);
    float sf1 = sinf(fr1), cf1 = cosf(fr1);
    float s0 = 0.f, c0 = 1.f, s1 = 0.f, c1v = 1.f;

    for (int n = 0; n < NTOK; n++) {
        float a0 = 0.f, a1 = 0.f;
        #pragma unroll
        for (int t = 0; t < 3; t++) {
            int pp = n - 1 + t;
            pp = (pp < 0) ? (NTOK - 1) : (pp >= NTOK ? 0 : pp);
            const float* xp = x_sm + pp * 4;
            #pragma unroll
            for (int p = 0; p < 16; p++) {
                float xv = xp[p];
                a0 += xv * w_sm[d0 * 49 + p * 3 + t];
                a1 += xv * w_sm[d1 * 49 + p * 3 + t];
            }
        }
        float pe0 = (d0 & 1) ? c0  : s0;
        float pe1 = (d1 & 1) ? c1v : s1;
        size_t base = ((size_t)bm * NTOK + n) * DM;
        float v0 = a0 + pe0, v1 = a1 + pe1;
        h[base + d0] = v0;
        h[base + d1] = v1;
        hh[base + d0] = __float2half(v0);
        hh[base + d1] = __float2half(v1);
        float ns0 = s0 * cf0 + c0 * sf0;
        float nc0 = c0 * cf0 - s0 * sf0;
        s0 = ns0; c0 = nc0;
        float ns1 = s1 * cf1 + c1v * sf1;
        float nc1 = c1v * cf1 - s1 * sf1;
        s1 = ns1; c1v = nc1;
    }
}

// ---------------------------------------------------------------------------
// FP16 mma attention per (bm, head), register softmax, 2 CTAs/SM. (R12)
// ---------------------------------------------------------------------------
#define QKP 72
#define SVP 136
#define OFF_KH   (96 * QKP)
#define OFF_VT_H (OFF_KH + 128 * QKP)
#define OFF_SH_H (OFF_VT_H + 64 * SVP)
#define RED_OFF_B ((OFF_SH_H + 96 * SVP) * 2)
#define AT_SMEM (RED_OFF_B + 96 * 4 * 4)

__global__ __launch_bounds__(256, 2)
void attn_fa_kernel(const __half* __restrict__ q, const __half* __restrict__ k,
                    const __half* __restrict__ v, __half* __restrict__ o)
{
    extern __shared__ __half smh[];
    __half* Qh = smh;
    __half* Kh = smh + OFF_KH;
    __half* Vt = smh + OFF_VT_H;
    __half* Sh = smh + OFF_SH_H;
    float*  red = (float*)((char*)smh + RED_OFF_B);

    int bmh = blockIdx.x;
    int bm = bmh >> 3, hh = bmh & 7;
    int tid = threadIdx.x;
    int wid = tid >> 5, lane = tid & 31;
    int qg = lane >> 2, qt = lane & 3;
    int lg = lane >> 3, lr = lane & 7;
    size_t base = (size_t)bm * NTOK * DM + hh * EH;

    const __half HZ = __float2half(0.f);
    for (int i = tid; i < 15 * QKP; i += 256) Qh[81 * QKP + i] = HZ;
    for (int i = tid; i < 47 * QKP; i += 256) Kh[81 * QKP + i] = HZ;
    for (int i = tid; i < 64 * 47; i += 256) {
        int e = i / 47, c = 81 + (i % 47);
        Vt[e * SVP + c] = HZ;
    }

    for (int i = tid; i < NTOK * 8; i += 256) {
        int n = i >> 3, e8 = i & 7;
        *(uint4*)&Qh[n * QKP + e8 * 8] = *(const uint4*)(q + base + (size_t)n * DM + e8 * 8);
        *(uint4*)&Kh[n * QKP + e8 * 8] = *(const uint4*)(k + base + (size_t)n * DM + e8 * 8);
    }
    for (int i = tid; i < NTOK * 64; i += 256) {
        int s = i >> 6, e = i & 63;
        Vt[e * SVP + s] = v[base + (size_t)s * DM + e];
    }
    __syncthreads();

    uint32_t qsu = smem_u32(Qh), ksu = smem_u32(Kh);
    uint32_t vtu = smem_u32(Vt), shu = smem_u32(Sh);
    int wm = (wid >> 2) * 48;
    int wnS = (wid & 3) * 32;
    int widn = wid & 3;

    float sacc[3][4][4];
    #pragma unroll
    for (int mt = 0; mt < 3; mt++)
        #pragma unroll
        for (int nt = 0; nt < 4; nt++)
            #pragma unroll
            for (int j = 0; j < 4; j++) sacc[mt][nt][j] = 0.f;
    {
        uint32_t baseA[3], baseB[2];
        #pragma unroll
        for (int mt = 0; mt < 3; mt++)
            baseA[mt] = qsu + (wm + mt * 16 + (lg & 1) * 8 + lr) * (QKP * 2) + (lg >> 1) * 16;
        #pragma unroll
        for (int p = 0; p < 2; p++)
            baseB[p]  = ksu + (wnS + (2 * p + (lg & 1)) * 8 + lr) * (QKP * 2) + (lg >> 1) * 16;

        #pragma unroll
        for (int ks = 0; ks < 4; ks++) {
            uint32_t kB = ks * 32;
            uint32_t af[3][4], bf[4][2];
            #pragma unroll
            for (int mt = 0; mt < 3; mt++)
                ldsm_x4(af[mt], baseA[mt] + kB);
            #pragma unroll
            for (int p = 0; p < 2; p++) {
                uint32_t t[4];
                ldsm_x4(t, baseB[p] + kB);
                bf[2 * p][0]     = t[0]; bf[2 * p][1]     = t[2];
                bf[2 * p + 1][0] = t[1]; bf[2 * p + 1][1] = t[3];
            }
            #pragma unroll
            for (int mt = 0; mt < 3; mt++)
                #pragma unroll
                for (int nt = 0; nt < 4; nt++)
                    mma_f16(sacc[mt][nt], af[mt], bf[nt]);
        }
    }

    const float SC = 0.125f;
    float rmax[3][2];
    #pragma unroll
    for (int mt = 0; mt < 3; mt++) { rmax[mt][0] = -1e30f; rmax[mt][1] = -1e30f; }
    #pragma unroll
    for (int mt = 0; mt < 3; mt++)
        #pragma unroll
        for (int nt = 0; nt < 4; nt++)
            #pragma unroll
            for (int j = 0; j < 4; j++) {
                int c = wnS + nt * 8 + 2 * qt + (j & 1);
                if (c <= 80) {
                    float vv = sacc[mt][nt][j] * SC;
                    int hl = j >> 1;
                    rmax[mt][hl] = fmaxf(rmax[mt][hl], vv);
                }
            }
    #pragma unroll
    for (int mt = 0; mt < 3; mt++)
        #pragma unroll
        for (int hl = 0; hl < 2; hl++) {
            rmax[mt][hl] = fmaxf(rmax[mt][hl], __shfl_xor_sync(0xffffffffu, rmax[mt][hl], 1));
            rmax[mt][hl] = fmaxf(rmax[mt][hl], __shfl_xor_sync(0xffffffffu, rmax[mt][hl], 2));
        }
    if (qt == 0) {
        #pragma unroll
        for (int mt = 0; mt < 3; mt++)
            #pragma unroll
            for (int hl = 0; hl < 2; hl++)
                red[(wm + mt * 16 + qg + hl * 8) * 4 + widn] = rmax[mt][hl];
    }
    __syncthreads();
    float fmx[3][2];
    #pragma unroll
    for (int mt = 0; mt < 3; mt++)
        #pragma unroll
        for (int hl = 0; hl < 2; hl++) {
            const float* rr = &red[(wm + mt * 16 + qg + hl * 8) * 4];
            fmx[mt][hl] = fmaxf(fmaxf(rr[0], rr[1]), fmaxf(rr[2], rr[3]));
        }
    __syncthreads();

    float rsum[3][2] = {};
    #pragma unroll
    for (int mt = 0; mt < 3; mt++)
        #pragma unroll
        for (int nt = 0; nt < 4; nt++)
            #pragma unroll
            for (int j = 0; j < 4; j++) {
                int c = wnS + nt * 8 + 2 * qt + (j & 1);
                int hl = j >> 1;
                float e = 0.f;
                if (c <= 80)
                    e = __expf(sacc[mt][nt][j] * SC - fmx[mt][hl]);
                sacc[mt][nt][j] = e;
                rsum[mt][hl] += e;
            }
    #pragma unroll
    for (int mt = 0; mt < 3; mt++)
        #pragma unroll
        for (int hl = 0; hl < 2; hl++) {
            rsum[mt][hl] += __shfl_xor_sync(0xffffffffu, rsum[mt][hl], 1);
            rsum[mt][hl] += __shfl_xor_sync(0xffffffffu, rsum[mt][hl], 2);
        }
    if (qt == 0) {
        #pragma unroll
        for (int mt = 0; mt < 3; mt++)
            #pragma unroll
            for (int hl = 0; hl < 2; hl++)
                red[(wm + mt * 16 + qg + hl * 8) * 4 + widn] = rsum[mt][hl];
    }
    __syncthreads();
    float finv[3][2];
    #pragma unroll
    for (int mt = 0; mt < 3; mt++)
        #pragma unroll
        for (int hl = 0; hl < 2; hl++) {
            const float* rr = &red[(wm + mt * 16 + qg + hl * 8) * 4];
            finv[mt][hl] = 1.0f / (rr[0] + rr[1] + rr[2] + rr[3]);
        }

    #pragma unroll
    for (int mt = 0; mt < 3; mt++)
        #pragma unroll
        for (int nt = 0; nt < 4; nt++)
            #pragma unroll
            for (int hl = 0; hl < 2; hl++) {
                int r = wm + mt * 16 + qg + hl * 8;
                int c = wnS + nt * 8 + 2 * qt;
                *(__half2*)&Sh[r * SVP + c] = __floats2half2_rn(
                    sacc[mt][nt][hl * 2 + 0] * finv[mt][hl],
                    sacc[mt][nt][hl * 2 + 1] * finv[mt][hl]);
            }
    __syncthreads();

    {
        int wnV = (wid & 3) * 16;
        uint32_t baseA[3], baseB;
        #pragma unroll
        for (int mt = 0; mt < 3; mt++)
            baseA[mt] = shu + (wm + mt * 16 + (lg & 1) * 8 + lr) * (SVP * 2) + (lg >> 1) * 16;
        baseB = vtu + (wnV + (lg & 1) * 8 + lr) * (SVP * 2) + (lg >> 1) * 16;

        float oacc[3][2][4];
        #pragma unroll
        for (int mt = 0; mt < 3; mt++)
            #pragma unroll
            for (int nt = 0; nt < 2; nt++)
                #pragma unroll
                for (int j = 0; j < 4; j++) oacc[mt][nt][j] = 0.f;

        #pragma unroll
        for (int ks = 0; ks < 8; ks++) {
            uint32_t kB = ks * 32;
            uint32_t af[3][4], bf[2][2];
            #pragma unroll
            for (int mt = 0; mt < 3; mt++)
                ldsm_x4(af[mt], baseA[mt] + kB);
            {
                uint32_t t[4];
                ldsm_x4(t, baseB + kB);
                bf[0][0] = t[0]; bf[0][1] = t[2];
                bf[1][0] = t[1]; bf[1][1] = t[3];
            }
            #pragma unroll
            for (int mt = 0; mt < 3; mt++)
                #pragma unroll
                for (int nt = 0; nt < 2; nt++)
                    mma_f16(oacc[mt][nt], af[mt], bf[nt]);
        }

        #pragma unroll
        for (int mt = 0; mt < 3; mt++)
            #pragma unroll
            for (int nt = 0; nt < 2; nt++) {
                int c  = wnV + nt * 8 + 2 * qt;
                int r0 = wm + mt * 16 + qg;
                #pragma unroll
                for (int hl = 0; hl < 2; hl++) {
                    int r = r0 + hl * 8;
                    if (r < NTOK)
                        *(__half2*)(o + base + (size_t)r * DM + c) = __floats2half2_rn(
                            oacc[mt][nt][hl * 2 + 0], oacc[mt][nt][hl * 2 + 1]);
                }
            }
    }
}

// ---------------------------------------------------------------------------
// BN finalize
// ---------------------------------------------------------------------------
__global__ void bn_reduce2_kernel(const float* __restrict__ gamma,
                                  const float* __restrict__ beta,
                                  float* __restrict__ scl, float* __restrict__ shf,
                                  __half* __restrict__ sclh, __half* __restrict__ shfh)
{
    int c = blockIdx.x;
    int tid = threadIdx.x, wid = tid >> 5, lane = tid & 31;
    float s = 0.f, q = 0.f;
    for (int j = tid; j < RTILES; j += 256) {
        s += g_psum[j * 512 + c];
        q += g_psq [j * 512 + c];
    }
    #pragma unroll
    for (int m = 16; m; m >>= 1) {
        s += __shfl_xor_sync(0xffffffffu, s, m);
        q += __shfl_xor_sync(0xffffffffu, q, m);
    }
    __shared__ float rs[8], rq[8];
    if (lane == 0) { rs[wid] = s; rq[wid] = q; }
    __syncthreads();
    if (tid == 0) {
        float S = 0.f, Q = 0.f;
        #pragma unroll
        for (int w = 0; w < 8; w++) { S += rs[w]; Q += rq[w]; }
        const float invn = 1.0f / (float)RT;
        float mu  = S * invn;
        float var = Q * invn - mu * mu;
        float rinv = rsqrtf(var + 1e-5f);
        float sc = rinv * gamma[c];
        float sh = beta[c] - mu * sc;
        scl[c] = sc;  shf[c] = sh;
        sclh[c] = __float2half(sc);
        shfh[c] = __float2half(sh);
    }
}

__global__ void bn_norm_kernel(const float* __restrict__ y,
                               const float* __restrict__ scl,
                               const float* __restrict__ shf,
                               float* __restrict__ out)
{
    const int total = RT * DM / 4;
    for (int i = blockIdx.x * blockDim.x + threadIdx.x; i < total;
         i += gridDim.x * blockDim.x) {
        float4 vv = ((const float4*)y)[i];
        int c = (i & 127) * 4;
        float4 oo;
        oo.x = vv.x * scl[c + 0] + shf[c + 0];
        oo.y = vv.y * scl[c + 1] + shf[c + 1];
        oo.z = vv.z * scl[c + 2] + shf[c + 2];
        oo.w = vv.w * scl[c + 3] + shf[c + 3];
        ((float4*)out)[i] = oo;
    }
}

// ---------------------------------------------------------------------------
// Orchestration
// ---------------------------------------------------------------------------
extern "C" void kernel_launch(void* const* d_in, const int* in_sizes, int n_in,
                              void* d_out, int out_size)
{
    const float* x_enc = (const float*)d_in[0];
    const float* tok_w = (const float*)d_in[1];
    const float* wq  = (const float*)d_in[2];
    const float* bq  = (const float*)d_in[3];
    const float* wk  = (const float*)d_in[4];
    const float* bk  = (const float*)d_in[5];
    const float* wv  = (const float*)d_in[6];
    const float* bv  = (const float*)d_in[7];
    const float* wo  = (const float*)d_in[8];
    const float* bo  = (const float*)d_in[9];
    const float* c1w = (const float*)d_in[10];
    const float* c1b = (const float*)d_in[11];
    const float* c2w = (const float*)d_in[12];
    const float* c2b = (const float*)d_in[13];
    const float* g1  = (const float*)d_in[14];
    const float* be1 = (const float*)d_in[15];
    const float* g2  = (const float*)d_in[16];
    const float* be2 = (const float*)d_in[17];
    float* out = (float*)d_out;

    float *p_h, *p_y, *p_scl, *p_shf;
    __half *p_hh, *p_qh, *p_kh, *p_vh, *p_atth, *p_yh, *p_th, *p_sclh, *p_shfh;
    __half *p_wqh, *p_wkh, *p_wvh, *p_woh, *p_c1h, *p_c2h;
    cudaGetSymbolAddress((void**)&p_h,   g_h);
    cudaGetSymbolAddress((void**)&p_y,   g_y);
    cudaGetSymbolAddress((void**)&p_hh,   g_h_h);
    cudaGetSymbolAddress((void**)&p_qh,   g_q_h);
    cudaGetSymbolAddress((void**)&p_kh,   g_k_h);
    cudaGetSymbolAddress((void**)&p_vh,   g_v_h);
    cudaGetSymbolAddress((void**)&p_atth, g_att_h);
    cudaGetSymbolAddress((void**)&p_yh,   g_y_h);
    cudaGetSymbolAddress((void**)&p_th,   g_t_h);
    cudaGetSymbolAddress((void**)&p_wqh, g_wq_h);
    cudaGetSymbolAddress((void**)&p_wkh, g_wk_h);
    cudaGetSymbolAddress((void**)&p_wvh, g_wv_h);
    cudaGetSymbolAddress((void**)&p_woh, g_wo_h);
    cudaGetSymbolAddress((void**)&p_c1h, g_c1_h);
    cudaGetSymbolAddress((void**)&p_c2h, g_c2_h);
    cudaGetSymbolAddress((void**)&p_scl, g_bnscale);
    cudaGetSymbolAddress((void**)&p_shf, g_bnshift);
    cudaGetSymbolAddress((void**)&p_sclh, g_bnscaleh);
    cudaGetSymbolAddress((void**)&p_shfh, g_bnshifth);
    float*  scl0  = p_scl;        float*  shf0  = p_shf;
    float*  scl1  = p_scl + 512;  float*  shf1  = p_shf + 512;
    __half* scl0h = p_sclh;       __half* shf0h = p_shfh;
    __half* scl1h = p_sclh + 512; __half* shf1h = p_shfh + 512;

    const int EMB_SMEM = EMB_SMEM_FLOATS * 4;
    cudaFuncSetAttribute(embed_kernel,
        cudaFuncAttributeMaxDynamicSharedMemorySize, EMB_SMEM);
    cudaFuncSetAttribute(attn_fa_kernel,
        cudaFuncAttributeMaxDynamicSharedMemorySize, AT_SMEM);
    cudaFuncSetAttribute(mma_gemm<0, 0, 0, 0, 1>,
        cudaFuncAttributeMaxDynamicSharedMemorySize, GEMM_SMEM);
    cudaFuncSetAttribute(mma_gemm<0, 1, 0, 0, 1>,
        cudaFuncAttributeMaxDynamicSharedMemorySize, GEMM_SMEM);
    cudaFuncSetAttribute(mma_gemm<2, 0, 1, 1, 1>,
        cudaFuncAttributeMaxDynamicSharedMemorySize, GEMM_SMEM);
    cudaFuncSetAttribute(mma_gemm<2, 2, 1, 1, 1>,
        cudaFuncAttributeMaxDynamicSharedMemorySize, GEMM_SMEM);
    cudaFuncSetAttribute(mma_gemm<1, 1, 0, 0, 1>,
        cudaFuncAttributeMaxDynamicSharedMemorySize, GEMM_SMEM);

    f2h_kernel<<<512, 256>>>(wq,  p_wqh, NL * DM * DM);
    f2h_kernel<<<512, 256>>>(wk,  p_wkh, NL * DM * DM);
    f2h_kernel<<<512, 256>>>(wv,  p_wvh, NL * DM * DM);
    f2h_kernel<<<512, 256>>>(wo,  p_woh, NL * DM * DM);
    f2h_kernel<<<512, 256>>>(c1w, p_c1h, NL * DFF * DM);
    f2h_kernel<<<512, 256>>>(c2w, p_c2h, NL * DM * DFF);

    embed_kernel<<<2048, 256, EMB_SMEM>>>(x_enc, tok_w, p_h, p_hh);

    for (int l = 0; l < NL; l++) {
        const int WOFF = l * DM * DM;
        const int FOFF = l * DFF * DM;

        if (l == 0) {
            mma_gemm<0, 0, 0, 0, 1><<<dim3(4, RTILES), 256, GEMM_SMEM>>>(
                p_hh, p_wqh + WOFF, bq + l * DM, nullptr, nullptr, nullptr,
                nullptr, nullptr, nullptr, p_qh, DM);
            mma_gemm<0, 0, 0, 0, 1><<<dim3(4, RTILES), 256, GEMM_SMEM>>>(
                p_hh, p_wkh + WOFF, bk + l * DM, nullptr, nullptr, nullptr,
                nullptr, nullptr, nullptr, p_kh, DM);
            mma_gemm<0, 0, 0, 0, 1><<<dim3(4, RTILES), 256, GEMM_SMEM>>>(
                p_hh, p_wvh + WOFF, bv + l * DM, nullptr, nullptr, nullptr,
                nullptr, nullptr, nullptr, p_vh, DM);
        } else {
            mma_gemm<0, 1, 0, 0, 1><<<dim3(4, RTILES), 256, GEMM_SMEM>>>(
                p_hh, p_wqh + WOFF, bq + l * DM, nullptr, nullptr, nullptr,
                scl1h, shf1h, nullptr, p_qh, DM);
            mma_gemm<0, 1, 0, 0, 1><<<dim3(4, RTILES), 256, GEMM_SMEM>>>(
                p_hh, p_wkh + WOFF, bk + l * DM, nullptr, nullptr, nullptr,
                scl1h, shf1h, nullptr, p_kh, DM);
            mma_gemm<0, 1, 0, 0, 1><<<dim3(4, RTILES), 256, GEMM_SMEM>>>(
                p_hh, p_wvh + WOFF, bv + l * DM, nullptr, nullptr, nullptr,
                scl1h, shf1h, nullptr, p_vh, DM);
        }

        attn_fa_kernel<<<2048 * NH, 256, AT_SMEM>>>(p_qh, p_kh, p_vh, p_atth);

        if (l == 0)
            mma_gemm<2, 0, 1, 1, 1><<<dim3(4, RTILES), 256, GEMM_SMEM>>>(
                p_atth, p_woh + WOFF, bo + l * DM, p_h, nullptr, nullptr,
                nullptr, nullptr, p_y, p_yh, DM);
        else
            mma_gemm<2, 2, 1, 1, 1><<<dim3(4, RTILES), 256, GEMM_SMEM>>>(
                p_atth, p_woh + WOFF, bo + l * DM, p_h, scl1, shf1,
                nullptr, nullptr, p_y, p_yh, DM);

        bn_reduce2_kernel<<<512, 256>>>(g1 + l * DM, be1 + l * DM,
                                        scl0, shf0, scl0h, shf0h);

        mma_gemm<1, 1, 0, 0, 1><<<dim3(8, RTILES), 256, GEMM_SMEM>>>(
            p_yh, p_c1h + FOFF, c1b + l * DFF, nullptr, nullptr, nullptr,
            scl0h, shf0h, nullptr, p_th, DM);
        mma_gemm<2, 2, 1, 1, 1><<<dim3(4, RTILES), 256, GEMM_SMEM>>>(
            p_th, p_c2h + FOFF, c2b + l * DM, p_y, scl0, shf0,
            nullptr, nullptr, p_h, p_hh, DFF);

        bn_reduce2_kernel<<<512, 256>>>(g2 + l * DM, be2 + l * DM,
                                        scl1, shf1, scl1h, shf1h);
    }

    bn_norm_kernel<<<4096, 256>>>(p_h, scl1, shf1, out);
}

// round 15
// speedup vs baseline: 1.8208x; 1.0192x over previous
#include <cuda_runtime.h>
#include <cuda_fp16.h>
#include <math.h>
#include <stdint.h>

// ---------------------------------------------------------------------------
// Problem constants
// ---------------------------------------------------------------------------
#define NTOK   81
#define DM     512
#define NH     8
#define EH     64
#define DFF    1024
#define NL     3
#define RT     (2048 * 81)           // 165888 tokens
#define RTILES (RT / 128)            // 1296

// ---------------------------------------------------------------------------
// Scratch (device globals)
// ---------------------------------------------------------------------------
__device__ float  g_h [RT * DM];     // fp32 residual: embed out / raw y2
__device__ float  g_y [RT * DM];     // fp32 residual: raw y1
__device__ __half g_h_h  [RT * DM];
__device__ __half g_q_h  [RT * DM];
__device__ __half g_k_h  [RT * DM];
__device__ __half g_v_h  [RT * DM];
__device__ __half g_att_h[RT * DM];
__device__ __half g_y_h  [RT * DM];
__device__ __half g_t_h  [RT * DFF];
__device__ __half g_wqkv_h[NL * 3 * DM * DM];   // concat [q|k|v]
__device__ float  g_bqkv  [NL * 3 * DM];
__device__ __half g_wo_h[NL * DM * DM];
__device__ __half g_c1_h[NL * DFF * DM];
__device__ __half g_c2_h[NL * DM * DFF];
__device__ float  g_psum[RTILES * 512];
__device__ float  g_psq [RTILES * 512];
__device__ float  g_bnscale[2 * 512];
__device__ float  g_bnshift[2 * 512];
__device__ __half g_bnscaleh[2 * 512];
__device__ __half g_bnshifth[2 * 512];

// ---------------------------------------------------------------------------
// PTX helpers
// ---------------------------------------------------------------------------
__device__ __forceinline__ uint32_t smem_u32(const void* p) {
    uint32_t a;
    asm("{ .reg .u64 t; cvta.to.shared.u64 t, %1; cvt.u32.u64 %0, t; }"
        : "=r"(a) : "l"(p));
    return a;
}

__device__ __forceinline__ void cp16(uint32_t dst, const void* src) {
    asm volatile("cp.async.cg.shared.global [%0], [%1], 16;"
                 :: "r"(dst), "l"(src) : "memory");
}
#define CP_COMMIT() asm volatile("cp.async.commit_group;" ::: "memory")

__device__ __forceinline__ void mma_f16(float* c, const uint32_t* a, const uint32_t* b) {
    asm volatile(
        "mma.sync.aligned.m16n8k16.row.col.f32.f16.f16.f32 "
        "{%0,%1,%2,%3}, {%4,%5,%6,%7}, {%8,%9}, {%0,%1,%2,%3};"
        : "+f"(c[0]), "+f"(c[1]), "+f"(c[2]), "+f"(c[3])
        : "r"(a[0]), "r"(a[1]), "r"(a[2]), "r"(a[3]), "r"(b[0]), "r"(b[1]));
}

__device__ __forceinline__ void ldsm_x4(uint32_t* r, uint32_t addr) {
    asm volatile("ldmatrix.sync.aligned.m8n8.x4.shared.b16 {%0,%1,%2,%3}, [%4];"
        : "=r"(r[0]), "=r"(r[1]), "=r"(r[2]), "=r"(r[3]) : "r"(addr));
}

// Fast exact-enough gelu: erf via Abramowitz-Stegun 7.1.26 (|err| <= 1.5e-7)
__device__ __forceinline__ float gelu_f(float x) {
    float y  = fabsf(x) * 0.70710678118654752f;
    float t  = __frcp_rn(1.0f + 0.3275911f * y);
    float p  = t * (0.254829592f + t * (-0.284496736f + t * (1.421413741f
             + t * (-1.453152027f + t * 1.061405429f))));
    float er = 1.0f - p * __expf(-y * y);
    er = copysignf(er, x);
    return 0.5f * x * (1.0f + er);
}

// ---------------------------------------------------------------------------
// FP16 GEMM (R11/R12 proven config): CTA 128x128, BK=64, 8 warps (2x4),
// warp tile 64x32, 2 CTAs/SM, 3-stage cp.async.cg, m16n8k16, fp32 accumulate.
// EPI: 0=bias, 1=bias+gelu, 2=bias+residual(fp32)
// AFF: 0=none, 1=half2 affine on A fragments, 2=fp32 affine on fp32 residual
// STATS / WF (fp32 out) / WH (half out)
// SPLIT3: grid.x=12 over concat [q|k|v]; route each 128-col block to Ch/Ch2/Ch3
// ---------------------------------------------------------------------------
#define PHB 144                          // bytes per smem row (72 halves)
#define A_HALF_B (128 * PHB)
#define STAGE_B (2 * A_HALF_B)
#define GEMM_SMEM (3 * STAGE_B)          // 110592 B

template <int EPI, int AFF, int STATS, int WF, int WH, int SPLIT3>
__global__ __launch_bounds__(256, 2)
void mma_gemm(const __half* __restrict__ A, const __half* __restrict__ W,
              const float* __restrict__ bias, const float* __restrict__ res,
              const float* __restrict__ scl, const float* __restrict__ shf,
              const __half* __restrict__ sclh, const __half* __restrict__ shfh,
              float* __restrict__ C, __half* __restrict__ Ch,
              __half* __restrict__ Ch2, __half* __restrict__ Ch3, int K)
{
    extern __shared__ float smf[];
    uint32_t sA = smem_u32(smf);
    uint32_t sB = sA + A_HALF_B;

    int tid  = threadIdx.x;
    int wid  = tid >> 5, lane = tid & 31;
    int wm   = (wid >> 2) * 64;
    int wn   = (wid & 3) * 32;
    int row0 = blockIdx.y * 128, col0 = blockIdx.x * 128;
    int qg   = lane >> 2, qt = lane & 3;
    int lg   = lane >> 3, lr = lane & 7;

    __half* Chout = Ch;
    int colShift = 0;
    int DoutS = gridDim.x * 128;
    if (SPLIT3) {
        int which = blockIdx.x >> 2;
        Chout = (which == 0) ? Ch : ((which == 1) ? Ch2 : Ch3);
        colShift = which * 512;
        DoutS = 512;
    }

    uint32_t baseA[4], baseB[2];
    #pragma unroll
    for (int mt = 0; mt < 4; mt++)
        baseA[mt] = sA + (wm + mt * 16 + (lg & 1) * 8 + lr) * PHB + (lg >> 1) * 16;
    #pragma unroll
    for (int p = 0; p < 2; p++)
        baseB[p]  = sB + (wn + (2 * p + (lg & 1)) * 8 + lr) * PHB + (lg >> 1) * 16;

    auto issue = [&](int st, int kb2) {
        uint32_t o = st * STAGE_B;
        #pragma unroll
        for (int i = 0; i < 4; i++) {
            int slot = tid + 256 * i;
            int row = slot >> 3, c16 = slot & 7;
            uint32_t d = o + row * PHB + c16 * 16;
            cp16(sA + d, A + (size_t)(row0 + row) * K + kb2 * 64 + c16 * 8);
            cp16(sB + d, W + (size_t)(col0 + row) * K + kb2 * 64 + c16 * 8);
        }
        CP_COMMIT();
    };

    int NKB = K / 64;
    issue(0, 0);
    if (NKB > 1) issue(1, 1);

    float acc[4][4][4];
    #pragma unroll
    for (int mt = 0; mt < 4; mt++)
        #pragma unroll
        for (int nt = 0; nt < 4; nt++)
            #pragma unroll
            for (int j = 0; j < 4; j++) acc[mt][nt][j] = 0.f;

    int st = 0, nst = 2;
    for (int kb = 0; kb < NKB; kb++) {
        if (kb + 1 < NKB)
            asm volatile("cp.async.wait_group 1;" ::: "memory");
        else
            asm volatile("cp.async.wait_group 0;" ::: "memory");
        __syncthreads();
        if (kb + 2 < NKB) {
            issue(nst, kb + 2);
            if (++nst == 3) nst = 0;
        }

        uint32_t stOff = st * STAGE_B;
        #pragma unroll
        for (int ks = 0; ks < 4; ks++) {
            uint32_t kB = stOff + ks * 32;
            uint32_t af[4][4], bf[4][2];
            #pragma unroll
            for (int mt = 0; mt < 4; mt++)
                ldsm_x4(af[mt], baseA[mt] + kB);
            #pragma unroll
            for (int p = 0; p < 2; p++) {
                uint32_t t[4];
                ldsm_x4(t, baseB[p] + kB);
                bf[2 * p][0]     = t[0]; bf[2 * p][1]     = t[2];
                bf[2 * p + 1][0] = t[1]; bf[2 * p + 1][1] = t[3];
            }
            if (AFF == 1) {
                int kg = kb * 64 + ks * 16 + 2 * qt;
                __half2 s_lo = *(const __half2*)&sclh[kg];
                __half2 h_lo = *(const __half2*)&shfh[kg];
                __half2 s_hi = *(const __half2*)&sclh[kg + 8];
                __half2 h_hi = *(const __half2*)&shfh[kg + 8];
                #pragma unroll
                for (int mt = 0; mt < 4; mt++) {
                    __half2 v0 = *(__half2*)&af[mt][0];
                    __half2 v1 = *(__half2*)&af[mt][1];
                    __half2 v2 = *(__half2*)&af[mt][2];
                    __half2 v3 = *(__half2*)&af[mt][3];
                    v0 = __hfma2(v0, s_lo, h_lo);
                    v1 = __hfma2(v1, s_lo, h_lo);
                    v2 = __hfma2(v2, s_hi, h_hi);
                    v3 = __hfma2(v3, s_hi, h_hi);
                    af[mt][0] = *(uint32_t*)&v0;
                    af[mt][1] = *(uint32_t*)&v1;
                    af[mt][2] = *(uint32_t*)&v2;
                    af[mt][3] = *(uint32_t*)&v3;
                }
            }
            #pragma unroll
            for (int mt = 0; mt < 4; mt++)
                #pragma unroll
                for (int nt = 0; nt < 4; nt++)
                    mma_f16(acc[mt][nt], af[mt], bf[nt]);
        }
        if (++st == 3) st = 0;
    }

    float cs[8], cq[8];
    if (STATS) {
        #pragma unroll
        for (int j = 0; j < 8; j++) { cs[j] = 0.f; cq[j] = 0.f; }
    }

    #pragma unroll
    for (int mt = 0; mt < 4; mt++) {
        #pragma unroll
        for (int nt = 0; nt < 4; nt++) {
            int c  = col0 + wn + nt * 8 + 2 * qt;   // global (bias/affine) col
            int r0 = row0 + wm + mt * 16 + qg;
            float b0 = bias[c], b1 = bias[c + 1];
            float s0 = 1.f, s1 = 1.f, h0 = 0.f, h1 = 0.f;
            if (AFF == 2) {
                s0 = scl[c]; s1 = scl[c + 1];
                h0 = shf[c]; h1 = shf[c + 1];
            }
            #pragma unroll
            for (int half = 0; half < 2; half++) {
                int r = r0 + half * 8;
                float vx = acc[mt][nt][half * 2 + 0] + b0;
                float vy = acc[mt][nt][half * 2 + 1] + b1;
                if (EPI == 1) {
                    vx = gelu_f(vx);
                    vy = gelu_f(vy);
                }
                size_t off = (size_t)r * DoutS + (c - colShift);
                if (EPI == 2) {
                    float2 rv = *(const float2*)(res + off);
                    if (AFF == 2) { vx += s0 * rv.x + h0; vy += s1 * rv.y + h1; }
                    else          { vx += rv.x;           vy += rv.y; }
                }
                if (STATS) {
                    cs[nt * 2 + 0] += vx; cq[nt * 2 + 0] += vx * vx;
                    cs[nt * 2 + 1] += vy; cq[nt * 2 + 1] += vy * vy;
                }
                if (WF)
                    *(float2*)(C + off) = make_float2(vx, vy);
                if (WH)
                    *(__half2*)(Chout + off) = __floats2half2_rn(vx, vy);
            }
        }
    }

    if (STATS) {
        #pragma unroll
        for (int j = 0; j < 8; j++) {
            #pragma unroll
            for (int m = 4; m <= 16; m <<= 1) {
                cs[j] += __shfl_xor_sync(0xffffffffu, cs[j], m);
                cq[j] += __shfl_xor_sync(0xffffffffu, cq[j], m);
            }
        }
        __syncthreads();
        float* ssum = smf;
        float* ssq  = smf + 256;
        int wrow = wid >> 2;
        if (lane < 4) {
            #pragma unroll
            for (int nt = 0; nt < 4; nt++) {
                #pragma unroll
                for (int p = 0; p < 2; p++) {
                    int cl = wn + nt * 8 + 2 * qt + p;
                    ssum[wrow * 128 + cl] = cs[nt * 2 + p];
                    ssq [wrow * 128 + cl] = cq[nt * 2 + p];
                }
            }
        }
        __syncthreads();
        if (tid < 128) {
            int slot = blockIdx.y * 512 + col0 + tid;
            g_psum[slot] = ssum[tid] + ssum[128 + tid];
            g_psq [slot] = ssq [tid] + ssq [128 + tid];
        }
    }
}

// ---------------------------------------------------------------------------
// fp32 -> fp16 conversion (weights)
// ---------------------------------------------------------------------------
__global__ void f2h_kernel(const float* __restrict__ src, __half* __restrict__ dst,
                           int n)
{
    for (int i = blockIdx.x * blockDim.x + threadIdx.x; i < n / 2;
         i += gridDim.x * blockDim.x) {
        float2 v = ((const float2*)src)[i];
        ((__half2*)dst)[i] = __floats2half2_rn(v.x, v.y);
    }
}

// concat per-layer qkv biases into [NL][1536]
__global__ void bias_concat_kernel(const float* __restrict__ bq,
                                   const float* __restrict__ bk,
                                   const float* __restrict__ bv,
                                   float* __restrict__ dst)
{
    int i = blockIdx.x * blockDim.x + threadIdx.x;
    if (i >= NL * 3 * DM) return;
    int l = i / (3 * DM), rem = i - l * 3 * DM;
    int which = rem / DM, c = rem - which * DM;
    const float* src = (which == 0) ? bq : (which == 1) ? bk : bv;
    dst[i] = src[l * DM + c];
}

// ---------------------------------------------------------------------------
// Token embedding: circular Conv1d + sinusoidal PE (rotation recurrence)
// ---------------------------------------------------------------------------
#define EMB_SMEM_FLOATS (512 * 49 + 336)
__global__ void embed_kernel(const float* __restrict__ x_enc,
                             const float* __restrict__ tok_w,
                             float* __restrict__ h, __half* __restrict__ hh)
{
    extern __shared__ float sm[];
    float* w_sm = sm;
    float* x_sm = sm + 512 * 49;
    int bm = blockIdx.x;
    int b = bm >> 6, m = bm & 63;
    int tid = threadIdx.x;

    for (int i = tid; i < 512 * 48; i += 256) {
        int d = i / 48, u = i - d * 48;
        w_sm[d * 49 + u] = tok_w[i];
    }
    for (int l = tid; l < 336; l += 256)
        x_sm[l] = x_enc[(b * 336 + l) * 64 + m];
    __syncthreads();

    const float CLOG = -9.210340371976184f / 256.0f;
    int d0 = tid, d1 = tid + 256;
    float fr0 = expf((float)(d0 >> 1) * CLOG);
    float fr1 = expf((float)(d1 >> 1) * CLOG);
    float sf0 = sinf(fr0), cf0 = cosf(fr0);
    float sf1 = sinf(fr1), cf1 = cosf(fr1);
    float s0 = 0.f, c0 = 1.f, s1 = 0.f, c1v = 1.f;

    for (int n = 0; n < NTOK; n++) {
        float a0 = 0.f, a1 = 0.f;
        #pragma unroll
        for (int t = 0; t < 3; t++) {
            int pp = n - 1 + t;
            pp = (pp < 0) ? (NTOK - 1) : (pp >= NTOK ? 0 : pp);
            const float* xp = x_sm + pp * 4;
            #pragma unroll
            for (int p = 0; p < 16; p++) {
                float xv = xp[p];
                a0 += xv * w_sm[d0 * 49 + p * 3 + t];
                a1 += xv * w_sm[d1 * 49 + p * 3 + t];
            }
        }
        float pe0 = (d0 & 1) ? c0  : s0;
        float pe1 = (d1 & 1) ? c1v : s1;
        size_t base = ((size_t)bm * NTOK + n) * DM;
        float v0 = a0 + pe0, v1 = a1 + pe1;
        h[base + d0] = v0;
        h[base + d1] = v1;
        hh[base + d0] = __float2half(v0);
        hh[base + d1] = __float2half(v1);
        float ns0 = s0 * cf0 + c0 * sf0;
        float nc0 = c0 * cf0 - s0 * sf0;
        s0 = ns0; c0 = nc0;
        float ns1 = s1 * cf1 + c1v * sf1;
        float nc1 = c1v * cf1 - s1 * sf1;
        s1 = ns1; c1v = nc1;
    }
}

// ---------------------------------------------------------------------------
// FP16 mma attention per (bm, head), register softmax, 2 CTAs/SM. (R12)
// ---------------------------------------------------------------------------
#define QKP 72
#define SVP 136
#define OFF_KH   (96 * QKP)
#define OFF_VT_H (OFF_KH + 128 * QKP)
#define OFF_SH_H (OFF_VT_H + 64 * SVP)
#define RED_OFF_B ((OFF_SH_H + 96 * SVP) * 2)
#define AT_SMEM (RED_OFF_B + 96 * 4 * 4)

__global__ __launch_bounds__(256, 2)
void attn_fa_kernel(const __half* __restrict__ q, const __half* __restrict__ k,
                    const __half* __restrict__ v, __half* __restrict__ o)
{
    extern __shared__ __half smh[];
    __half* Qh = smh;
    __half* Kh = smh + OFF_KH;
    __half* Vt = smh + OFF_VT_H;
    __half* Sh = smh + OFF_SH_H;
    float*  red = (float*)((char*)smh + RED_OFF_B);

    int bmh = blockIdx.x;
    int bm = bmh >> 3, hh = bmh & 7;
    int tid = threadIdx.x;
    int wid = tid >> 5, lane = tid & 31;
    int qg = lane >> 2, qt = lane & 3;
    int lg = lane >> 3, lr = lane & 7;
    size_t base = (size_t)bm * NTOK * DM + hh * EH;

    const __half HZ = __float2half(0.f);
    for (int i = tid; i < 15 * QKP; i += 256) Qh[81 * QKP + i] = HZ;
    for (int i = tid; i < 47 * QKP; i += 256) Kh[81 * QKP + i] = HZ;
    for (int i = tid; i < 64 * 47; i += 256) {
        int e = i / 47, c = 81 + (i % 47);
        Vt[e * SVP + c] = HZ;
    }

    for (int i = tid; i < NTOK * 8; i += 256) {
        int n = i >> 3, e8 = i & 7;
        *(uint4*)&Qh[n * QKP + e8 * 8] = *(const uint4*)(q + base + (size_t)n * DM + e8 * 8);
        *(uint4*)&Kh[n * QKP + e8 * 8] = *(const uint4*)(k + base + (size_t)n * DM + e8 * 8);
    }
    // V transpose: vectorized row loads, scalar column scatters
    for (int i = tid; i < NTOK * 8; i += 256) {
        int s = i >> 3, e8 = i & 7;
        __half tmp[8];
        *(uint4*)tmp = *(const uint4*)(v + base + (size_t)s * DM + e8 * 8);
        #pragma unroll
        for (int j = 0; j < 8; j++)
            Vt[(e8 * 8 + j) * SVP + s] = tmp[j];
    }
    __syncthreads();

    uint32_t qsu = smem_u32(Qh), ksu = smem_u32(Kh);
    uint32_t vtu = smem_u32(Vt), shu = smem_u32(Sh);
    int wm = (wid >> 2) * 48;
    int wnS = (wid & 3) * 32;
    int widn = wid & 3;

    float sacc[3][4][4];
    #pragma unroll
    for (int mt = 0; mt < 3; mt++)
        #pragma unroll
        for (int nt = 0; nt < 4; nt++)
            #pragma unroll
            for (int j = 0; j < 4; j++) sacc[mt][nt][j] = 0.f;
    {
        uint32_t baseA[3], baseB[2];
        #pragma unroll
        for (int mt = 0; mt < 3; mt++)
            baseA[mt] = qsu + (wm + mt * 16 + (lg & 1) * 8 + lr) * (QKP * 2) + (lg >> 1) * 16;
        #pragma unroll
        for (int p = 0; p < 2; p++)
            baseB[p]  = ksu + (wnS + (2 * p + (lg & 1)) * 8 + lr) * (QKP * 2) + (lg >> 1) * 16;

        #pragma unroll
        for (int ks = 0; ks < 4; ks++) {
            uint32_t kB = ks * 32;
            uint32_t af[3][4], bf[4][2];
            #pragma unroll
            for (int mt = 0; mt < 3; mt++)
                ldsm_x4(af[mt], baseA[mt] + kB);
            #pragma unroll
            for (int p = 0; p < 2; p++) {
                uint32_t t[4];
                ldsm_x4(t, baseB[p] + kB);
                bf[2 * p][0]     = t[0]; bf[2 * p][1]     = t[2];
                bf[2 * p + 1][0] = t[1]; bf[2 * p + 1][1] = t[3];
            }
            #pragma unroll
            for (int mt = 0; mt < 3; mt++)
                #pragma unroll
                for (int nt = 0; nt < 4; nt++)
                    mma_f16(sacc[mt][nt], af[mt], bf[nt]);
        }
    }

    const float SC = 0.125f;
    float rmax[3][2];
    #pragma unroll
    for (int mt = 0; mt < 3; mt++) { rmax[mt][0] = -1e30f; rmax[mt][1] = -1e30f; }
    #pragma unroll
    for (int mt = 0; mt < 3; mt++)
        #pragma unroll
        for (int nt = 0; nt < 4; nt++)
            #pragma unroll
            for (int j = 0; j < 4; j++) {
                int c = wnS + nt * 8 + 2 * qt + (j & 1);
                if (c <= 80) {
                    float vv = sacc[mt][nt][j] * SC;
                    int hl = j >> 1;
                    rmax[mt][hl] = fmaxf(rmax[mt][hl], vv);
                }
            }
    #pragma unroll
    for (int mt = 0; mt < 3; mt++)
        #pragma unroll
        for (int hl = 0; hl < 2; hl++) {
            rmax[mt][hl] = fmaxf(rmax[mt][hl], __shfl_xor_sync(0xffffffffu, rmax[mt][hl], 1));
            rmax[mt][hl] = fmaxf(rmax[mt][hl], __shfl_xor_sync(0xffffffffu, rmax[mt][hl], 2));
        }
    if (qt == 0) {
        #pragma unroll
        for (int mt = 0; mt < 3; mt++)
            #pragma unroll
            for (int hl = 0; hl < 2; hl++)
                red[(wm + mt * 16 + qg + hl * 8) * 4 + widn] = rmax[mt][hl];
    }
    __syncthreads();
    float fmx[3][2];
    #pragma unroll
    for (int mt = 0; mt < 3; mt++)
        #pragma unroll
        for (int hl = 0; hl < 2; hl++) {
            const float* rr = &red[(wm + mt * 16 + qg + hl * 8) * 4];
            fmx[mt][hl] = fmaxf(fmaxf(rr[0], rr[1]), fmaxf(rr[2], rr[3]));
        }
    __syncthreads();

    float rsum[3][2] = {};
    #pragma unroll
    for (int mt = 0; mt < 3; mt++)
        #pragma unroll
        for (int nt = 0; nt < 4; nt++)
            #pragma unroll
            for (int j = 0; j < 4; j++) {
                int c = wnS + nt * 8 + 2 * qt + (j & 1);
                int hl = j >> 1;
                float e = 0.f;
                if (c <= 80)
                    e = __expf(sacc[mt][nt][j] * SC - fmx[mt][hl]);
                sacc[mt][nt][j] = e;
                rsum[mt][hl] += e;
            }
    #pragma unroll
    for (int mt = 0; mt < 3; mt++)
        #pragma unroll
        for (int hl = 0; hl < 2; hl++) {
            rsum[mt][hl] += __shfl_xor_sync(0xffffffffu, rsum[mt][hl], 1);
            rsum[mt][hl] += __shfl_xor_sync(0xffffffffu, rsum[mt][hl], 2);
        }
    if (qt == 0) {
        #pragma unroll
        for (int mt = 0; mt < 3; mt++)
            #pragma unroll
            for (int hl = 0; hl < 2; hl++)
                red[(wm + mt * 16 + qg + hl * 8) * 4 + widn] = rsum[mt][hl];
    }
    __syncthreads();
    float finv[3][2];
    #pragma unroll
    for (int mt = 0; mt < 3; mt++)
        #pragma unroll
        for (int hl = 0; hl < 2; hl++) {
            const float* rr = &red[(wm + mt * 16 + qg + hl * 8) * 4];
            finv[mt][hl] = 1.0f / (rr[0] + rr[1] + rr[2] + rr[3]);
        }

    #pragma unroll
    for (int mt = 0; mt < 3; mt++)
        #pragma unroll
        for (int nt = 0; nt < 4; nt++)
            #pragma unroll
            for (int hl = 0; hl < 2; hl++) {
                int r = wm + mt * 16 + qg + hl * 8;
                int c = wnS + nt * 8 + 2 * qt;
                *(__half2*)&Sh[r * SVP + c] = __floats2half2_rn(
                    sacc[mt][nt][hl * 2 + 0] * finv[mt][hl],
                    sacc[mt][nt][hl * 2 + 1] * finv[mt][hl]);
            }
    __syncthreads();

    {
        int wnV = (wid & 3) * 16;
        uint32_t baseA[3], baseB;
        #pragma unroll
        for (int mt = 0; mt < 3; mt++)
            baseA[mt] = shu + (wm + mt * 16 + (lg & 1) * 8 + lr) * (SVP * 2) + (lg >> 1) * 16;
        baseB = vtu + (wnV + (lg & 1) * 8 + lr) * (SVP * 2) + (lg >> 1) * 16;

        float oacc[3][2][4];
        #pragma unroll
        for (int mt = 0; mt < 3; mt++)
            #pragma unroll
            for (int nt = 0; nt < 2; nt++)
                #pragma unroll
                for (int j = 0; j < 4; j++) oacc[mt][nt][j] = 0.f;

        #pragma unroll
        for (int ks = 0; ks < 8; ks++) {
            uint32_t kB = ks * 32;
            uint32_t af[3][4], bf[2][2];
            #pragma unroll
            for (int mt = 0; mt < 3; mt++)
                ldsm_x4(af[mt], baseA[mt] + kB);
            {
                uint32_t t[4];
                ldsm_x4(t, baseB + kB);
                bf[0][0] = t[0]; bf[0][1] = t[2];
                bf[1][0] = t[1]; bf[1][1] = t[3];
            }
            #pragma unroll
            for (int mt = 0; mt < 3; mt++)
                #pragma unroll
                for (int nt = 0; nt < 2; nt++)
                    mma_f16(oacc[mt][nt], af[mt], bf[nt]);
        }

        #pragma unroll
        for (int mt = 0; mt < 3; mt++)
            #pragma unroll
            for (int nt = 0; nt < 2; nt++) {
                int c  = wnV + nt * 8 + 2 * qt;
                int r0 = wm + mt * 16 + qg;
                #pragma unroll
                for (int hl = 0; hl < 2; hl++) {
                    int r = r0 + hl * 8;
                    if (r < NTOK)
                        *(__half2*)(o + base + (size_t)r * DM + c) = __floats2half2_rn(
                            oacc[mt][nt][hl * 2 + 0], oacc[mt][nt][hl * 2 + 1]);
                }
            }
    }
}

// ---------------------------------------------------------------------------
// BN finalize
// ---------------------------------------------------------------------------
__global__ void bn_reduce2_kernel(const float* __restrict__ gamma,
                                  const float* __restrict__ beta,
                                  float* __restrict__ scl, float* __restrict__ shf,
                                  __half* __restrict__ sclh, __half* __restrict__ shfh)
{
    int c = blockIdx.x;
    int tid = threadIdx.x, wid = tid >> 5, lane = tid & 31;
    float s = 0.f, q = 0.f;
    for (int j = tid; j < RTILES; j += 256) {
        s += g_psum[j * 512 + c];
        q += g_psq [j * 512 + c];
    }
    #pragma unroll
    for (int m = 16; m; m >>= 1) {
        s += __shfl_xor_sync(0xffffffffu, s, m);
        q += __shfl_xor_sync(0xffffffffu, q, m);
    }
    __shared__ float rs[8], rq[8];
    if (lane == 0) { rs[wid] = s; rq[wid] = q; }
    __syncthreads();
    if (tid == 0) {
        float S = 0.f, Q = 0.f;
        #pragma unroll
        for (int w = 0; w < 8; w++) { S += rs[w]; Q += rq[w]; }
        const float invn = 1.0f / (float)RT;
        float mu  = S * invn;
        float var = Q * invn - mu * mu;
        float rinv = rsqrtf(var + 1e-5f);
        float sc = rinv * gamma[c];
        float sh = beta[c] - mu * sc;
        scl[c] = sc;  shf[c] = sh;
        sclh[c] = __float2half(sc);
        shfh[c] = __float2half(sh);
    }
}

__global__ void bn_norm_kernel(const float* __restrict__ y,
                               const float* __restrict__ scl,
                               const float* __restrict__ shf,
                               float* __restrict__ out)
{
    const int total = RT * DM / 4;
    for (int i = blockIdx.x * blockDim.x + threadIdx.x; i < total;
         i += gridDim.x * blockDim.x) {
        float4 vv = ((const float4*)y)[i];
        int c = (i & 127) * 4;
        float4 oo;
        oo.x = vv.x * scl[c + 0] + shf[c + 0];
        oo.y = vv.y * scl[c + 1] + shf[c + 1];
        oo.z = vv.z * scl[c + 2] + shf[c + 2];
        oo.w = vv.w * scl[c + 3] + shf[c + 3];
        ((float4*)out)[i] = oo;
    }
}

// ---------------------------------------------------------------------------
// Orchestration
// ---------------------------------------------------------------------------
extern "C" void kernel_launch(void* const* d_in, const int* in_sizes, int n_in,
                              void* d_out, int out_size)
{
    const float* x_enc = (const float*)d_in[0];
    const float* tok_w = (const float*)d_in[1];
    const float* wq  = (const float*)d_in[2];
    const float* bq  = (const float*)d_in[3];
    const float* wk  = (const float*)d_in[4];
    const float* bk  = (const float*)d_in[5];
    const float* wv  = (const float*)d_in[6];
    const float* bv  = (const float*)d_in[7];
    const float* wo  = (const float*)d_in[8];
    const float* bo  = (const float*)d_in[9];
    const float* c1w = (const float*)d_in[10];
    const float* c1b = (const float*)d_in[11];
    const float* c2w = (const float*)d_in[12];
    const float* c2b = (const float*)d_in[13];
    const float* g1  = (const float*)d_in[14];
    const float* be1 = (const float*)d_in[15];
    const float* g2  = (const float*)d_in[16];
    const float* be2 = (const float*)d_in[17];
    float* out = (float*)d_out;

    float *p_h, *p_y, *p_scl, *p_shf, *p_bqkv;
    __half *p_hh, *p_qh, *p_kh, *p_vh, *p_atth, *p_yh, *p_th, *p_sclh, *p_shfh;
    __half *p_wqkv, *p_woh, *p_c1h, *p_c2h;
    cudaGetSymbolAddress((void**)&p_h,   g_h);
    cudaGetSymbolAddress((void**)&p_y,   g_y);
    cudaGetSymbolAddress((void**)&p_hh,   g_h_h);
    cudaGetSymbolAddress((void**)&p_qh,   g_q_h);
    cudaGetSymbolAddress((void**)&p_kh,   g_k_h);
    cudaGetSymbolAddress((void**)&p_vh,   g_v_h);
    cudaGetSymbolAddress((void**)&p_atth, g_att_h);
    cudaGetSymbolAddress((void**)&p_yh,   g_y_h);
    cudaGetSymbolAddress((void**)&p_th,   g_t_h);
    cudaGetSymbolAddress((void**)&p_wqkv, g_wqkv_h);
    cudaGetSymbolAddress((void**)&p_bqkv, g_bqkv);
    cudaGetSymbolAddress((void**)&p_woh, g_wo_h);
    cudaGetSymbolAddress((void**)&p_c1h, g_c1_h);
    cudaGetSymbolAddress((void**)&p_c2h, g_c2_h);
    cudaGetSymbolAddress((void**)&p_scl, g_bnscale);
    cudaGetSymbolAddress((void**)&p_shf, g_bnshift);
    cudaGetSymbolAddress((void**)&p_sclh, g_bnscaleh);
    cudaGetSymbolAddress((void**)&p_shfh, g_bnshifth);
    float*  scl0  = p_scl;        float*  shf0  = p_shf;
    float*  scl1  = p_scl + 512;  float*  shf1  = p_shf + 512;
    __half* scl0h = p_sclh;       __half* shf0h = p_shfh;
    __half* scl1h = p_sclh + 512; __half* shf1h = p_shfh + 512;

    const int EMB_SMEM = EMB_SMEM_FLOATS * 4;
    cudaFuncSetAttribute(embed_kernel,
        cudaFuncAttributeMaxDynamicSharedMemorySize, EMB_SMEM);
    cudaFuncSetAttribute(attn_fa_kernel,
        cudaFuncAttributeMaxDynamicSharedMemorySize, AT_SMEM);
    cudaFuncSetAttribute(mma_gemm<0, 0, 0, 0, 1, 1>,
        cudaFuncAttributeMaxDynamicSharedMemorySize, GEMM_SMEM);
    cudaFuncSetAttribute(mma_gemm<0, 1, 0, 0, 1, 1>,
        cudaFuncAttributeMaxDynamicSharedMemorySize, GEMM_SMEM);
    cudaFuncSetAttribute(mma_gemm<2, 0, 1, 1, 1, 0>,
        cudaFuncAttributeMaxDynamicSharedMemorySize, GEMM_SMEM);
    cudaFuncSetAttribute(mma_gemm<2, 2, 1, 1, 1, 0>,
        cudaFuncAttributeMaxDynamicSharedMemorySize, GEMM_SMEM);
    cudaFuncSetAttribute(mma_gemm<1, 1, 0, 0, 1, 0>,
        cudaFuncAttributeMaxDynamicSharedMemorySize, GEMM_SMEM);

    // weight conversion: qkv concat per layer [q|k|v] x [512][512]
    for (int l = 0; l < NL; l++) {
        f2h_kernel<<<256, 256>>>(wq + l * DM * DM, p_wqkv + (size_t)l * 3 * DM * DM,
                                 DM * DM);
        f2h_kernel<<<256, 256>>>(wk + l * DM * DM, p_wqkv + (size_t)l * 3 * DM * DM + DM * DM,
                                 DM * DM);
        f2h_kernel<<<256, 256>>>(wv + l * DM * DM, p_wqkv + (size_t)l * 3 * DM * DM + 2 * DM * DM,
                                 DM * DM);
    }
    bias_concat_kernel<<<(NL * 3 * DM + 255) / 256, 256>>>(bq, bk, bv, p_bqkv);
    f2h_kernel<<<512, 256>>>(wo,  p_woh, NL * DM * DM);
    f2h_kernel<<<512, 256>>>(c1w, p_c1h, NL * DFF * DM);
    f2h_kernel<<<512, 256>>>(c2w, p_c2h, NL * DM * DFF);

    embed_kernel<<<2048, 256, EMB_SMEM>>>(x_enc, tok_w, p_h, p_hh);

    for (int l = 0; l < NL; l++) {
        const size_t QKVW = (size_t)l * 3 * DM * DM;
        const int WOFF = l * DM * DM;
        const int FOFF = l * DFF * DM;

        if (l == 0)
            mma_gemm<0, 0, 0, 0, 1, 1><<<dim3(12, RTILES), 256, GEMM_SMEM>>>(
                p_hh, p_wqkv + QKVW, p_bqkv + l * 3 * DM, nullptr, nullptr, nullptr,
                nullptr, nullptr, nullptr, p_qh, p_kh, p_vh, DM);
        else
            mma_gemm<0, 1, 0, 0, 1, 1><<<dim3(12, RTILES), 256, GEMM_SMEM>>>(
                p_hh, p_wqkv + QKVW, p_bqkv + l * 3 * DM, nullptr, nullptr, nullptr,
                scl1h, shf1h, nullptr, p_qh, p_kh, p_vh, DM);

        attn_fa_kernel<<<2048 * NH, 256, AT_SMEM>>>(p_qh, p_kh, p_vh, p_atth);

        if (l == 0)
            mma_gemm<2, 0, 1, 1, 1, 0><<<dim3(4, RTILES), 256, GEMM_SMEM>>>(
                p_atth, p_woh + WOFF, bo + l * DM, p_h, nullptr, nullptr,
                nullptr, nullptr, p_y, p_yh, nullptr, nullptr, DM);
        else
            mma_gemm<2, 2, 1, 1, 1, 0><<<dim3(4, RTILES), 256, GEMM_SMEM>>>(
                p_atth, p_woh + WOFF, bo + l * DM, p_h, scl1, shf1,
                nullptr, nullptr, p_y, p_yh, nullptr, nullptr, DM);

        bn_reduce2_kernel<<<512, 256>>>(g1 + l * DM, be1 + l * DM,
                                        scl0, shf0, scl0h, shf0h);

        mma_gemm<1, 1, 0, 0, 1, 0><<<dim3(8, RTILES), 256, GEMM_SMEM>>>(
            p_yh, p_c1h + FOFF, c1b + l * DFF, nullptr, nullptr, nullptr,
            scl0h, shf0h, nullptr, p_th, nullptr, nullptr, DM);
        mma_gemm<2, 2, 1, 1, 1, 0><<<dim3(4, RTILES), 256, GEMM_SMEM>>>(
            p_th, p_c2h + FOFF, c2b + l * DM, p_y, scl0, shf0,
            nullptr, nullptr, p_h, p_hh, nullptr, nullptr, DFF);

        bn_reduce2_kernel<<<512, 256>>>(g2 + l * DM, be2 + l * DM,
                                        scl1, shf1, scl1h, shf1h);
    }

    bn_norm_kernel<<<4096, 256>>>(p_h, scl1, shf1, out);
}

// round 16
// speedup vs baseline: 1.8878x; 1.0368x over previous
#include <cuda_runtime.h>
#include <cuda_fp16.h>
#include <math.h>
#include <stdint.h>

// ---------------------------------------------------------------------------
// Problem constants
// ---------------------------------------------------------------------------
#define NTOK   81
#define DM     512
#define NH     8
#define EH     64
#define DFF    1024
#define NL     3
#define RT     (2048 * 81)           // 165888 tokens
#define RTILES (RT / 128)            // 1296

// ---------------------------------------------------------------------------
// Scratch (device globals)
// ---------------------------------------------------------------------------
__device__ float  g_h [RT * DM];     // fp32 residual: embed out / raw y2
__device__ float  g_y [RT * DM];     // fp32 residual: raw y1
__device__ __half g_h_h  [RT * DM];
__device__ __half g_q_h  [RT * DM];
__device__ __half g_k_h  [RT * DM];
__device__ __half g_v_h  [RT * DM];
__device__ __half g_att_h[RT * DM];
__device__ __half g_y_h  [RT * DM];
__device__ __half g_t_h  [RT * DFF];
__device__ __half g_wqkv_h[NL * 3 * DM * DM];   // concat [q|k|v]
__device__ float  g_bqkv  [NL * 3 * DM];
__device__ __half g_wo_h[NL * DM * DM];
__device__ __half g_c1_h[NL * DFF * DM];
__device__ __half g_c2_h[NL * DM * DFF];
__device__ float  g_psum[RTILES * 512];
__device__ float  g_psq [RTILES * 512];
__device__ float  g_bnscale[2 * 512];
__device__ float  g_bnshift[2 * 512];
__device__ __half g_bnscaleh[2 * 512];
__device__ __half g_bnshifth[2 * 512];

// ---------------------------------------------------------------------------
// PTX helpers
// ---------------------------------------------------------------------------
__device__ __forceinline__ uint32_t smem_u32(const void* p) {
    uint32_t a;
    asm("{ .reg .u64 t; cvta.to.shared.u64 t, %1; cvt.u32.u64 %0, t; }"
        : "=r"(a) : "l"(p));
    return a;
}

__device__ __forceinline__ void cp16(uint32_t dst, const void* src) {
    asm volatile("cp.async.cg.shared.global [%0], [%1], 16;"
                 :: "r"(dst), "l"(src) : "memory");
}
#define CP_COMMIT() asm volatile("cp.async.commit_group;" ::: "memory")

__device__ __forceinline__ void mma_f16(float* c, const uint32_t* a, const uint32_t* b) {
    asm volatile(
        "mma.sync.aligned.m16n8k16.row.col.f32.f16.f16.f32 "
        "{%0,%1,%2,%3}, {%4,%5,%6,%7}, {%8,%9}, {%0,%1,%2,%3};"
        : "+f"(c[0]), "+f"(c[1]), "+f"(c[2]), "+f"(c[3])
        : "r"(a[0]), "r"(a[1]), "r"(a[2]), "r"(a[3]), "r"(b[0]), "r"(b[1]));
}

__device__ __forceinline__ void ldsm_x4(uint32_t* r, uint32_t addr) {
    asm volatile("ldmatrix.sync.aligned.m8n8.x4.shared.b16 {%0,%1,%2,%3}, [%4];"
        : "=r"(r[0]), "=r"(r[1]), "=r"(r[2]), "=r"(r[3]) : "r"(addr));
}

// Fast gelu: erf via Abramowitz-Stegun 7.1.26 (|err| <= 1.5e-7)
__device__ __forceinline__ float gelu_f(float x) {
    float y  = fabsf(x) * 0.70710678118654752f;
    float t  = __frcp_rn(1.0f + 0.3275911f * y);
    float p  = t * (0.254829592f + t * (-0.284496736f + t * (1.421413741f
             + t * (-1.453152027f + t * 1.061405429f))));
    float er = 1.0f - p * __expf(-y * y);
    er = copysignf(er, x);
    return 0.5f * x * (1.0f + er);
}

// ---------------------------------------------------------------------------
// FP16 GEMM (frozen proven config): CTA 128x128, BK=64, 8 warps (2x4),
// warp tile 64x32, 2 CTAs/SM, 3-stage cp.async.cg, m16n8k16, fp32 accumulate.
// EPI: 0=bias, 1=bias+gelu, 2=bias+residual(fp32)
// AFF: 0=none, 1=half2 affine on A fragments, 2=fp32 affine on fp32 residual
// STATS / WF / WH / SPLIT3 (grid.x=12 over concat [q|k|v])
// ---------------------------------------------------------------------------
#define PHB 144
#define A_HALF_B (128 * PHB)
#define STAGE_B (2 * A_HALF_B)
#define GEMM_SMEM (3 * STAGE_B)          // 110592 B

template <int EPI, int AFF, int STATS, int WF, int WH, int SPLIT3>
__global__ __launch_bounds__(256, 2)
void mma_gemm(const __half* __restrict__ A, const __half* __restrict__ W,
              const float* __restrict__ bias, const float* __restrict__ res,
              const float* __restrict__ scl, const float* __restrict__ shf,
              const __half* __restrict__ sclh, const __half* __restrict__ shfh,
              float* __restrict__ C, __half* __restrict__ Ch,
              __half* __restrict__ Ch2, __half* __restrict__ Ch3, int K)
{
    extern __shared__ float smf[];
    uint32_t sA = smem_u32(smf);
    uint32_t sB = sA + A_HALF_B;

    int tid  = threadIdx.x;
    int wid  = tid >> 5, lane = tid & 31;
    int wm   = (wid >> 2) * 64;
    int wn   = (wid & 3) * 32;
    int row0 = blockIdx.y * 128, col0 = blockIdx.x * 128;
    int qg   = lane >> 2, qt = lane & 3;
    int lg   = lane >> 3, lr = lane & 7;

    __half* Chout = Ch;
    int colShift = 0;
    int DoutS = gridDim.x * 128;
    if (SPLIT3) {
        int which = blockIdx.x >> 2;
        Chout = (which == 0) ? Ch : ((which == 1) ? Ch2 : Ch3);
        colShift = which * 512;
        DoutS = 512;
    }

    uint32_t baseA[4], baseB[2];
    #pragma unroll
    for (int mt = 0; mt < 4; mt++)
        baseA[mt] = sA + (wm + mt * 16 + (lg & 1) * 8 + lr) * PHB + (lg >> 1) * 16;
    #pragma unroll
    for (int p = 0; p < 2; p++)
        baseB[p]  = sB + (wn + (2 * p + (lg & 1)) * 8 + lr) * PHB + (lg >> 1) * 16;

    auto issue = [&](int st, int kb2) {
        uint32_t o = st * STAGE_B;
        #pragma unroll
        for (int i = 0; i < 4; i++) {
            int slot = tid + 256 * i;
            int row = slot >> 3, c16 = slot & 7;
            uint32_t d = o + row * PHB + c16 * 16;
            cp16(sA + d, A + (size_t)(row0 + row) * K + kb2 * 64 + c16 * 8);
            cp16(sB + d, W + (size_t)(col0 + row) * K + kb2 * 64 + c16 * 8);
        }
        CP_COMMIT();
    };

    int NKB = K / 64;
    issue(0, 0);
    if (NKB > 1) issue(1, 1);

    float acc[4][4][4];
    #pragma unroll
    for (int mt = 0; mt < 4; mt++)
        #pragma unroll
        for (int nt = 0; nt < 4; nt++)
            #pragma unroll
            for (int j = 0; j < 4; j++) acc[mt][nt][j] = 0.f;

    int st = 0, nst = 2;
    for (int kb = 0; kb < NKB; kb++) {
        if (kb + 1 < NKB)
            asm volatile("cp.async.wait_group 1;" ::: "memory");
        else
            asm volatile("cp.async.wait_group 0;" ::: "memory");
        __syncthreads();
        if (kb + 2 < NKB) {
            issue(nst, kb + 2);
            if (++nst == 3) nst = 0;
        }

        uint32_t stOff = st * STAGE_B;
        #pragma unroll
        for (int ks = 0; ks < 4; ks++) {
            uint32_t kB = stOff + ks * 32;
            uint32_t af[4][4], bf[4][2];
            #pragma unroll
            for (int mt = 0; mt < 4; mt++)
                ldsm_x4(af[mt], baseA[mt] + kB);
            #pragma unroll
            for (int p = 0; p < 2; p++) {
                uint32_t t[4];
                ldsm_x4(t, baseB[p] + kB);
                bf[2 * p][0]     = t[0]; bf[2 * p][1]     = t[2];
                bf[2 * p + 1][0] = t[1]; bf[2 * p + 1][1] = t[3];
            }
            if (AFF == 1) {
                int kg = kb * 64 + ks * 16 + 2 * qt;
                __half2 s_lo = *(const __half2*)&sclh[kg];
                __half2 h_lo = *(const __half2*)&shfh[kg];
                __half2 s_hi = *(const __half2*)&sclh[kg + 8];
                __half2 h_hi = *(const __half2*)&shfh[kg + 8];
                #pragma unroll
                for (int mt = 0; mt < 4; mt++) {
                    __half2 v0 = *(__half2*)&af[mt][0];
                    __half2 v1 = *(__half2*)&af[mt][1];
                    __half2 v2 = *(__half2*)&af[mt][2];
                    __half2 v3 = *(__half2*)&af[mt][3];
                    v0 = __hfma2(v0, s_lo, h_lo);
                    v1 = __hfma2(v1, s_lo, h_lo);
                    v2 = __hfma2(v2, s_hi, h_hi);
                    v3 = __hfma2(v3, s_hi, h_hi);
                    af[mt][0] = *(uint32_t*)&v0;
                    af[mt][1] = *(uint32_t*)&v1;
                    af[mt][2] = *(uint32_t*)&v2;
                    af[mt][3] = *(uint32_t*)&v3;
                }
            }
            #pragma unroll
            for (int mt = 0; mt < 4; mt++)
                #pragma unroll
                for (int nt = 0; nt < 4; nt++)
                    mma_f16(acc[mt][nt], af[mt], bf[nt]);
        }
        if (++st == 3) st = 0;
    }

    float cs[8], cq[8];
    if (STATS) {
        #pragma unroll
        for (int j = 0; j < 8; j++) { cs[j] = 0.f; cq[j] = 0.f; }
    }

    #pragma unroll
    for (int mt = 0; mt < 4; mt++) {
        #pragma unroll
        for (int nt = 0; nt < 4; nt++) {
            int c  = col0 + wn + nt * 8 + 2 * qt;
            int r0 = row0 + wm + mt * 16 + qg;
            float b0 = bias[c], b1 = bias[c + 1];
            float s0 = 1.f, s1 = 1.f, h0 = 0.f, h1 = 0.f;
            if (AFF == 2) {
                s0 = scl[c]; s1 = scl[c + 1];
                h0 = shf[c]; h1 = shf[c + 1];
            }
            #pragma unroll
            for (int half = 0; half < 2; half++) {
                int r = r0 + half * 8;
                float vx = acc[mt][nt][half * 2 + 0] + b0;
                float vy = acc[mt][nt][half * 2 + 1] + b1;
                if (EPI == 1) {
                    vx = gelu_f(vx);
                    vy = gelu_f(vy);
                }
                size_t off = (size_t)r * DoutS + (c - colShift);
                if (EPI == 2) {
                    float2 rv = *(const float2*)(res + off);
                    if (AFF == 2) { vx += s0 * rv.x + h0; vy += s1 * rv.y + h1; }
                    else          { vx += rv.x;           vy += rv.y; }
                }
                if (STATS) {
                    cs[nt * 2 + 0] += vx; cq[nt * 2 + 0] += vx * vx;
                    cs[nt * 2 + 1] += vy; cq[nt * 2 + 1] += vy * vy;
                }
                if (WF)
                    *(float2*)(C + off) = make_float2(vx, vy);
                if (WH)
                    *(__half2*)(Chout + off) = __floats2half2_rn(vx, vy);
            }
        }
    }

    if (STATS) {
        #pragma unroll
        for (int j = 0; j < 8; j++) {
            #pragma unroll
            for (int m = 4; m <= 16; m <<= 1) {
                cs[j] += __shfl_xor_sync(0xffffffffu, cs[j], m);
                cq[j] += __shfl_xor_sync(0xffffffffu, cq[j], m);
            }
        }
        __syncthreads();
        float* ssum = smf;
        float* ssq  = smf + 256;
        int wrow = wid >> 2;
        if (lane < 4) {
            #pragma unroll
            for (int nt = 0; nt < 4; nt++) {
                #pragma unroll
                for (int p = 0; p < 2; p++) {
                    int cl = wn + nt * 8 + 2 * qt + p;
                    ssum[wrow * 128 + cl] = cs[nt * 2 + p];
                    ssq [wrow * 128 + cl] = cq[nt * 2 + p];
                }
            }
        }
        __syncthreads();
        if (tid < 128) {
            int slot = blockIdx.y * 512 + col0 + tid;
            g_psum[slot] = ssum[tid] + ssum[128 + tid];
            g_psq [slot] = ssq [tid] + ssq [128 + tid];
        }
    }
}

// ---------------------------------------------------------------------------
// Fused setup: all weight conversions (qkv concat, wo, c1, c2) + bias concat
// ---------------------------------------------------------------------------
#define WSZ (DM * DM)
__global__ void setup_kernel(const float* __restrict__ wq, const float* __restrict__ wk,
                             const float* __restrict__ wv, const float* __restrict__ wo,
                             const float* __restrict__ c1w, const float* __restrict__ c2w,
                             const float* __restrict__ bq, const float* __restrict__ bk,
                             const float* __restrict__ bv,
                             __half* __restrict__ wqkv, __half* __restrict__ woh,
                             __half* __restrict__ c1h, __half* __restrict__ c2h,
                             float* __restrict__ bqkv)
{
    int tid0 = blockIdx.x * blockDim.x + threadIdx.x;
    int stride = gridDim.x * blockDim.x;

    for (int i = tid0; i < NL * 3 * WSZ / 2; i += stride) {
        int seg = i / (WSZ / 2);
        int off = i - seg * (WSZ / 2);
        int l = seg / 3, w = seg - l * 3;
        const float* src = ((w == 0) ? wq : (w == 1) ? wk : wv) + (size_t)l * WSZ;
        float2 v = ((const float2*)src)[off];
        ((__half2*)(wqkv + (size_t)l * 3 * WSZ + (size_t)w * WSZ))[off] =
            __floats2half2_rn(v.x, v.y);
    }
    for (int i = tid0; i < NL * WSZ / 2; i += stride) {
        float2 v = ((const float2*)wo)[i];
        ((__half2*)woh)[i] = __floats2half2_rn(v.x, v.y);
    }
    for (int i = tid0; i < NL * DFF * DM / 2; i += stride) {
        float2 v = ((const float2*)c1w)[i];
        ((__half2*)c1h)[i] = __floats2half2_rn(v.x, v.y);
    }
    for (int i = tid0; i < NL * DM * DFF / 2; i += stride) {
        float2 v = ((const float2*)c2w)[i];
        ((__half2*)c2h)[i] = __floats2half2_rn(v.x, v.y);
    }
    for (int i = tid0; i < NL * 3 * DM; i += stride) {
        int l = i / (3 * DM), rem = i - l * 3 * DM;
        int w = rem / DM, c = rem - w * DM;
        const float* src = (w == 0) ? bq : (w == 1) ? bk : bv;
        bqkv[i] = src[l * DM + c];
    }
}

// ---------------------------------------------------------------------------
// Token embedding: circular Conv1d + sinusoidal PE (rotation recurrence)
// ---------------------------------------------------------------------------
#define EMB_SMEM_FLOATS (512 * 49 + 336)
__global__ void embed_kernel(const float* __restrict__ x_enc,
                             const float* __restrict__ tok_w,
                             float* __restrict__ h, __half* __restrict__ hh)
{
    extern __shared__ float sm[];
    float* w_sm = sm;
    float* x_sm = sm + 512 * 49;
    int bm = blockIdx.x;
    int b = bm >> 6, m = bm & 63;
    int tid = threadIdx.x;

    for (int i = tid; i < 512 * 48; i += 256) {
        int d = i / 48, u = i - d * 48;
        w_sm[d * 49 + u] = tok_w[i];
    }
    for (int l = tid; l < 336; l += 256)
        x_sm[l] = x_enc[(b * 336 + l) * 64 + m];
    __syncthreads();

    const float CLOG = -9.210340371976184f / 256.0f;
    int d0 = tid, d1 = tid + 256;
    float fr0 = expf((float)(d0 >> 1) * CLOG);
    float fr1 = expf((float)(d1 >> 1) * CLOG);
    float sf0 = sinf(fr0), cf0 = cosf(fr0);
    float sf1 = sinf(fr1), cf1 = cosf(fr1);
    float s0 = 0.f, c0 = 1.f, s1 = 0.f, c1v = 1.f;

    for (int n = 0; n < NTOK; n++) {
        float a0 = 0.f, a1 = 0.f;
        #pragma unroll
        for (int t = 0; t < 3; t++) {
            int pp = n - 1 + t;
            pp = (pp < 0) ? (NTOK - 1) : (pp >= NTOK ? 0 : pp);
            const float* xp = x_sm + pp * 4;
            #pragma unroll
            for (int p = 0; p < 16; p++) {
                float xv = xp[p];
                a0 += xv * w_sm[d0 * 49 + p * 3 + t];
                a1 += xv * w_sm[d1 * 49 + p * 3 + t];
            }
        }
        float pe0 = (d0 & 1) ? c0  : s0;
        float pe1 = (d1 & 1) ? c1v : s1;
        size_t base = ((size_t)bm * NTOK + n) * DM;
        float v0 = a0 + pe0, v1 = a1 + pe1;
        h[base + d0] = v0;
        h[base + d1] = v1;
        hh[base + d0] = __float2half(v0);
        hh[base + d1] = __float2half(v1);
        float ns0 = s0 * cf0 + c0 * sf0;
        float nc0 = c0 * cf0 - s0 * sf0;
        s0 = ns0; c0 = nc0;
        float ns1 = s1 * cf1 + c1v * sf1;
        float nc1 = c1v * cf1 - s1 * sf1;
        s1 = ns1; c1v = nc1;
    }
}

// ---------------------------------------------------------------------------
// FP16 mma attention, register softmax, Sh ALIASES Qh/Kh (dead after score
// mma; barrier-ordered) -> 50 KB smem, 3 CTAs/SM via __launch_bounds__.
// ---------------------------------------------------------------------------
#define QKP 72
#define SVP 136
#define OFF_KH   (96 * QKP)                 // 6912 halves
#define OFF_VT_H (OFF_KH + 128 * QKP)       // 16128 halves (Sh aliases [0,13056))
#define RED_OFF_B ((OFF_VT_H + 64 * SVP) * 2)  // 49664 bytes
#define AT_SMEM (RED_OFF_B + 96 * 4 * 4)       // 51200 bytes

__global__ __launch_bounds__(256, 3)
void attn_fa_kernel(const __half* __restrict__ q, const __half* __restrict__ k,
                    const __half* __restrict__ v, __half* __restrict__ o)
{
    extern __shared__ __half smh[];
    __half* Qh = smh;
    __half* Kh = smh + OFF_KH;
    __half* Vt = smh + OFF_VT_H;
    __half* Sh = smh;                       // alias over Qh/Kh (safe, see above)
    float*  red = (float*)((char*)smh + RED_OFF_B);

    int bmh = blockIdx.x;
    int bm = bmh >> 3, hh = bmh & 7;
    int tid = threadIdx.x;
    int wid = tid >> 5, lane = tid & 31;
    int qg = lane >> 2, qt = lane & 3;
    int lg = lane >> 3, lr = lane & 7;
    size_t base = (size_t)bm * NTOK * DM + hh * EH;

    const __half HZ = __float2half(0.f);
    for (int i = tid; i < 15 * QKP; i += 256) Qh[81 * QKP + i] = HZ;
    for (int i = tid; i < 47 * QKP; i += 256) Kh[81 * QKP + i] = HZ;
    for (int i = tid; i < 64 * 47; i += 256) {
        int e = i / 47, c = 81 + (i % 47);
        Vt[e * SVP + c] = HZ;
    }

    for (int i = tid; i < NTOK * 8; i += 256) {
        int n = i >> 3, e8 = i & 7;
        *(uint4*)&Qh[n * QKP + e8 * 8] = *(const uint4*)(q + base + (size_t)n * DM + e8 * 8);
        *(uint4*)&Kh[n * QKP + e8 * 8] = *(const uint4*)(k + base + (size_t)n * DM + e8 * 8);
    }
    for (int i = tid; i < NTOK * 8; i += 256) {
        int s = i >> 3, e8 = i & 7;
        __half tmp[8];
        *(uint4*)tmp = *(const uint4*)(v + base + (size_t)s * DM + e8 * 8);
        #pragma unroll
        for (int j = 0; j < 8; j++)
            Vt[(e8 * 8 + j) * SVP + s] = tmp[j];
    }
    __syncthreads();

    uint32_t qsu = smem_u32(Qh), ksu = smem_u32(Kh);
    uint32_t vtu = smem_u32(Vt), shu = smem_u32(Sh);
    int wm = (wid >> 2) * 48;
    int wnS = (wid & 3) * 32;
    int widn = wid & 3;

    float sacc[3][4][4];
    #pragma unroll
    for (int mt = 0; mt < 3; mt++)
        #pragma unroll
        for (int nt = 0; nt < 4; nt++)
            #pragma unroll
            for (int j = 0; j < 4; j++) sacc[mt][nt][j] = 0.f;
    {
        uint32_t baseA[3], baseB[2];
        #pragma unroll
        for (int mt = 0; mt < 3; mt++)
            baseA[mt] = qsu + (wm + mt * 16 + (lg & 1) * 8 + lr) * (QKP * 2) + (lg >> 1) * 16;
        #pragma unroll
        for (int p = 0; p < 2; p++)
            baseB[p]  = ksu + (wnS + (2 * p + (lg & 1)) * 8 + lr) * (QKP * 2) + (lg >> 1) * 16;

        #pragma unroll
        for (int ks = 0; ks < 4; ks++) {
            uint32_t kB = ks * 32;
            uint32_t af[3][4], bf[4][2];
            #pragma unroll
            for (int mt = 0; mt < 3; mt++)
                ldsm_x4(af[mt], baseA[mt] + kB);
            #pragma unroll
            for (int p = 0; p < 2; p++) {
                uint32_t t[4];
                ldsm_x4(t, baseB[p] + kB);
                bf[2 * p][0]     = t[0]; bf[2 * p][1]     = t[2];
                bf[2 * p + 1][0] = t[1]; bf[2 * p + 1][1] = t[3];
            }
            #pragma unroll
            for (int mt = 0; mt < 3; mt++)
                #pragma unroll
                for (int nt = 0; nt < 4; nt++)
                    mma_f16(sacc[mt][nt], af[mt], bf[nt]);
        }
    }

    const float SC = 0.125f;
    float rmax[3][2];
    #pragma unroll
    for (int mt = 0; mt < 3; mt++) { rmax[mt][0] = -1e30f; rmax[mt][1] = -1e30f; }
    #pragma unroll
    for (int mt = 0; mt < 3; mt++)
        #pragma unroll
        for (int nt = 0; nt < 4; nt++)
            #pragma unroll
            for (int j = 0; j < 4; j++) {
                int c = wnS + nt * 8 + 2 * qt + (j & 1);
                if (c <= 80) {
                    float vv = sacc[mt][nt][j] * SC;
                    int hl = j >> 1;
                    rmax[mt][hl] = fmaxf(rmax[mt][hl], vv);
                }
            }
    #pragma unroll
    for (int mt = 0; mt < 3; mt++)
        #pragma unroll
        for (int hl = 0; hl < 2; hl++) {
            rmax[mt][hl] = fmaxf(rmax[mt][hl], __shfl_xor_sync(0xffffffffu, rmax[mt][hl], 1));
            rmax[mt][hl] = fmaxf(rmax[mt][hl], __shfl_xor_sync(0xffffffffu, rmax[mt][hl], 2));
        }
    if (qt == 0) {
        #pragma unroll
        for (int mt = 0; mt < 3; mt++)
            #pragma unroll
            for (int hl = 0; hl < 2; hl++)
                red[(wm + mt * 16 + qg + hl * 8) * 4 + widn] = rmax[mt][hl];
    }
    __syncthreads();       // <- also orders all score-mma before Sh aliasing
    float fmx[3][2];
    #pragma unroll
    for (int mt = 0; mt < 3; mt++)
        #pragma unroll
        for (int hl = 0; hl < 2; hl++) {
            const float* rr = &red[(wm + mt * 16 + qg + hl * 8) * 4];
            fmx[mt][hl] = fmaxf(fmaxf(rr[0], rr[1]), fmaxf(rr[2], rr[3]));
        }
    __syncthreads();

    float rsum[3][2] = {};
    #pragma unroll
    for (int mt = 0; mt < 3; mt++)
        #pragma unroll
        for (int nt = 0; nt < 4; nt++)
            #pragma unroll
            for (int j = 0; j < 4; j++) {
                int c = wnS + nt * 8 + 2 * qt + (j & 1);
                int hl = j >> 1;
                float e = 0.f;
                if (c <= 80)
                    e = __expf(sacc[mt][nt][j] * SC - fmx[mt][hl]);
                sacc[mt][nt][j] = e;
                rsum[mt][hl] += e;
            }
    #pragma unroll
    for (int mt = 0; mt < 3; mt++)
        #pragma unroll
        for (int hl = 0; hl < 2; hl++) {
            rsum[mt][hl] += __shfl_xor_sync(0xffffffffu, rsum[mt][hl], 1);
            rsum[mt][hl] += __shfl_xor_sync(0xffffffffu, rsum[mt][hl], 2);
        }
    if (qt == 0) {
        #pragma unroll
        for (int mt = 0; mt < 3; mt++)
            #pragma unroll
            for (int hl = 0; hl < 2; hl++)
                red[(wm + mt * 16 + qg + hl * 8) * 4 + widn] = rsum[mt][hl];
    }
    __syncthreads();
    float finv[3][2];
    #pragma unroll
    for (int mt = 0; mt < 3; mt++)
        #pragma unroll
        for (int hl = 0; hl < 2; hl++) {
            const float* rr = &red[(wm + mt * 16 + qg + hl * 8) * 4];
            finv[mt][hl] = 1.0f / (rr[0] + rr[1] + rr[2] + rr[3]);
        }

    #pragma unroll
    for (int mt = 0; mt < 3; mt++)
        #pragma unroll
        for (int nt = 0; nt < 4; nt++)
            #pragma unroll
            for (int hl = 0; hl < 2; hl++) {
                int r = wm + mt * 16 + qg + hl * 8;
                int c = wnS + nt * 8 + 2 * qt;
                *(__half2*)&Sh[r * SVP + c] = __floats2half2_rn(
                    sacc[mt][nt][hl * 2 + 0] * finv[mt][hl],
                    sacc[mt][nt][hl * 2 + 1] * finv[mt][hl]);
            }
    __syncthreads();

    {
        int wnV = (wid & 3) * 16;
        uint32_t baseA[3], baseB;
        #pragma unroll
        for (int mt = 0; mt < 3; mt++)
            baseA[mt] = shu + (wm + mt * 16 + (lg & 1) * 8 + lr) * (SVP * 2) + (lg >> 1) * 16;
        baseB = vtu + (wnV + (lg & 1) * 8 + lr) * (SVP * 2) + (lg >> 1) * 16;

        float oacc[3][2][4];
        #pragma unroll
        for (int mt = 0; mt < 3; mt++)
            #pragma unroll
            for (int nt = 0; nt < 2; nt++)
                #pragma unroll
                for (int j = 0; j < 4; j++) oacc[mt][nt][j] = 0.f;

        #pragma unroll
        for (int ks = 0; ks < 8; ks++) {
            uint32_t kB = ks * 32;
            uint32_t af[3][4], bf[2][2];
            #pragma unroll
            for (int mt = 0; mt < 3; mt++)
                ldsm_x4(af[mt], baseA[mt] + kB);
            {
                uint32_t t[4];
                ldsm_x4(t, baseB + kB);
                bf[0][0] = t[0]; bf[0][1] = t[2];
                bf[1][0] = t[1]; bf[1][1] = t[3];
            }
            #pragma unroll
            for (int mt = 0; mt < 3; mt++)
                #pragma unroll
                for (int nt = 0; nt < 2; nt++)
                    mma_f16(oacc[mt][nt], af[mt], bf[nt]);
        }

        #pragma unroll
        for (int mt = 0; mt < 3; mt++)
            #pragma unroll
            for (int nt = 0; nt < 2; nt++) {
                int c  = wnV + nt * 8 + 2 * qt;
                int r0 = wm + mt * 16 + qg;
                #pragma unroll
                for (int hl = 0; hl < 2; hl++) {
                    int r = r0 + hl * 8;
                    if (r < NTOK)
                        *(__half2*)(o + base + (size_t)r * DM + c) = __floats2half2_rn(
                            oacc[mt][nt][hl * 2 + 0], oacc[mt][nt][hl * 2 + 1]);
                }
            }
    }
}

// ---------------------------------------------------------------------------
// BN finalize
// ---------------------------------------------------------------------------
__global__ void bn_reduce2_kernel(const float* __restrict__ gamma,
                                  const float* __restrict__ beta,
                                  float* __restrict__ scl, float* __restrict__ shf,
                                  __half* __restrict__ sclh, __half* __restrict__ shfh)
{
    int c = blockIdx.x;
    int tid = threadIdx.x, wid = tid >> 5, lane = tid & 31;
    float s = 0.f, q = 0.f;
    for (int j = tid; j < RTILES; j += 256) {
        s += g_psum[j * 512 + c];
        q += g_psq [j * 512 + c];
    }
    #pragma unroll
    for (int m = 16; m; m >>= 1) {
        s += __shfl_xor_sync(0xffffffffu, s, m);
        q += __shfl_xor_sync(0xffffffffu, q, m);
    }
    __shared__ float rs[8], rq[8];
    if (lane == 0) { rs[wid] = s; rq[wid] = q; }
    __syncthreads();
    if (tid == 0) {
        float S = 0.f, Q = 0.f;
        #pragma unroll
        for (int w = 0; w < 8; w++) { S += rs[w]; Q += rq[w]; }
        const float invn = 1.0f / (float)RT;
        float mu  = S * invn;
        float var = Q * invn - mu * mu;
        float rinv = rsqrtf(var + 1e-5f);
        float sc = rinv * gamma[c];
        float sh = beta[c] - mu * sc;
        scl[c] = sc;  shf[c] = sh;
        sclh[c] = __float2half(sc);
        shfh[c] = __float2half(sh);
    }
}

__global__ void bn_norm_kernel(const float* __restrict__ y,
                               const float* __restrict__ scl,
                               const float* __restrict__ shf,
                               float* __restrict__ out)
{
    const int total = RT * DM / 4;
    for (int i = blockIdx.x * blockDim.x + threadIdx.x; i < total;
         i += gridDim.x * blockDim.x) {
        float4 vv = ((const float4*)y)[i];
        int c = (i & 127) * 4;
        float4 oo;
        oo.x = vv.x * scl[c + 0] + shf[c + 0];
        oo.y = vv.y * scl[c + 1] + shf[c + 1];
        oo.z = vv.z * scl[c + 2] + shf[c + 2];
        oo.w = vv.w * scl[c + 3] + shf[c + 3];
        ((float4*)out)[i] = oo;
    }
}

// ---------------------------------------------------------------------------
// Orchestration
// ---------------------------------------------------------------------------
extern "C" void kernel_launch(void* const* d_in, const int* in_sizes, int n_in,
                              void* d_out, int out_size)
{
    const float* x_enc = (const float*)d_in[0];
    const float* tok_w = (const float*)d_in[1];
    const float* wq  = (const float*)d_in[2];
    const float* bq  = (const float*)d_in[3];
    const float* wk  = (const float*)d_in[4];
    const float* bk  = (const float*)d_in[5];
    const float* wv  = (const float*)d_in[6];
    const float* bv  = (const float*)d_in[7];
    const float* wo  = (const float*)d_in[8];
    const float* bo  = (const float*)d_in[9];
    const float* c1w = (const float*)d_in[10];
    const float* c1b = (const float*)d_in[11];
    const float* c2w = (const float*)d_in[12];
    const float* c2b = (const float*)d_in[13];
    const float* g1  = (const float*)d_in[14];
    const float* be1 = (const float*)d_in[15];
    const float* g2  = (const float*)d_in[16];
    const float* be2 = (const float*)d_in[17];
    float* out = (float*)d_out;

    float *p_h, *p_y, *p_scl, *p_shf, *p_bqkv;
    __half *p_hh, *p_qh, *p_kh, *p_vh, *p_atth, *p_yh, *p_th, *p_sclh, *p_shfh;
    __half *p_wqkv, *p_woh, *p_c1h, *p_c2h;
    cudaGetSymbolAddress((void**)&p_h,   g_h);
    cudaGetSymbolAddress((void**)&p_y,   g_y);
    cudaGetSymbolAddress((void**)&p_hh,   g_h_h);
    cudaGetSymbolAddress((void**)&p_qh,   g_q_h);
    cudaGetSymbolAddress((void**)&p_kh,   g_k_h);
    cudaGetSymbolAddress((void**)&p_vh,   g_v_h);
    cudaGetSymbolAddress((void**)&p_atth, g_att_h);
    cudaGetSymbolAddress((void**)&p_yh,   g_y_h);
    cudaGetSymbolAddress((void**)&p_th,   g_t_h);
    cudaGetSymbolAddress((void**)&p_wqkv, g_wqkv_h);
    cudaGetSymbolAddress((void**)&p_bqkv, g_bqkv);
    cudaGetSymbolAddress((void**)&p_woh, g_wo_h);
    cudaGetSymbolAddress((void**)&p_c1h, g_c1_h);
    cudaGetSymbolAddress((void**)&p_c2h, g_c2_h);
    cudaGetSymbolAddress((void**)&p_scl, g_bnscale);
    cudaGetSymbolAddress((void**)&p_shf, g_bnshift);
    cudaGetSymbolAddress((void**)&p_sclh, g_bnscaleh);
    cudaGetSymbolAddress((void**)&p_shfh, g_bnshifth);
    float*  scl0  = p_scl;        float*  shf0  = p_shf;
    float*  scl1  = p_scl + 512;  float*  shf1  = p_shf + 512;
    __half* scl0h = p_sclh;       __half* shf0h = p_shfh;
    __half* scl1h = p_sclh + 512; __half* shf1h = p_shfh + 512;

    const int EMB_SMEM = EMB_SMEM_FLOATS * 4;
    cudaFuncSetAttribute(embed_kernel,
        cudaFuncAttributeMaxDynamicSharedMemorySize, EMB_SMEM);
    cudaFuncSetAttribute(attn_fa_kernel,
        cudaFuncAttributeMaxDynamicSharedMemorySize, AT_SMEM);
    cudaFuncSetAttribute(mma_gemm<0, 0, 0, 0, 1, 1>,
        cudaFuncAttributeMaxDynamicSharedMemorySize, GEMM_SMEM);
    cudaFuncSetAttribute(mma_gemm<0, 1, 0, 0, 1, 1>,
        cudaFuncAttributeMaxDynamicSharedMemorySize, GEMM_SMEM);
    cudaFuncSetAttribute(mma_gemm<2, 0, 1, 1, 1, 0>,
        cudaFuncAttributeMaxDynamicSharedMemorySize, GEMM_SMEM);
    cudaFuncSetAttribute(mma_gemm<2, 2, 1, 1, 1, 0>,
        cudaFuncAttributeMaxDynamicSharedMemorySize, GEMM_SMEM);
    cudaFuncSetAttribute(mma_gemm<1, 1, 0, 0, 1, 0>,
        cudaFuncAttributeMaxDynamicSharedMemorySize, GEMM_SMEM);

    setup_kernel<<<1024, 256>>>(wq, wk, wv, wo, c1w, c2w, bq, bk, bv,
                                p_wqkv, p_woh, p_c1h, p_c2h, p_bqkv);

    embed_kernel<<<2048, 256, EMB_SMEM>>>(x_enc, tok_w, p_h, p_hh);

    for (int l = 0; l < NL; l++) {
        const size_t QKVW = (size_t)l * 3 * DM * DM;
        const int WOFF = l * DM * DM;
        const int FOFF = l * DFF * DM;

        if (l == 0)
            mma_gemm<0, 0, 0, 0, 1, 1><<<dim3(12, RTILES), 256, GEMM_SMEM>>>(
                p_hh, p_wqkv + QKVW, p_bqkv + l * 3 * DM, nullptr, nullptr, nullptr,
                nullptr, nullptr, nullptr, p_qh, p_kh, p_vh, DM);
        else
            mma_gemm<0, 1, 0, 0, 1, 1><<<dim3(12, RTILES), 256, GEMM_SMEM>>>(
                p_hh, p_wqkv + QKVW, p_bqkv + l * 3 * DM, nullptr, nullptr, nullptr,
                scl1h, shf1h, nullptr, p_qh, p_kh, p_vh, DM);

        attn_fa_kernel<<<2048 * NH, 256, AT_SMEM>>>(p_qh, p_kh, p_vh, p_atth);

        if (l == 0)
            mma_gemm<2, 0, 1, 1, 1, 0><<<dim3(4, RTILES), 256, GEMM_SMEM>>>(
                p_atth, p_woh + WOFF, bo + l * DM, p_h, nullptr, nullptr,
                nullptr, nullptr, p_y, p_yh, nullptr, nullptr, DM);
        else
            mma_gemm<2, 2, 1, 1, 1, 0><<<dim3(4, RTILES), 256, GEMM_SMEM>>>(
                p_atth, p_woh + WOFF, bo + l * DM, p_h, scl1, shf1,
                nullptr, nullptr, p_y, p_yh, nullptr, nullptr, DM);

        bn_reduce2_kernel<<<512, 256>>>(g1 + l * DM, be1 + l * DM,
                                        scl0, shf0, scl0h, shf0h);

        mma_gemm<1, 1, 0, 0, 1, 0><<<dim3(8, RTILES), 256, GEMM_SMEM>>>(
            p_yh, p_c1h + FOFF, c1b + l * DFF, nullptr, nullptr, nullptr,
            scl0h, shf0h, nullptr, p_th, nullptr, nullptr, DM);
        mma_gemm<2, 2, 1, 1, 1, 0><<<dim3(4, RTILES), 256, GEMM_SMEM>>>(
            p_th, p_c2h + FOFF, c2b + l * DM, p_y, scl0, shf0,
            nullptr, nullptr, p_h, p_hh, nullptr, nullptr, DFF);

        bn_reduce2_kernel<<<512, 256>>>(g2 + l * DM, be2 + l * DM,
                                        scl1, shf1, scl1h, shf1h);
    }

    bn_norm_kernel<<<4096, 256>>>(p_h, scl1, shf1, out);
}

// round 17
// speedup vs baseline: 1.8957x; 1.0042x over previous
#include <cuda_runtime.h>
#include <cuda_fp16.h>
#include <math.h>
#include <stdint.h>

// ---------------------------------------------------------------------------
// Problem constants
// ---------------------------------------------------------------------------
#define NTOK   81
#define DM     512
#define NH     8
#define EH     64
#define DFF    1024
#define NL     3
#define RT     (2048 * 81)           // 165888 tokens
#define RTILES (RT / 128)            // 1296

// ---------------------------------------------------------------------------
// Scratch (device globals)
// ---------------------------------------------------------------------------
__device__ float  g_h [RT * DM];     // fp32 residual: embed out / raw y2
__device__ float  g_y [RT * DM];     // fp32 residual: raw y1
__device__ __half g_h_h  [RT * DM];
__device__ __half g_q_h  [RT * DM];
__device__ __half g_k_h  [RT * DM];
__device__ __half g_v_h  [RT * DM];
__device__ __half g_att_h[RT * DM];
__device__ __half g_y_h  [RT * DM];
__device__ __half g_t_h  [RT * DFF];
__device__ __half g_wqkv_h[NL * 3 * DM * DM];   // concat [q|k|v]
__device__ float  g_bqkv  [NL * 3 * DM];
__device__ __half g_wo_h[NL * DM * DM];
__device__ __half g_c1_h[NL * DFF * DM];
__device__ __half g_c2_h[NL * DM * DFF];
__device__ float  g_psum[RTILES * 512];
__device__ float  g_psq [RTILES * 512];
__device__ float  g_bnscale[2 * 512];
__device__ float  g_bnshift[2 * 512];
__device__ __half g_bnscaleh[2 * 512];
__device__ __half g_bnshifth[2 * 512];

// ---------------------------------------------------------------------------
// PTX helpers
// ---------------------------------------------------------------------------
__device__ __forceinline__ uint32_t smem_u32(const void* p) {
    uint32_t a;
    asm("{ .reg .u64 t; cvta.to.shared.u64 t, %1; cvt.u32.u64 %0, t; }"
        : "=r"(a) : "l"(p));
    return a;
}

__device__ __forceinline__ void cp16(uint32_t dst, const void* src) {
    asm volatile("cp.async.cg.shared.global [%0], [%1], 16;"
                 :: "r"(dst), "l"(src) : "memory");
}
#define CP_COMMIT() asm volatile("cp.async.commit_group;" ::: "memory")

__device__ __forceinline__ void mma_f16(float* c, const uint32_t* a, const uint32_t* b) {
    asm volatile(
        "mma.sync.aligned.m16n8k16.row.col.f32.f16.f16.f32 "
        "{%0,%1,%2,%3}, {%4,%5,%6,%7}, {%8,%9}, {%0,%1,%2,%3};"
        : "+f"(c[0]), "+f"(c[1]), "+f"(c[2]), "+f"(c[3])
        : "r"(a[0]), "r"(a[1]), "r"(a[2]), "r"(a[3]), "r"(b[0]), "r"(b[1]));
}

__device__ __forceinline__ void ldsm_x4(uint32_t* r, uint32_t addr) {
    asm volatile("ldmatrix.sync.aligned.m8n8.x4.shared.b16 {%0,%1,%2,%3}, [%4];"
        : "=r"(r[0]), "=r"(r[1]), "=r"(r[2]), "=r"(r[3]) : "r"(addr));
}

// Fast gelu: erf via Abramowitz-Stegun 7.1.26 (|err| <= 1.5e-7)
__device__ __forceinline__ float gelu_f(float x) {
    float y  = fabsf(x) * 0.70710678118654752f;
    float t  = __frcp_rn(1.0f + 0.3275911f * y);
    float p  = t * (0.254829592f + t * (-0.284496736f + t * (1.421413741f
             + t * (-1.453152027f + t * 1.061405429f))));
    float er = 1.0f - p * __expf(-y * y);
    er = copysignf(er, x);
    return 0.5f * x * (1.0f + er);
}

// ---------------------------------------------------------------------------
// FP16 GEMM (frozen proven config): CTA 128x128, BK=64, 8 warps (2x4),
// warp tile 64x32, 2 CTAs/SM, 3-stage cp.async.cg, m16n8k16, fp32 accumulate.
// EPI: 0=bias, 1=bias+gelu, 2=bias+residual(fp32)
// AFF: 0=none, 1=half2 affine on A fragments, 2=fp32 affine on fp32 residual
// STATS / WF / WH / SPLIT3 (grid.x=12 over concat [q|k|v])
// ---------------------------------------------------------------------------
#define PHB 144
#define A_HALF_B (128 * PHB)
#define STAGE_B (2 * A_HALF_B)
#define GEMM_SMEM (3 * STAGE_B)          // 110592 B

template <int EPI, int AFF, int STATS, int WF, int WH, int SPLIT3>
__global__ __launch_bounds__(256, 2)
void mma_gemm(const __half* __restrict__ A, const __half* __restrict__ W,
              const float* __restrict__ bias, const float* __restrict__ res,
              const float* __restrict__ scl, const float* __restrict__ shf,
              const __half* __restrict__ sclh, const __half* __restrict__ shfh,
              float* __restrict__ C, __half* __restrict__ Ch,
              __half* __restrict__ Ch2, __half* __restrict__ Ch3, int K)
{
    extern __shared__ float smf[];
    uint32_t sA = smem_u32(smf);
    uint32_t sB = sA + A_HALF_B;

    int tid  = threadIdx.x;
    int wid  = tid >> 5, lane = tid & 31;
    int wm   = (wid >> 2) * 64;
    int wn   = (wid & 3) * 32;
    int row0 = blockIdx.y * 128, col0 = blockIdx.x * 128;
    int qg   = lane >> 2, qt = lane & 3;
    int lg   = lane >> 3, lr = lane & 7;

    __half* Chout = Ch;
    int colShift = 0;
    int DoutS = gridDim.x * 128;
    if (SPLIT3) {
        int which = blockIdx.x >> 2;
        Chout = (which == 0) ? Ch : ((which == 1) ? Ch2 : Ch3);
        colShift = which * 512;
        DoutS = 512;
    }

    uint32_t baseA[4], baseB[2];
    #pragma unroll
    for (int mt = 0; mt < 4; mt++)
        baseA[mt] = sA + (wm + mt * 16 + (lg & 1) * 8 + lr) * PHB + (lg >> 1) * 16;
    #pragma unroll
    for (int p = 0; p < 2; p++)
        baseB[p]  = sB + (wn + (2 * p + (lg & 1)) * 8 + lr) * PHB + (lg >> 1) * 16;

    auto issue = [&](int st, int kb2) {
        uint32_t o = st * STAGE_B;
        #pragma unroll
        for (int i = 0; i < 4; i++) {
            int slot = tid + 256 * i;
            int row = slot >> 3, c16 = slot & 7;
            uint32_t d = o + row * PHB + c16 * 16;
            cp16(sA + d, A + (size_t)(row0 + row) * K + kb2 * 64 + c16 * 8);
            cp16(sB + d, W + (size_t)(col0 + row) * K + kb2 * 64 + c16 * 8);
        }
        CP_COMMIT();
    };

    int NKB = K / 64;
    issue(0, 0);
    if (NKB > 1) issue(1, 1);

    float acc[4][4][4];
    #pragma unroll
    for (int mt = 0; mt < 4; mt++)
        #pragma unroll
        for (int nt = 0; nt < 4; nt++)
            #pragma unroll
            for (int j = 0; j < 4; j++) acc[mt][nt][j] = 0.f;

    int st = 0, nst = 2;
    for (int kb = 0; kb < NKB; kb++) {
        if (kb + 1 < NKB)
            asm volatile("cp.async.wait_group 1;" ::: "memory");
        else
            asm volatile("cp.async.wait_group 0;" ::: "memory");
        __syncthreads();
        if (kb + 2 < NKB) {
            issue(nst, kb + 2);
            if (++nst == 3) nst = 0;
        }

        uint32_t stOff = st * STAGE_B;
        #pragma unroll
        for (int ks = 0; ks < 4; ks++) {
            uint32_t kB = stOff + ks * 32;
            uint32_t af[4][4], bf[4][2];
            #pragma unroll
            for (int mt = 0; mt < 4; mt++)
                ldsm_x4(af[mt], baseA[mt] + kB);
            #pragma unroll
            for (int p = 0; p < 2; p++) {
                uint32_t t[4];
                ldsm_x4(t, baseB[p] + kB);
                bf[2 * p][0]     = t[0]; bf[2 * p][1]     = t[2];
                bf[2 * p + 1][0] = t[1]; bf[2 * p + 1][1] = t[3];
            }
            if (AFF == 1) {
                int kg = kb * 64 + ks * 16 + 2 * qt;
                __half2 s_lo = *(const __half2*)&sclh[kg];
                __half2 h_lo = *(const __half2*)&shfh[kg];
                __half2 s_hi = *(const __half2*)&sclh[kg + 8];
                __half2 h_hi = *(const __half2*)&shfh[kg + 8];
                #pragma unroll
                for (int mt = 0; mt < 4; mt++) {
                    __half2 v0 = *(__half2*)&af[mt][0];
                    __half2 v1 = *(__half2*)&af[mt][1];
                    __half2 v2 = *(__half2*)&af[mt][2];
                    __half2 v3 = *(__half2*)&af[mt][3];
                    v0 = __hfma2(v0, s_lo, h_lo);
                    v1 = __hfma2(v1, s_lo, h_lo);
                    v2 = __hfma2(v2, s_hi, h_hi);
                    v3 = __hfma2(v3, s_hi, h_hi);
                    af[mt][0] = *(uint32_t*)&v0;
                    af[mt][1] = *(uint32_t*)&v1;
                    af[mt][2] = *(uint32_t*)&v2;
                    af[mt][3] = *(uint32_t*)&v3;
                }
            }
            #pragma unroll
            for (int mt = 0; mt < 4; mt++)
                #pragma unroll
                for (int nt = 0; nt < 4; nt++)
                    mma_f16(acc[mt][nt], af[mt], bf[nt]);
        }
        if (++st == 3) st = 0;
    }

    float cs[8], cq[8];
    if (STATS) {
        #pragma unroll
        for (int j = 0; j < 8; j++) { cs[j] = 0.f; cq[j] = 0.f; }
    }

    #pragma unroll
    for (int mt = 0; mt < 4; mt++) {
        #pragma unroll
        for (int nt = 0; nt < 4; nt++) {
            int c  = col0 + wn + nt * 8 + 2 * qt;
            int r0 = row0 + wm + mt * 16 + qg;
            float b0 = bias[c], b1 = bias[c + 1];
            float s0 = 1.f, s1 = 1.f, h0 = 0.f, h1 = 0.f;
            if (AFF == 2) {
                s0 = scl[c]; s1 = scl[c + 1];
                h0 = shf[c]; h1 = shf[c + 1];
            }
            #pragma unroll
            for (int half = 0; half < 2; half++) {
                int r = r0 + half * 8;
                float vx = acc[mt][nt][half * 2 + 0] + b0;
                float vy = acc[mt][nt][half * 2 + 1] + b1;
                if (EPI == 1) {
                    vx = gelu_f(vx);
                    vy = gelu_f(vy);
                }
                size_t off = (size_t)r * DoutS + (c - colShift);
                if (EPI == 2) {
                    float2 rv = *(const float2*)(res + off);
                    if (AFF == 2) { vx += s0 * rv.x + h0; vy += s1 * rv.y + h1; }
                    else          { vx += rv.x;           vy += rv.y; }
                }
                if (STATS) {
                    cs[nt * 2 + 0] += vx; cq[nt * 2 + 0] += vx * vx;
                    cs[nt * 2 + 1] += vy; cq[nt * 2 + 1] += vy * vy;
                }
                if (WF)
                    *(float2*)(C + off) = make_float2(vx, vy);
                if (WH)
                    *(__half2*)(Chout + off) = __floats2half2_rn(vx, vy);
            }
        }
    }

    if (STATS) {
        #pragma unroll
        for (int j = 0; j < 8; j++) {
            #pragma unroll
            for (int m = 4; m <= 16; m <<= 1) {
                cs[j] += __shfl_xor_sync(0xffffffffu, cs[j], m);
                cq[j] += __shfl_xor_sync(0xffffffffu, cq[j], m);
            }
        }
        __syncthreads();
        float* ssum = smf;
        float* ssq  = smf + 256;
        int wrow = wid >> 2;
        if (lane < 4) {
            #pragma unroll
            for (int nt = 0; nt < 4; nt++) {
                #pragma unroll
                for (int p = 0; p < 2; p++) {
                    int cl = wn + nt * 8 + 2 * qt + p;
                    ssum[wrow * 128 + cl] = cs[nt * 2 + p];
                    ssq [wrow * 128 + cl] = cq[nt * 2 + p];
                }
            }
        }
        __syncthreads();
        if (tid < 128) {
            int slot = blockIdx.y * 512 + col0 + tid;
            g_psum[slot] = ssum[tid] + ssum[128 + tid];
            g_psq [slot] = ssq [tid] + ssq [128 + tid];
        }
    }
}

// ---------------------------------------------------------------------------
// Fused setup: all weight conversions + bias concat
// ---------------------------------------------------------------------------
#define WSZ (DM * DM)
__global__ void setup_kernel(const float* __restrict__ wq, const float* __restrict__ wk,
                             const float* __restrict__ wv, const float* __restrict__ wo,
                             const float* __restrict__ c1w, const float* __restrict__ c2w,
                             const float* __restrict__ bq, const float* __restrict__ bk,
                             const float* __restrict__ bv,
                             __half* __restrict__ wqkv, __half* __restrict__ woh,
                             __half* __restrict__ c1h, __half* __restrict__ c2h,
                             float* __restrict__ bqkv)
{
    int tid0 = blockIdx.x * blockDim.x + threadIdx.x;
    int stride = gridDim.x * blockDim.x;

    for (int i = tid0; i < NL * 3 * WSZ / 2; i += stride) {
        int seg = i / (WSZ / 2);
        int off = i - seg * (WSZ / 2);
        int l = seg / 3, w = seg - l * 3;
        const float* src = ((w == 0) ? wq : (w == 1) ? wk : wv) + (size_t)l * WSZ;
        float2 v = ((const float2*)src)[off];
        ((__half2*)(wqkv + (size_t)l * 3 * WSZ + (size_t)w * WSZ))[off] =
            __floats2half2_rn(v.x, v.y);
    }
    for (int i = tid0; i < NL * WSZ / 2; i += stride) {
        float2 v = ((const float2*)wo)[i];
        ((__half2*)woh)[i] = __floats2half2_rn(v.x, v.y);
    }
    for (int i = tid0; i < NL * DFF * DM / 2; i += stride) {
        float2 v = ((const float2*)c1w)[i];
        ((__half2*)c1h)[i] = __floats2half2_rn(v.x, v.y);
    }
    for (int i = tid0; i < NL * DM * DFF / 2; i += stride) {
        float2 v = ((const float2*)c2w)[i];
        ((__half2*)c2h)[i] = __floats2half2_rn(v.x, v.y);
    }
    for (int i = tid0; i < NL * 3 * DM; i += stride) {
        int l = i / (3 * DM), rem = i - l * 3 * DM;
        int w = rem / DM, c = rem - w * DM;
        const float* src = (w == 0) ? bq : (w == 1) ? bk : bv;
        bqkv[i] = src[l * DM + c];
    }
}

// ---------------------------------------------------------------------------
// Token embedding: circular Conv1d + sinusoidal PE (rotation recurrence)
// ---------------------------------------------------------------------------
#define EMB_SMEM_FLOATS (512 * 49 + 336)
__global__ void embed_kernel(const float* __restrict__ x_enc,
                             const float* __restrict__ tok_w,
                             float* __restrict__ h, __half* __restrict__ hh)
{
    extern __shared__ float sm[];
    float* w_sm = sm;
    float* x_sm = sm + 512 * 49;
    int bm = blockIdx.x;
    int b = bm >> 6, m = bm & 63;
    int tid = threadIdx.x;

    for (int i = tid; i < 512 * 48; i += 256) {
        int d = i / 48, u = i - d * 48;
        w_sm[d * 49 + u] = tok_w[i];
    }
    for (int l = tid; l < 336; l += 256)
        x_sm[l] = x_enc[(b * 336 + l) * 64 + m];
    __syncthreads();

    const float CLOG = -9.210340371976184f / 256.0f;
    int d0 = tid, d1 = tid + 256;
    float fr0 = expf((float)(d0 >> 1) * CLOG);
    float fr1 = expf((float)(d1 >> 1) * CLOG);
    float sf0 = sinf(fr0), cf0 = cosf(fr0);
    float sf1 = sinf(fr1), cf1 = cosf(fr1);
    float s0 = 0.f, c0 = 1.f, s1 = 0.f, c1v = 1.f;

    for (int n = 0; n < NTOK; n++) {
        float a0 = 0.f, a1 = 0.f;
        #pragma unroll
        for (int t = 0; t < 3; t++) {
            int pp = n - 1 + t;
            pp = (pp < 0) ? (NTOK - 1) : (pp >= NTOK ? 0 : pp);
            const float* xp = x_sm + pp * 4;
            #pragma unroll
            for (int p = 0; p < 16; p++) {
                float xv = xp[p];
                a0 += xv * w_sm[d0 * 49 + p * 3 + t];
                a1 += xv * w_sm[d1 * 49 + p * 3 + t];
            }
        }
        float pe0 = (d0 & 1) ? c0  : s0;
        float pe1 = (d1 & 1) ? c1v : s1;
        size_t base = ((size_t)bm * NTOK + n) * DM;
        float v0 = a0 + pe0, v1 = a1 + pe1;
        h[base + d0] = v0;
        h[base + d1] = v1;
        hh[base + d0] = __float2half(v0);
        hh[base + d1] = __float2half(v1);
        float ns0 = s0 * cf0 + c0 * sf0;
        float nc0 = c0 * cf0 - s0 * sf0;
        s0 = ns0; c0 = nc0;
        float ns1 = s1 * cf1 + c1v * sf1;
        float nc1 = c1v * cf1 - s1 * sf1;
        s1 = ns1; c1v = nc1;
    }
}

// ---------------------------------------------------------------------------
// FP16 mma attention, unpredicated register softmax (pad cols are exact
// zeros: max over all cols = max(real,0); sum corrected by -47*exp(-mx);
// pad P values multiply zeroed Vt columns). Sh aliases Qh/Kh; 3 CTAs/SM.
// ---------------------------------------------------------------------------
#define QKP 72
#define SVP 136
#define OFF_KH   (96 * QKP)
#define OFF_VT_H (OFF_KH + 128 * QKP)
#define RED_OFF_B ((OFF_VT_H + 64 * SVP) * 2)
#define AT_SMEM (RED_OFF_B + 96 * 4 * 4)       // 51200 bytes

__global__ __launch_bounds__(256, 3)
void attn_fa_kernel(const __half* __restrict__ q, const __half* __restrict__ k,
                    const __half* __restrict__ v, __half* __restrict__ o)
{
    extern __shared__ __half smh[];
    __half* Qh = smh;
    __half* Kh = smh + OFF_KH;
    __half* Vt = smh + OFF_VT_H;
    __half* Sh = smh;                       // alias over Qh/Kh
    float*  red = (float*)((char*)smh + RED_OFF_B);

    int bmh = blockIdx.x;
    int bm = bmh >> 3, hh = bmh & 7;
    int tid = threadIdx.x;
    int wid = tid >> 5, lane = tid & 31;
    int qg = lane >> 2, qt = lane & 3;
    int lg = lane >> 3, lr = lane & 7;
    size_t base = (size_t)bm * NTOK * DM + hh * EH;

    const __half HZ = __float2half(0.f);
    for (int i = tid; i < 15 * QKP; i += 256) Qh[81 * QKP + i] = HZ;
    for (int i = tid; i < 47 * QKP; i += 256) Kh[81 * QKP + i] = HZ;
    for (int i = tid; i < 64 * 47; i += 256) {
        int e = i / 47, c = 81 + (i % 47);
        Vt[e * SVP + c] = HZ;
    }

    for (int i = tid; i < NTOK * 8; i += 256) {
        int n = i >> 3, e8 = i & 7;
        *(uint4*)&Qh[n * QKP + e8 * 8] = *(const uint4*)(q + base + (size_t)n * DM + e8 * 8);
        *(uint4*)&Kh[n * QKP + e8 * 8] = *(const uint4*)(k + base + (size_t)n * DM + e8 * 8);
    }
    for (int i = tid; i < NTOK * 8; i += 256) {
        int s = i >> 3, e8 = i & 7;
        __half tmp[8];
        *(uint4*)tmp = *(const uint4*)(v + base + (size_t)s * DM + e8 * 8);
        #pragma unroll
        for (int j = 0; j < 8; j++)
            Vt[(e8 * 8 + j) * SVP + s] = tmp[j];
    }
    __syncthreads();

    uint32_t qsu = smem_u32(Qh), ksu = smem_u32(Kh);
    uint32_t vtu = smem_u32(Vt), shu = smem_u32(Sh);
    int wm = (wid >> 2) * 48;
    int wnS = (wid & 3) * 32;
    int widn = wid & 3;

    float sacc[3][4][4];
    #pragma unroll
    for (int mt = 0; mt < 3; mt++)
        #pragma unroll
        for (int nt = 0; nt < 4; nt++)
            #pragma unroll
            for (int j = 0; j < 4; j++) sacc[mt][nt][j] = 0.f;
    {
        uint32_t baseA[3], baseB[2];
        #pragma unroll
        for (int mt = 0; mt < 3; mt++)
            baseA[mt] = qsu + (wm + mt * 16 + (lg & 1) * 8 + lr) * (QKP * 2) + (lg >> 1) * 16;
        #pragma unroll
        for (int p = 0; p < 2; p++)
            baseB[p]  = ksu + (wnS + (2 * p + (lg & 1)) * 8 + lr) * (QKP * 2) + (lg >> 1) * 16;

        #pragma unroll
        for (int ks = 0; ks < 4; ks++) {
            uint32_t kB = ks * 32;
            uint32_t af[3][4], bf[4][2];
            #pragma unroll
            for (int mt = 0; mt < 3; mt++)
                ldsm_x4(af[mt], baseA[mt] + kB);
            #pragma unroll
            for (int p = 0; p < 2; p++) {
                uint32_t t[4];
                ldsm_x4(t, baseB[p] + kB);
                bf[2 * p][0]     = t[0]; bf[2 * p][1]     = t[2];
                bf[2 * p + 1][0] = t[1]; bf[2 * p + 1][1] = t[3];
            }
            #pragma unroll
            for (int mt = 0; mt < 3; mt++)
                #pragma unroll
                for (int nt = 0; nt < 4; nt++)
                    mma_f16(sacc[mt][nt], af[mt], bf[nt]);
        }
    }

    const float SC = 0.125f;
    // ---- max pass (unpredicated: pad scores are exactly 0 -> mx=max(real,0)) ----
    float rmax[3][2];
    #pragma unroll
    for (int mt = 0; mt < 3; mt++) { rmax[mt][0] = 0.f; rmax[mt][1] = 0.f; }
    #pragma unroll
    for (int mt = 0; mt < 3; mt++)
        #pragma unroll
        for (int nt = 0; nt < 4; nt++)
            #pragma unroll
            for (int j = 0; j < 4; j++)
                rmax[mt][j >> 1] = fmaxf(rmax[mt][j >> 1], sacc[mt][nt][j] * SC);
    #pragma unroll
    for (int mt = 0; mt < 3; mt++)
        #pragma unroll
        for (int hl = 0; hl < 2; hl++) {
            rmax[mt][hl] = fmaxf(rmax[mt][hl], __shfl_xor_sync(0xffffffffu, rmax[mt][hl], 1));
            rmax[mt][hl] = fmaxf(rmax[mt][hl], __shfl_xor_sync(0xffffffffu, rmax[mt][hl], 2));
        }
    if (qt == 0) {
        #pragma unroll
        for (int mt = 0; mt < 3; mt++)
            #pragma unroll
            for (int hl = 0; hl < 2; hl++)
                red[(wm + mt * 16 + qg + hl * 8) * 4 + widn] = rmax[mt][hl];
    }
    __syncthreads();
    float fmx[3][2];
    #pragma unroll
    for (int mt = 0; mt < 3; mt++)
        #pragma unroll
        for (int hl = 0; hl < 2; hl++) {
            const float* rr = &red[(wm + mt * 16 + qg + hl * 8) * 4];
            fmx[mt][hl] = fmaxf(fmaxf(rr[0], rr[1]), fmaxf(rr[2], rr[3]));
        }
    __syncthreads();

    // ---- exp pass (unpredicated; pad cols contribute exactly exp(-mx) each) ----
    float rsum[3][2] = {};
    #pragma unroll
    for (int mt = 0; mt < 3; mt++)
        #pragma unroll
        for (int nt = 0; nt < 4; nt++)
            #pragma unroll
            for (int j = 0; j < 4; j++) {
                int hl = j >> 1;
                float e = __expf(sacc[mt][nt][j] * SC - fmx[mt][hl]);
                sacc[mt][nt][j] = e;
                rsum[mt][hl] += e;
            }
    #pragma unroll
    for (int mt = 0; mt < 3; mt++)
        #pragma unroll
        for (int hl = 0; hl < 2; hl++) {
            rsum[mt][hl] += __shfl_xor_sync(0xffffffffu, rsum[mt][hl], 1);
            rsum[mt][hl] += __shfl_xor_sync(0xffffffffu, rsum[mt][hl], 2);
        }
    if (qt == 0) {
        #pragma unroll
        for (int mt = 0; mt < 3; mt++)
            #pragma unroll
            for (int hl = 0; hl < 2; hl++)
                red[(wm + mt * 16 + qg + hl * 8) * 4 + widn] = rsum[mt][hl];
    }
    __syncthreads();
    float finv[3][2];
    #pragma unroll
    for (int mt = 0; mt < 3; mt++)
        #pragma unroll
        for (int hl = 0; hl < 2; hl++) {
            const float* rr = &red[(wm + mt * 16 + qg + hl * 8) * 4];
            float total = rr[0] + rr[1] + rr[2] + rr[3];
            // subtract the 47 pad columns' exact contribution exp(0 - mx)
            total -= 47.0f * __expf(-fmx[mt][hl]);
            finv[mt][hl] = 1.0f / total;
        }

    #pragma unroll
    for (int mt = 0; mt < 3; mt++)
        #pragma unroll
        for (int nt = 0; nt < 4; nt++)
            #pragma unroll
            for (int hl = 0; hl < 2; hl++) {
                int r = wm + mt * 16 + qg + hl * 8;
                int c = wnS + nt * 8 + 2 * qt;
                *(__half2*)&Sh[r * SVP + c] = __floats2half2_rn(
                    sacc[mt][nt][hl * 2 + 0] * finv[mt][hl],
                    sacc[mt][nt][hl * 2 + 1] * finv[mt][hl]);
            }
    __syncthreads();

    {
        int wnV = (wid & 3) * 16;
        uint32_t baseA[3], baseB;
        #pragma unroll
        for (int mt = 0; mt < 3; mt++)
            baseA[mt] = shu + (wm + mt * 16 + (lg & 1) * 8 + lr) * (SVP * 2) + (lg >> 1) * 16;
        baseB = vtu + (wnV + (lg & 1) * 8 + lr) * (SVP * 2) + (lg >> 1) * 16;

        float oacc[3][2][4];
        #pragma unroll
        for (int mt = 0; mt < 3; mt++)
            #pragma unroll
            for (int nt = 0; nt < 2; nt++)
                #pragma unroll
                for (int j = 0; j < 4; j++) oacc[mt][nt][j] = 0.f;

        #pragma unroll
        for (int ks = 0; ks < 8; ks++) {
            uint32_t kB = ks * 32;
            uint32_t af[3][4], bf[2][2];
            #pragma unroll
            for (int mt = 0; mt < 3; mt++)
                ldsm_x4(af[mt], baseA[mt] + kB);
            {
                uint32_t t[4];
                ldsm_x4(t, baseB + kB);
                bf[0][0] = t[0]; bf[0][1] = t[2];
                bf[1][0] = t[1]; bf[1][1] = t[3];
            }
            #pragma unroll
            for (int mt = 0; mt < 3; mt++)
                #pragma unroll
                for (int nt = 0; nt < 2; nt++)
                    mma_f16(oacc[mt][nt], af[mt], bf[nt]);
        }

        #pragma unroll
        for (int mt = 0; mt < 3; mt++)
            #pragma unroll
            for (int nt = 0; nt < 2; nt++) {
                int c  = wnV + nt * 8 + 2 * qt;
                int r0 = wm + mt * 16 + qg;
                #pragma unroll
                for (int hl = 0; hl < 2; hl++) {
                    int r = r0 + hl * 8;
                    if (r < NTOK)
                        *(__half2*)(o + base + (size_t)r * DM + c) = __floats2half2_rn(
                            oacc[mt][nt][hl * 2 + 0], oacc[mt][nt][hl * 2 + 1]);
                }
            }
    }
}

// ---------------------------------------------------------------------------
// BN finalize
// ---------------------------------------------------------------------------
__global__ void bn_reduce2_kernel(const float* __restrict__ gamma,
                                  const float* __restrict__ beta,
                                  float* __restrict__ scl, float* __restrict__ shf,
                                  __half* __restrict__ sclh, __half* __restrict__ shfh)
{
    int c = blockIdx.x;
    int tid = threadIdx.x, wid = tid >> 5, lane = tid & 31;
    float s = 0.f, q = 0.f;
    for (int j = tid; j < RTILES; j += 256) {
        s += g_psum[j * 512 + c];
        q += g_psq [j * 512 + c];
    }
    #pragma unroll
    for (int m = 16; m; m >>= 1) {
        s += __shfl_xor_sync(0xffffffffu, s, m);
        q += __shfl_xor_sync(0xffffffffu, q, m);
    }
    __shared__ float rs[8], rq[8];
    if (lane == 0) { rs[wid] = s; rq[wid] = q; }
    __syncthreads();
    if (tid == 0) {
        float S = 0.f, Q = 0.f;
        #pragma unroll
        for (int w = 0; w < 8; w++) { S += rs[w]; Q += rq[w]; }
        const float invn = 1.0f / (float)RT;
        float mu  = S * invn;
        float var = Q * invn - mu * mu;
        float rinv = rsqrtf(var + 1e-5f);
        float sc = rinv * gamma[c];
        float sh = beta[c] - mu * sc;
        scl[c] = sc;  shf[c] = sh;
        sclh[c] = __float2half(sc);
        shfh[c] = __float2half(sh);
    }
}

__global__ void bn_norm_kernel(const float* __restrict__ y,
                               const float* __restrict__ scl,
                               const float* __restrict__ shf,
                               float* __restrict__ out)
{
    const int total = RT * DM / 4;
    for (int i = blockIdx.x * blockDim.x + threadIdx.x; i < total;
         i += gridDim.x * blockDim.x) {
        float4 vv = ((const float4*)y)[i];
        int c = (i & 127) * 4;
        float4 oo;
        oo.x = vv.x * scl[c + 0] + shf[c + 0];
        oo.y = vv.y * scl[c + 1] + shf[c + 1];
        oo.z = vv.z * scl[c + 2] + shf[c + 2];
        oo.w = vv.w * scl[c + 3] + shf[c + 3];
        ((float4*)out)[i] = oo;
    }
}

// ---------------------------------------------------------------------------
// Orchestration
// ---------------------------------------------------------------------------
extern "C" void kernel_launch(void* const* d_in, const int* in_sizes, int n_in,
                              void* d_out, int out_size)
{
    const float* x_enc = (const float*)d_in[0];
    const float* tok_w = (const float*)d_in[1];
    const float* wq  = (const float*)d_in[2];
    const float* bq  = (const float*)d_in[3];
    const float* wk  = (const float*)d_in[4];
    const float* bk  = (const float*)d_in[5];
    const float* wv  = (const float*)d_in[6];
    const float* bv  = (const float*)d_in[7];
    const float* wo  = (const float*)d_in[8];
    const float* bo  = (const float*)d_in[9];
    const float* c1w = (const float*)d_in[10];
    const float* c1b = (const float*)d_in[11];
    const float* c2w = (const float*)d_in[12];
    const float* c2b = (const float*)d_in[13];
    const float* g1  = (const float*)d_in[14];
    const float* be1 = (const float*)d_in[15];
    const float* g2  = (const float*)d_in[16];
    const float* be2 = (const float*)d_in[17];
    float* out = (float*)d_out;

    float *p_h, *p_y, *p_scl, *p_shf, *p_bqkv;
    __half *p_hh, *p_qh, *p_kh, *p_vh, *p_atth, *p_yh, *p_th, *p_sclh, *p_shfh;
    __half *p_wqkv, *p_woh, *p_c1h, *p_c2h;
    cudaGetSymbolAddress((void**)&p_h,   g_h);
    cudaGetSymbolAddress((void**)&p_y,   g_y);
    cudaGetSymbolAddress((void**)&p_hh,   g_h_h);
    cudaGetSymbolAddress((void**)&p_qh,   g_q_h);
    cudaGetSymbolAddress((void**)&p_kh,   g_k_h);
    cudaGetSymbolAddress((void**)&p_vh,   g_v_h);
    cudaGetSymbolAddress((void**)&p_atth, g_att_h);
    cudaGetSymbolAddress((void**)&p_yh,   g_y_h);
    cudaGetSymbolAddress((void**)&p_th,   g_t_h);
    cudaGetSymbolAddress((void**)&p_wqkv, g_wqkv_h);
    cudaGetSymbolAddress((void**)&p_bqkv, g_bqkv);
    cudaGetSymbolAddress((void**)&p_woh, g_wo_h);
    cudaGetSymbolAddress((void**)&p_c1h, g_c1_h);
    cudaGetSymbolAddress((void**)&p_c2h, g_c2_h);
    cudaGetSymbolAddress((void**)&p_scl, g_bnscale);
    cudaGetSymbolAddress((void**)&p_shf, g_bnshift);
    cudaGetSymbolAddress((void**)&p_sclh, g_bnscaleh);
    cudaGetSymbolAddress((void**)&p_shfh, g_bnshifth);
    float*  scl0  = p_scl;        float*  shf0  = p_shf;
    float*  scl1  = p_scl + 512;  float*  shf1  = p_shf + 512;
    __half* scl0h = p_sclh;       __half* shf0h = p_shfh;
    __half* scl1h = p_sclh + 512; __half* shf1h = p_shfh + 512;

    const int EMB_SMEM = EMB_SMEM_FLOATS * 4;
    cudaFuncSetAttribute(embed_kernel,
        cudaFuncAttributeMaxDynamicSharedMemorySize, EMB_SMEM);
    cudaFuncSetAttribute(attn_fa_kernel,
        cudaFuncAttributeMaxDynamicSharedMemorySize, AT_SMEM);
    cudaFuncSetAttribute(mma_gemm<0, 0, 0, 0, 1, 1>,
        cudaFuncAttributeMaxDynamicSharedMemorySize, GEMM_SMEM);
    cudaFuncSetAttribute(mma_gemm<0, 1, 0, 0, 1, 1>,
        cudaFuncAttributeMaxDynamicSharedMemorySize, GEMM_SMEM);
    cudaFuncSetAttribute(mma_gemm<2, 0, 1, 1, 1, 0>,
        cudaFuncAttributeMaxDynamicSharedMemorySize, GEMM_SMEM);
    cudaFuncSetAttribute(mma_gemm<2, 2, 1, 1, 1, 0>,
        cudaFuncAttributeMaxDynamicSharedMemorySize, GEMM_SMEM);
    cudaFuncSetAttribute(mma_gemm<1, 1, 0, 0, 1, 0>,
        cudaFuncAttributeMaxDynamicSharedMemorySize, GEMM_SMEM);

    setup_kernel<<<1024, 256>>>(wq, wk, wv, wo, c1w, c2w, bq, bk, bv,
                                p_wqkv, p_woh, p_c1h, p_c2h, p_bqkv);

    embed_kernel<<<2048, 256, EMB_SMEM>>>(x_enc, tok_w, p_h, p_hh);

    for (int l = 0; l < NL; l++) {
        const size_t QKVW = (size_t)l * 3 * DM * DM;
        const int WOFF = l * DM * DM;
        const int FOFF = l * DFF * DM;

        if (l == 0)
            mma_gemm<0, 0, 0, 0, 1, 1><<<dim3(12, RTILES), 256, GEMM_SMEM>>>(
                p_hh, p_wqkv + QKVW, p_bqkv + l * 3 * DM, nullptr, nullptr, nullptr,
                nullptr, nullptr, nullptr, p_qh, p_kh, p_vh, DM);
        else
            mma_gemm<0, 1, 0, 0, 1, 1><<<dim3(12, RTILES), 256, GEMM_SMEM>>>(
                p_hh, p_wqkv + QKVW, p_bqkv + l * 3 * DM, nullptr, nullptr, nullptr,
                scl1h, shf1h, nullptr, p_qh, p_kh, p_vh, DM);

        attn_fa_kernel<<<2048 * NH, 256, AT_SMEM>>>(p_qh, p_kh, p_vh, p_atth);

        if (l == 0)
            mma_gemm<2, 0, 1, 1, 1, 0><<<dim3(4, RTILES), 256, GEMM_SMEM>>>(
                p_atth, p_woh + WOFF, bo + l * DM, p_h, nullptr, nullptr,
                nullptr, nullptr, p_y, p_yh, nullptr, nullptr, DM);
        else
            mma_gemm<2, 2, 1, 1, 1, 0><<<dim3(4, RTILES), 256, GEMM_SMEM>>>(
                p_atth, p_woh + WOFF, bo + l * DM, p_h, scl1, shf1,
                nullptr, nullptr, p_y, p_yh, nullptr, nullptr, DM);

        bn_reduce2_kernel<<<512, 256>>>(g1 + l * DM, be1 + l * DM,
                                        scl0, shf0, scl0h, shf0h);

        mma_gemm<1, 1, 0, 0, 1, 0><<<dim3(8, RTILES), 256, GEMM_SMEM>>>(
            p_yh, p_c1h + FOFF, c1b + l * DFF, nullptr, nullptr, nullptr,
            scl0h, shf0h, nullptr, p_th, nullptr, nullptr, DM);
        mma_gemm<2, 2, 1, 1, 1, 0><<<dim3(4, RTILES), 256, GEMM_SMEM>>>(
            p_th, p_c2h + FOFF, c2b + l * DM, p_y, scl0, shf0,
            nullptr, nullptr, p_h, p_hh, nullptr, nullptr, DFF);

        bn_reduce2_kernel<<<512, 256>>>(g2 + l * DM, be2 + l * DM,
                                        scl1, shf1, scl1h, shf1h);
    }

    bn_norm_kernel<<<4096, 256>>>(p_h, scl1, shf1, out);
}